// round 5
// baseline (speedup 1.0000x reference)
#include <cuda_runtime.h>
#include <cuda_fp16.h>
#include <cstdint>
#include <math.h>

// ---------------- problem constants ----------------
#define BB   16
#define CC   256
#define HWSZ 1024
#define DH   32
#define HEADS 8
#define KTOP 4
#define MRC  1024
#define NWIN 64
#define EPSV 1e-5f

// ---------------- device scratch ----------------
__device__ float g_qkv[BB * 3*CC * HWSZ];
__device__ float g_qm [BB * HEADS * NWIN * DH];
__device__ float g_km [BB * HEADS * NWIN * DH];
__device__ int   g_idx[BB * HEADS * NWIN * KTOP];
__device__ float g_msg[BB * CC  * HWSZ];
__device__ float g_x1 [BB * CC  * HWSZ];
__device__ float g_h1 [BB * MRC * HWSZ];
__device__ float g_h2 [BB * MRC * HWSZ];

__device__ __forceinline__ float gelu_f(float x) {
    return 0.5f * x * (1.0f + erff(x * 0.7071067811865475f));
}

// ---------------- fp16 warp MMA ----------------
__device__ __forceinline__ void mma_f16(float* d, const uint32_t* a, uint32_t b0, uint32_t b1) {
    asm volatile(
        "mma.sync.aligned.m16n8k16.row.col.f32.f16.f16.f32 "
        "{%0,%1,%2,%3}, {%4,%5,%6,%7}, {%8,%9}, {%0,%1,%2,%3};"
        : "+f"(d[0]), "+f"(d[1]), "+f"(d[2]), "+f"(d[3])
        : "r"(a[0]), "r"(a[1]), "r"(a[2]), "r"(a[3]), "r"(b0), "r"(b1));
}

__device__ __forceinline__ void cvt_split(float x, __half& h, __half& l) {
    h = __float2half_rn(x);
    l = __float2half_rn(x - __half2float(h));
}

// smem layout constants (per stage)
#define WS_STRIDE 40
#define AS_STRIDE 34
#define WS_LO_ELEM 5120       // 128*40
#define AS_BYTE_OFF 20480     // 2*128*40*2
#define AS_LO_ELEM 4352       // 128*34
#define STAGE_BYTES 37888
#define GEMM_SMEM (2 * STAGE_BYTES)

// ---------------- tensor-core fused GEMM ----------------
// Out[b,o,n] = epilogue( sum_c Wm[o,c] * pre(A[b,c,n]) )
// PASSES: 1 = hiW*hiA; 2 = +loW*hiA; 3 = +hiW*loA
// PRE: apply bn0+gelu to A elements (channel-indexed) in the load path
template<int MODE, int PASSES, int PRE>
__global__ void __launch_bounds__(256, 1)
mgemm_k(const float* __restrict__ Wm, const float* __restrict__ A,
        float* __restrict__ Out, int O, int Kd,
        const float* __restrict__ Res, const float* __restrict__ bias,
        const float* __restrict__ g,  const float* __restrict__ bb,
        const float* __restrict__ mm, const float* __restrict__ vv,
        const float* __restrict__ p_g, const float* __restrict__ p_b,
        const float* __restrict__ p_m, const float* __restrict__ p_v) {
    extern __shared__ char smc[];
    const int tid = threadIdx.x, lane = tid & 31, warp = tid >> 5;
    const int b = blockIdx.z, om = blockIdx.x * 128, n0 = blockIdx.y * 128;
    const int wm = warp >> 1, wn = warp & 1;
    const int gq = lane >> 2, tq = lane & 3;

    const float* Wb = Wm + (size_t)om * Kd;
    const float* Ab = A + (size_t)b * Kd * HWSZ + n0;

    float acc[2][8][4];
    #pragma unroll
    for (int mt = 0; mt < 2; mt++)
        #pragma unroll
        for (int nt = 0; nt < 8; nt++)
            #pragma unroll
            for (int r = 0; r < 4; r++) acc[mt][nt][r] = 0.f;

    const int wrow = tid >> 3;
    const int wcol = (tid & 7) * 4;
    const int acr  = tid >> 5;
    const int acn  = (tid & 31) * 4;

    float4 wv[4], av[4];
    const int nch = Kd >> 5;

    // prologue transform for A elements (4 channels per thread: it*8+acr)
    auto pre_fix = [&](float4& v, int c) {
        if (PRE) {
            float s = p_g[c] * rsqrtf(p_v[c] + EPSV);
            float sh = p_b[c] - p_m[c] * s;
            v.x = gelu_f(v.x * s + sh); v.y = gelu_f(v.y * s + sh);
            v.z = gelu_f(v.z * s + sh); v.w = gelu_f(v.w * s + sh);
        }
    };

    #pragma unroll
    for (int it = 0; it < 4; it++)
        wv[it] = *(const float4*)(Wb + (size_t)(it * 32 + wrow) * Kd + wcol);
    #pragma unroll
    for (int it = 0; it < 4; it++) {
        av[it] = *(const float4*)(Ab + (size_t)(it * 8 + acr) * HWSZ + acn);
        pre_fix(av[it], it * 8 + acr);
    }

    {
        __half* ws_hi = (__half*)smc;
        __half* ws_lo = ws_hi + WS_LO_ELEM;
        __half* as_hi = (__half*)(smc + AS_BYTE_OFF);
        __half* as_lo = as_hi + AS_LO_ELEM;
        #pragma unroll
        for (int it = 0; it < 4; it++) {
            __half h4[4], l4[4];
            cvt_split(wv[it].x, h4[0], l4[0]); cvt_split(wv[it].y, h4[1], l4[1]);
            cvt_split(wv[it].z, h4[2], l4[2]); cvt_split(wv[it].w, h4[3], l4[3]);
            int idx = (it * 32 + wrow) * WS_STRIDE + wcol;
            *(uint2*)&ws_hi[idx] = *(uint2*)h4;
            if (PASSES >= 2) *(uint2*)&ws_lo[idx] = *(uint2*)l4;
        }
        #pragma unroll
        for (int it = 0; it < 4; it++) {
            int c = it * 8 + acr;
            float vs4[4] = {av[it].x, av[it].y, av[it].z, av[it].w};
            #pragma unroll
            for (int j = 0; j < 4; j++) {
                __half h, l; cvt_split(vs4[j], h, l);
                as_hi[(acn + j) * AS_STRIDE + c] = h;
                if (PASSES >= 3) as_lo[(acn + j) * AS_STRIDE + c] = l;
            }
        }
    }
    __syncthreads();

    for (int ch = 0; ch < nch; ch++) {
        int s = ch & 1;
        char* st = smc + s * STAGE_BYTES;
        int k0n = (ch + 1) << 5;

        if (ch + 1 < nch) {
            #pragma unroll
            for (int it = 0; it < 4; it++)
                wv[it] = *(const float4*)(Wb + (size_t)(it * 32 + wrow) * Kd + k0n + wcol);
            #pragma unroll
            for (int it = 0; it < 4; it++) {
                av[it] = *(const float4*)(Ab + (size_t)(k0n + it * 8 + acr) * HWSZ + acn);
                pre_fix(av[it], k0n + it * 8 + acr);
            }
        }

        const __half* ws_hi = (const __half*)st;
        const __half* ws_lo = ws_hi + WS_LO_ELEM;
        const __half* as_hi = (const __half*)(st + AS_BYTE_OFF);
        const __half* as_lo = as_hi + AS_LO_ELEM;

        #pragma unroll
        for (int ks = 0; ks < 2; ks++) {
            uint32_t afh[2][4], afl[2][4];
            #pragma unroll
            for (int mt = 0; mt < 2; mt++) {
                int rb = wm * 32 + mt * 16;
                int cb = ks * 16 + 2 * tq;
                afh[mt][0] = *(const uint32_t*)&ws_hi[(rb + gq)     * WS_STRIDE + cb];
                afh[mt][1] = *(const uint32_t*)&ws_hi[(rb + gq + 8) * WS_STRIDE + cb];
                afh[mt][2] = *(const uint32_t*)&ws_hi[(rb + gq)     * WS_STRIDE + cb + 8];
                afh[mt][3] = *(const uint32_t*)&ws_hi[(rb + gq + 8) * WS_STRIDE + cb + 8];
                if (PASSES >= 2) {
                    afl[mt][0] = *(const uint32_t*)&ws_lo[(rb + gq)     * WS_STRIDE + cb];
                    afl[mt][1] = *(const uint32_t*)&ws_lo[(rb + gq + 8) * WS_STRIDE + cb];
                    afl[mt][2] = *(const uint32_t*)&ws_lo[(rb + gq)     * WS_STRIDE + cb + 8];
                    afl[mt][3] = *(const uint32_t*)&ws_lo[(rb + gq + 8) * WS_STRIDE + cb + 8];
                }
            }
            #pragma unroll
            for (int nt = 0; nt < 8; nt++) {
                int nb = wn * 64 + nt * 8 + gq;
                int kb = ks * 16 + 2 * tq;
                uint32_t bh0 = *(const uint32_t*)&as_hi[nb * AS_STRIDE + kb];
                uint32_t bh1 = *(const uint32_t*)&as_hi[nb * AS_STRIDE + kb + 8];
                #pragma unroll
                for (int mt = 0; mt < 2; mt++) {
                    mma_f16(acc[mt][nt], afh[mt], bh0, bh1);
                    if (PASSES >= 2) mma_f16(acc[mt][nt], afl[mt], bh0, bh1);
                }
                if (PASSES >= 3) {
                    uint32_t bl0 = *(const uint32_t*)&as_lo[nb * AS_STRIDE + kb];
                    uint32_t bl1 = *(const uint32_t*)&as_lo[nb * AS_STRIDE + kb + 8];
                    #pragma unroll
                    for (int mt = 0; mt < 2; mt++)
                        mma_f16(acc[mt][nt], afh[mt], bl0, bl1);
                }
            }
        }

        if (ch + 1 < nch) {
            char* st2 = smc + (s ^ 1) * STAGE_BYTES;
            __half* ws_hi2 = (__half*)st2;
            __half* ws_lo2 = ws_hi2 + WS_LO_ELEM;
            __half* as_hi2 = (__half*)(st2 + AS_BYTE_OFF);
            __half* as_lo2 = as_hi2 + AS_LO_ELEM;
            #pragma unroll
            for (int it = 0; it < 4; it++) {
                __half h4[4], l4[4];
                cvt_split(wv[it].x, h4[0], l4[0]); cvt_split(wv[it].y, h4[1], l4[1]);
                cvt_split(wv[it].z, h4[2], l4[2]); cvt_split(wv[it].w, h4[3], l4[3]);
                int idx = (it * 32 + wrow) * WS_STRIDE + wcol;
                *(uint2*)&ws_hi2[idx] = *(uint2*)h4;
                if (PASSES >= 2) *(uint2*)&ws_lo2[idx] = *(uint2*)l4;
            }
            #pragma unroll
            for (int it = 0; it < 4; it++) {
                int c = it * 8 + acr;
                float vs4[4] = {av[it].x, av[it].y, av[it].z, av[it].w};
                #pragma unroll
                for (int j = 0; j < 4; j++) {
                    __half h, l; cvt_split(vs4[j], h, l);
                    as_hi2[(acn + j) * AS_STRIDE + c] = h;
                    if (PASSES >= 3) as_lo2[(acn + j) * AS_STRIDE + c] = l;
                }
            }
        }
        __syncthreads();
    }

    // ---- epilogue ----
    #pragma unroll
    for (int mt = 0; mt < 2; mt++) {
        int o0 = om + wm * 32 + mt * 16 + gq;
        int o1 = o0 + 8;
        float s0 = 0.f, bs0 = 0.f, s1 = 0.f, bs1 = 0.f, bi0 = 0.f, bi1 = 0.f;
        if (MODE == 2 || MODE == 3) {
            s0 = g[o0] * rsqrtf(vv[o0] + EPSV); bs0 = bb[o0] - mm[o0] * s0;
            s1 = g[o1] * rsqrtf(vv[o1] + EPSV); bs1 = bb[o1] - mm[o1] * s1;
        }
        if (MODE == 1) { bi0 = bias[o0]; bi1 = bias[o1]; }
        #pragma unroll
        for (int nt = 0; nt < 8; nt++) {
            int n = n0 + wn * 64 + nt * 8 + 2 * tq;
            size_t oi0 = ((size_t)b * O + o0) * HWSZ + n;
            size_t oi1 = ((size_t)b * O + o1) * HWSZ + n;
            float r0 = acc[mt][nt][0], r1 = acc[mt][nt][1];
            float r2 = acc[mt][nt][2], r3 = acc[mt][nt][3];
            if (MODE == 1) {
                float2 e0 = *(const float2*)&Res[oi0];
                float2 e1 = *(const float2*)&Res[oi1];
                r0 += e0.x + bi0; r1 += e0.y + bi0;
                r2 += e1.x + bi1; r3 += e1.y + bi1;
            }
            if (MODE == 2) {
                r0 = gelu_f(r0 * s0 + bs0); r1 = gelu_f(r1 * s0 + bs0);
                r2 = gelu_f(r2 * s1 + bs1); r3 = gelu_f(r3 * s1 + bs1);
            }
            if (MODE == 3) {
                float2 e0 = *(const float2*)&Res[oi0];
                float2 e1 = *(const float2*)&Res[oi1];
                r0 = e0.x + r0 * s0 + bs0; r1 = e0.y + r1 * s0 + bs0;
                r2 = e1.x + r2 * s1 + bs1; r3 = e1.y + r3 * s1 + bs1;
            }
            float2 v0 = {r0, r1}, v1 = {r2, r3};
            *(float2*)&Out[oi0] = v0;
            *(float2*)&Out[oi1] = v1;
        }
    }
}

// ---------------- window means (coalesced): block per (b,h) ----------------
__global__ void wmean_k() {
    int bh = blockIdx.x;
    int b = bh >> 3, h = bh & 7;
    int tid = threadIdx.x;
    __shared__ float spq[256], spk[256];
    const float* qpl = g_qkv + ((size_t)b * 3 * CC + h * DH) * HWSZ;
    const float* kpl = qpl + (size_t)CC * HWSZ;
    for (int d = 0; d < DH; d++) {
        float4 vq = ((const float4*)(qpl + (size_t)d * HWSZ))[tid];
        float4 vk = ((const float4*)(kpl + (size_t)d * HWSZ))[tid];
        spq[tid] = vq.x + vq.y + vq.z + vq.w;
        spk[tid] = vk.x + vk.y + vk.z + vk.w;
        __syncthreads();
        if (tid < 64) {
            int wy = tid >> 3, wx = tid & 7;
            int base = wy * 32 + wx;
            float sq = spq[base] + spq[base + 8] + spq[base + 16] + spq[base + 24];
            float sk = spk[base] + spk[base + 8] + spk[base + 16] + spk[base + 24];
            g_qm[((size_t)bh * 64 + tid) * DH + d] = sq * 0.0625f;
            g_km[((size_t)bh * 64 + tid) * DH + d] = sk * 0.0625f;
        }
        __syncthreads();
    }
}

// ---------------- affinity + exact top-4 (warp-parallel) ----------------
__global__ void topk_k() {
    int bh = blockIdx.x;
    __shared__ float kt[32][65];
    __shared__ float qs[64][32];
    int tid = threadIdx.x, warp = tid >> 5, lane = tid & 31;
    for (int e = tid; e < 2048; e += 256) {
        int j = e >> 5, d = e & 31;
        kt[d][j] = g_km[(size_t)bh * 2048 + e];
        qs[j][d] = g_qm[(size_t)bh * 2048 + e];
    }
    __syncthreads();
    for (int ii = 0; ii < 8; ii++) {
        int i = warp * 8 + ii;
        float s0 = 0.f, s1 = 0.f;
        #pragma unroll
        for (int d = 0; d < 32; d++) {
            float q = qs[i][d];
            s0 += q * kt[d][lane];
            s1 += q * kt[d][lane + 32];
        }
        float v0 = s0, v1 = s1;
        #pragma unroll
        for (int t = 0; t < KTOP; t++) {
            float bvv; int bj;
            if (v0 >= v1) { bvv = v0; bj = lane; } else { bvv = v1; bj = lane + 32; }
            #pragma unroll
            for (int off = 16; off; off >>= 1) {
                float ov = __shfl_xor_sync(0xffffffffu, bvv, off);
                int   oj = __shfl_xor_sync(0xffffffffu, bj,  off);
                if (ov > bvv || (ov == bvv && oj < bj)) { bvv = ov; bj = oj; }
            }
            if (lane == 0) g_idx[((size_t)bh * 64 + i) * KTOP + t] = bj;
            if (bj == lane)      v0 = -INFINITY;
            if (bj == lane + 32) v1 = -INFINITY;
        }
    }
}

// ---------------- gathered window attention ----------------
__global__ void attn_k() {
    int bid = blockIdx.x;
    int n = bid & 63;
    int h = (bid >> 6) & 7;
    int b = bid >> 9;
    __shared__ float qs[16][33];
    __shared__ float ks[64][33];
    __shared__ float vs[64][33];
    __shared__ float sc[16][64];
    __shared__ int   widx[KTOP];
    int tid = threadIdx.x;
    if (tid < KTOP) widx[tid] = g_idx[(size_t)bid * KTOP + tid];
    __syncthreads();

    int wy = n >> 3, wx = n & 7;
    const float* qbase = g_qkv + ((size_t)b * 3 * CC + h * DH) * HWSZ;
    const float* kbase = qbase + (size_t)CC * HWSZ;
    const float* vbase = qbase + (size_t)2 * CC * HWSZ;

    for (int e = tid; e < 512; e += 128) {
        int d = e >> 4, t = e & 15;
        int hw = ((wy * 4 + (t >> 2)) << 5) + wx * 4 + (t & 3);
        qs[t][d] = qbase[(size_t)d * HWSZ + hw];
    }
    for (int e = tid; e < 2048; e += 128) {
        int d = e >> 6, kt = e & 63;
        int j = widx[kt >> 4];
        int t = kt & 15;
        int jy = j >> 3, jx = j & 7;
        int hw = ((jy * 4 + (t >> 2)) << 5) + jx * 4 + (t & 3);
        ks[kt][d] = kbase[(size_t)d * HWSZ + hw];
        vs[kt][d] = vbase[(size_t)d * HWSZ + hw];
    }
    __syncthreads();

    int warp = tid >> 5, lane = tid & 31;
    const float scale = 0.17677669529663687f;
    #pragma unroll
    for (int rr = 0; rr < 4; rr++) {
        int row = warp * 4 + rr;
        float s0 = 0.f, s1 = 0.f;
        #pragma unroll
        for (int d = 0; d < 32; d++) {
            float qv = qs[row][d];
            s0 += qv * ks[lane][d];
            s1 += qv * ks[lane + 32][d];
        }
        s0 *= scale; s1 *= scale;
        float mx = fmaxf(s0, s1);
        #pragma unroll
        for (int off = 16; off; off >>= 1) mx = fmaxf(mx, __shfl_xor_sync(0xffffffffu, mx, off));
        float e0 = expf(s0 - mx), e1 = expf(s1 - mx);
        float sum = e0 + e1;
        #pragma unroll
        for (int off = 16; off; off >>= 1) sum += __shfl_xor_sync(0xffffffffu, sum, off);
        float inv = 1.0f / sum;
        sc[row][lane]      = e0 * inv;
        sc[row][lane + 32] = e1 * inv;
    }
    __syncwarp();
    float* mbase = g_msg + ((size_t)b * CC + h * DH) * HWSZ;
    #pragma unroll
    for (int rr = 0; rr < 4; rr++) {
        int row = warp * 4 + rr;
        float acc = 0.f;
        #pragma unroll
        for (int k = 0; k < 64; k++) acc += sc[row][k] * vs[k][lane];
        int hw = ((wy * 4 + (row >> 2)) << 5) + wx * 4 + (row & 3);
        mbase[(size_t)lane * HWSZ + hw] = acc;
    }
}

// ---------------- depthwise 3x3 + bn2 + gelu (float4) ----------------
__global__ void dw_k(const float* __restrict__ dw,
                     const float* __restrict__ g2, const float* __restrict__ b2,
                     const float* __restrict__ m2, const float* __restrict__ v2) {
    int bc = blockIdx.x;
    int c = bc & (MRC - 1);
    __shared__ float t[1024];
    __shared__ float wsh[9];
    int tid = threadIdx.x;
    const float* p = g_h1 + (size_t)bc * HWSZ;
    ((float4*)t)[tid] = ((const float4*)p)[tid];
    if (tid < 9) wsh[tid] = dw[c * 9 + tid];
    __syncthreads();
    float s = g2[c] * rsqrtf(v2[c] + EPSV);
    float bs = b2[c] - m2[c] * s;
    float* outp = g_h2 + (size_t)bc * HWSZ;
    int y = tid >> 3, x0 = (tid & 7) * 4;
    float4 res;
    float* rp = (float*)&res;
    #pragma unroll
    for (int j = 0; j < 4; j++) {
        int x = x0 + j;
        float acc = 0.f;
        #pragma unroll
        for (int dy = -1; dy <= 1; dy++) {
            int yy = y + dy;
            if (yy < 0 || yy > 31) continue;
            #pragma unroll
            for (int dx = -1; dx <= 1; dx++) {
                int xx = x + dx;
                if (xx < 0 || xx > 31) continue;
                acc += wsh[(dy + 1) * 3 + (dx + 1)] * t[yy * 32 + xx];
            }
        }
        rp[j] = gelu_f(acc * s + bs);
    }
    ((float4*)outp)[tid] = res;
}

// ---------------- launcher ----------------
extern "C" void kernel_launch(void* const* d_in, const int* in_sizes, int n_in,
                              void* d_out, int out_size) {
    const float* x      = (const float*)d_in[0];
    const float* bn0_g  = (const float*)d_in[1];
    const float* bn0_b  = (const float*)d_in[2];
    const float* bn0_m  = (const float*)d_in[3];
    const float* bn0_v  = (const float*)d_in[4];
    const float* w_qkv  = (const float*)d_in[5];
    const float* w_mrg  = (const float*)d_in[6];
    const float* b_mrg  = (const float*)d_in[7];
    const float* w1     = (const float*)d_in[8];
    const float* bn1_g  = (const float*)d_in[9];
    const float* bn1_b  = (const float*)d_in[10];
    const float* bn1_m  = (const float*)d_in[11];
    const float* bn1_v  = (const float*)d_in[12];
    const float* dw     = (const float*)d_in[13];
    const float* bn2_g  = (const float*)d_in[14];
    const float* bn2_b  = (const float*)d_in[15];
    const float* bn2_m  = (const float*)d_in[16];
    const float* bn2_v  = (const float*)d_in[17];
    const float* w2     = (const float*)d_in[18];
    const float* bn3_g  = (const float*)d_in[19];
    const float* bn3_b  = (const float*)d_in[20];
    const float* bn3_m  = (const float*)d_in[21];
    const float* bn3_v  = (const float*)d_in[22];

    float *qkv, *msg, *x1, *h1, *h2;
    cudaGetSymbolAddress((void**)&qkv, g_qkv);
    cudaGetSymbolAddress((void**)&msg, g_msg);
    cudaGetSymbolAddress((void**)&x1,  g_x1);
    cudaGetSymbolAddress((void**)&h1,  g_h1);
    cudaGetSymbolAddress((void**)&h2,  g_h2);

    cudaFuncSetAttribute((const void*)mgemm_k<0,3,1>, cudaFuncAttributeMaxDynamicSharedMemorySize, GEMM_SMEM);
    cudaFuncSetAttribute((const void*)mgemm_k<1,1,0>, cudaFuncAttributeMaxDynamicSharedMemorySize, GEMM_SMEM);
    cudaFuncSetAttribute((const void*)mgemm_k<2,1,0>, cudaFuncAttributeMaxDynamicSharedMemorySize, GEMM_SMEM);
    cudaFuncSetAttribute((const void*)mgemm_k<3,1,0>, cudaFuncAttributeMaxDynamicSharedMemorySize, GEMM_SMEM);

    // 1. qkv = w_qkv @ gelu(bn0(x))   (fused prologue; 3-pass for top-k fidelity)
    mgemm_k<0,3,1><<<dim3(768 / 128, 8, BB), 256, GEMM_SMEM>>>(
        w_qkv, x, qkv, 768, 256, nullptr, nullptr, nullptr, nullptr, nullptr, nullptr,
        bn0_g, bn0_b, bn0_m, bn0_v);

    // 2. window means
    wmean_k<<<BB * HEADS, 256>>>();

    // 3. affinity + top-4
    topk_k<<<BB * HEADS, 256>>>();

    // 4. gathered attention
    attn_k<<<BB * HEADS * NWIN, 128>>>();

    // 5. x1 = x + w_merge @ msg + b_merge   (1-pass)
    mgemm_k<1,1,0><<<dim3(CC / 128, 8, BB), 256, GEMM_SMEM>>>(
        w_mrg, msg, x1, CC, 256, x, b_mrg, nullptr, nullptr, nullptr, nullptr,
        nullptr, nullptr, nullptr, nullptr);

    // 6. h1 = gelu(bn1(w1 @ x1))   (1-pass)
    mgemm_k<2,1,0><<<dim3(MRC / 128, 8, BB), 256, GEMM_SMEM>>>(
        w1, x1, h1, MRC, 256, nullptr, nullptr, bn1_g, bn1_b, bn1_m, bn1_v,
        nullptr, nullptr, nullptr, nullptr);

    // 7. h2 = gelu(bn2(dwconv3x3(h1)))
    dw_k<<<BB * MRC, 256>>>(dw, bn2_g, bn2_b, bn2_m, bn2_v);

    // 8. out = x1 + bn3(w2 @ h2)   (1-pass)
    mgemm_k<3,1,0><<<dim3(CC / 128, 8, BB), 256, GEMM_SMEM>>>(
        w2, h2, (float*)d_out, CC, 1024, x1, nullptr, bn3_g, bn3_b, bn3_m, bn3_v,
        nullptr, nullptr, nullptr, nullptr);
}

// round 6
// speedup vs baseline: 1.1045x; 1.1045x over previous
#include <cuda_runtime.h>
#include <cuda_fp16.h>
#include <cstdint>
#include <math.h>

// ---------------- problem constants ----------------
#define BB   16
#define CC   256
#define HWSZ 1024
#define DH   32
#define HEADS 8
#define KTOP 4
#define MRC  1024
#define NWIN 64
#define EPSV 1e-5f

// ---------------- device scratch ----------------
__device__ float g_h0 [BB * CC  * HWSZ];
__device__ float g_qkv[BB * 3*CC * HWSZ];
__device__ float g_qm [BB * HEADS * NWIN * DH];
__device__ float g_km [BB * HEADS * NWIN * DH];
__device__ int   g_idx[BB * HEADS * NWIN * KTOP];
__device__ float g_msg[BB * CC  * HWSZ];
__device__ float g_x1 [BB * CC  * HWSZ];
__device__ float g_h1 [BB * MRC * HWSZ];
__device__ float g_h2 [BB * MRC * HWSZ];

__device__ __forceinline__ float gelu_f(float x) {
    return 0.5f * x * (1.0f + erff(x * 0.7071067811865475f));
}

// ---------------- fp16 warp MMA ----------------
__device__ __forceinline__ void mma_f16(float* d, const uint32_t* a, uint32_t b0, uint32_t b1) {
    asm volatile(
        "mma.sync.aligned.m16n8k16.row.col.f32.f16.f16.f32 "
        "{%0,%1,%2,%3}, {%4,%5,%6,%7}, {%8,%9}, {%0,%1,%2,%3};"
        : "+f"(d[0]), "+f"(d[1]), "+f"(d[2]), "+f"(d[3])
        : "r"(a[0]), "r"(a[1]), "r"(a[2]), "r"(a[3]), "r"(b0), "r"(b1));
}

__device__ __forceinline__ void cvt_split(float x, __half& h, __half& l) {
    h = __float2half_rn(x);
    l = __float2half_rn(x - __half2float(h));
}

// smem layout constants (per stage)
#define WS_STRIDE 40
#define AS_STRIDE 34
#define WS_LO_ELEM 5120       // 128*40
#define AS_BYTE_OFF 20480     // 2*128*40*2
#define AS_LO_ELEM 4352       // 128*34
#define STAGE_BYTES 37888
#define GEMM_SMEM (2 * STAGE_BYTES)

// ---------------- kernel: h0 = gelu(bn0(x)) ----------------
__global__ void bn0_gelu_k(const float* __restrict__ x,
                           const float* __restrict__ g, const float* __restrict__ b,
                           const float* __restrict__ m, const float* __restrict__ v) {
    int i = blockIdx.x * 256 + threadIdx.x;
    if (i >= BB * CC * HWSZ) return;
    int c = (i >> 10) & (CC - 1);
    float s = g[c] * rsqrtf(v[c] + EPSV);
    g_h0[i] = gelu_f((x[i] - m[c]) * s + b[c]);
}

// ---------------- tensor-core fused GEMM ----------------
// PASSES: 1 = hiW*hiA; 2 = +loW*hiA; 3 = +hiW*loA
template<int MODE, int PASSES>
__global__ void __launch_bounds__(256, 1)
mgemm_k(const float* __restrict__ Wm, const float* __restrict__ A,
        float* __restrict__ Out, int O, int Kd,
        const float* __restrict__ Res, const float* __restrict__ bias,
        const float* __restrict__ g,  const float* __restrict__ bb,
        const float* __restrict__ mm, const float* __restrict__ vv) {
    extern __shared__ char smc[];
    const int tid = threadIdx.x, lane = tid & 31, warp = tid >> 5;
    const int b = blockIdx.z, om = blockIdx.x * 128, n0 = blockIdx.y * 128;
    const int wm = warp >> 1, wn = warp & 1;
    const int gq = lane >> 2, tq = lane & 3;

    const float* Wb = Wm + (size_t)om * Kd;
    const float* Ab = A + (size_t)b * Kd * HWSZ + n0;

    float acc[2][8][4];
    #pragma unroll
    for (int mt = 0; mt < 2; mt++)
        #pragma unroll
        for (int nt = 0; nt < 8; nt++)
            #pragma unroll
            for (int r = 0; r < 4; r++) acc[mt][nt][r] = 0.f;

    const int wrow = tid >> 3;
    const int wcol = (tid & 7) * 4;
    const int acr  = tid >> 5;
    const int acn  = (tid & 31) * 4;

    float4 wv[4], av[4];
    const int nch = Kd >> 5;

    #pragma unroll
    for (int it = 0; it < 4; it++)
        wv[it] = *(const float4*)(Wb + (size_t)(it * 32 + wrow) * Kd + wcol);
    #pragma unroll
    for (int it = 0; it < 4; it++)
        av[it] = *(const float4*)(Ab + (size_t)(it * 8 + acr) * HWSZ + acn);

    {
        __half* ws_hi = (__half*)smc;
        __half* ws_lo = ws_hi + WS_LO_ELEM;
        __half* as_hi = (__half*)(smc + AS_BYTE_OFF);
        __half* as_lo = as_hi + AS_LO_ELEM;
        #pragma unroll
        for (int it = 0; it < 4; it++) {
            __half h4[4], l4[4];
            cvt_split(wv[it].x, h4[0], l4[0]); cvt_split(wv[it].y, h4[1], l4[1]);
            cvt_split(wv[it].z, h4[2], l4[2]); cvt_split(wv[it].w, h4[3], l4[3]);
            int idx = (it * 32 + wrow) * WS_STRIDE + wcol;
            *(uint2*)&ws_hi[idx] = *(uint2*)h4;
            if (PASSES >= 2) *(uint2*)&ws_lo[idx] = *(uint2*)l4;
        }
        #pragma unroll
        for (int it = 0; it < 4; it++) {
            int c = it * 8 + acr;
            float vs4[4] = {av[it].x, av[it].y, av[it].z, av[it].w};
            #pragma unroll
            for (int j = 0; j < 4; j++) {
                __half h, l; cvt_split(vs4[j], h, l);
                as_hi[(acn + j) * AS_STRIDE + c] = h;
                if (PASSES >= 3) as_lo[(acn + j) * AS_STRIDE + c] = l;
            }
        }
    }
    __syncthreads();

    for (int ch = 0; ch < nch; ch++) {
        int s = ch & 1;
        char* st = smc + s * STAGE_BYTES;
        int k0n = (ch + 1) << 5;

        if (ch + 1 < nch) {
            #pragma unroll
            for (int it = 0; it < 4; it++)
                wv[it] = *(const float4*)(Wb + (size_t)(it * 32 + wrow) * Kd + k0n + wcol);
            #pragma unroll
            for (int it = 0; it < 4; it++)
                av[it] = *(const float4*)(Ab + (size_t)(k0n + it * 8 + acr) * HWSZ + acn);
        }

        const __half* ws_hi = (const __half*)st;
        const __half* ws_lo = ws_hi + WS_LO_ELEM;
        const __half* as_hi = (const __half*)(st + AS_BYTE_OFF);
        const __half* as_lo = as_hi + AS_LO_ELEM;

        #pragma unroll
        for (int ks = 0; ks < 2; ks++) {
            uint32_t afh[2][4], afl[2][4];
            #pragma unroll
            for (int mt = 0; mt < 2; mt++) {
                int rb = wm * 32 + mt * 16;
                int cb = ks * 16 + 2 * tq;
                afh[mt][0] = *(const uint32_t*)&ws_hi[(rb + gq)     * WS_STRIDE + cb];
                afh[mt][1] = *(const uint32_t*)&ws_hi[(rb + gq + 8) * WS_STRIDE + cb];
                afh[mt][2] = *(const uint32_t*)&ws_hi[(rb + gq)     * WS_STRIDE + cb + 8];
                afh[mt][3] = *(const uint32_t*)&ws_hi[(rb + gq + 8) * WS_STRIDE + cb + 8];
                if (PASSES >= 2) {
                    afl[mt][0] = *(const uint32_t*)&ws_lo[(rb + gq)     * WS_STRIDE + cb];
                    afl[mt][1] = *(const uint32_t*)&ws_lo[(rb + gq + 8) * WS_STRIDE + cb];
                    afl[mt][2] = *(const uint32_t*)&ws_lo[(rb + gq)     * WS_STRIDE + cb + 8];
                    afl[mt][3] = *(const uint32_t*)&ws_lo[(rb + gq + 8) * WS_STRIDE + cb + 8];
                }
            }
            #pragma unroll
            for (int nt = 0; nt < 8; nt++) {
                int nb = wn * 64 + nt * 8 + gq;
                int kb = ks * 16 + 2 * tq;
                uint32_t bh0 = *(const uint32_t*)&as_hi[nb * AS_STRIDE + kb];
                uint32_t bh1 = *(const uint32_t*)&as_hi[nb * AS_STRIDE + kb + 8];
                #pragma unroll
                for (int mt = 0; mt < 2; mt++) {
                    mma_f16(acc[mt][nt], afh[mt], bh0, bh1);
                    if (PASSES >= 2) mma_f16(acc[mt][nt], afl[mt], bh0, bh1);
                }
                if (PASSES >= 3) {
                    uint32_t bl0 = *(const uint32_t*)&as_lo[nb * AS_STRIDE + kb];
                    uint32_t bl1 = *(const uint32_t*)&as_lo[nb * AS_STRIDE + kb + 8];
                    #pragma unroll
                    for (int mt = 0; mt < 2; mt++)
                        mma_f16(acc[mt][nt], afh[mt], bl0, bl1);
                }
            }
        }

        if (ch + 1 < nch) {
            char* st2 = smc + (s ^ 1) * STAGE_BYTES;
            __half* ws_hi2 = (__half*)st2;
            __half* ws_lo2 = ws_hi2 + WS_LO_ELEM;
            __half* as_hi2 = (__half*)(st2 + AS_BYTE_OFF);
            __half* as_lo2 = as_hi2 + AS_LO_ELEM;
            #pragma unroll
            for (int it = 0; it < 4; it++) {
                __half h4[4], l4[4];
                cvt_split(wv[it].x, h4[0], l4[0]); cvt_split(wv[it].y, h4[1], l4[1]);
                cvt_split(wv[it].z, h4[2], l4[2]); cvt_split(wv[it].w, h4[3], l4[3]);
                int idx = (it * 32 + wrow) * WS_STRIDE + wcol;
                *(uint2*)&ws_hi2[idx] = *(uint2*)h4;
                if (PASSES >= 2) *(uint2*)&ws_lo2[idx] = *(uint2*)l4;
            }
            #pragma unroll
            for (int it = 0; it < 4; it++) {
                int c = it * 8 + acr;
                float vs4[4] = {av[it].x, av[it].y, av[it].z, av[it].w};
                #pragma unroll
                for (int j = 0; j < 4; j++) {
                    __half h, l; cvt_split(vs4[j], h, l);
                    as_hi2[(acn + j) * AS_STRIDE + c] = h;
                    if (PASSES >= 3) as_lo2[(acn + j) * AS_STRIDE + c] = l;
                }
            }
        }
        __syncthreads();
    }

    // ---- epilogue ----
    #pragma unroll
    for (int mt = 0; mt < 2; mt++) {
        int o0 = om + wm * 32 + mt * 16 + gq;
        int o1 = o0 + 8;
        float s0 = 0.f, bs0 = 0.f, s1 = 0.f, bs1 = 0.f, bi0 = 0.f, bi1 = 0.f;
        if (MODE == 2 || MODE == 3) {
            s0 = g[o0] * rsqrtf(vv[o0] + EPSV); bs0 = bb[o0] - mm[o0] * s0;
            s1 = g[o1] * rsqrtf(vv[o1] + EPSV); bs1 = bb[o1] - mm[o1] * s1;
        }
        if (MODE == 1) { bi0 = bias[o0]; bi1 = bias[o1]; }
        #pragma unroll
        for (int nt = 0; nt < 8; nt++) {
            int n = n0 + wn * 64 + nt * 8 + 2 * tq;
            size_t oi0 = ((size_t)b * O + o0) * HWSZ + n;
            size_t oi1 = ((size_t)b * O + o1) * HWSZ + n;
            float r0 = acc[mt][nt][0], r1 = acc[mt][nt][1];
            float r2 = acc[mt][nt][2], r3 = acc[mt][nt][3];
            if (MODE == 1) {
                float2 e0 = *(const float2*)&Res[oi0];
                float2 e1 = *(const float2*)&Res[oi1];
                r0 += e0.x + bi0; r1 += e0.y + bi0;
                r2 += e1.x + bi1; r3 += e1.y + bi1;
            }
            if (MODE == 2) {
                r0 = gelu_f(r0 * s0 + bs0); r1 = gelu_f(r1 * s0 + bs0);
                r2 = gelu_f(r2 * s1 + bs1); r3 = gelu_f(r3 * s1 + bs1);
            }
            if (MODE == 3) {
                float2 e0 = *(const float2*)&Res[oi0];
                float2 e1 = *(const float2*)&Res[oi1];
                r0 = e0.x + r0 * s0 + bs0; r1 = e0.y + r1 * s0 + bs0;
                r2 = e1.x + r2 * s1 + bs1; r3 = e1.y + r3 * s1 + bs1;
            }
            float2 v0 = {r0, r1}, v1 = {r2, r3};
            *(float2*)&Out[oi0] = v0;
            *(float2*)&Out[oi1] = v1;
        }
    }
}

// ---------------- window means (coalesced): block per (b,h) ----------------
__global__ void wmean_k() {
    int bh = blockIdx.x;
    int b = bh >> 3, h = bh & 7;
    int tid = threadIdx.x;
    __shared__ float spq[256], spk[256];
    const float* qpl = g_qkv + ((size_t)b * 3 * CC + h * DH) * HWSZ;
    const float* kpl = qpl + (size_t)CC * HWSZ;
    for (int d = 0; d < DH; d++) {
        float4 vq = ((const float4*)(qpl + (size_t)d * HWSZ))[tid];
        float4 vk = ((const float4*)(kpl + (size_t)d * HWSZ))[tid];
        spq[tid] = vq.x + vq.y + vq.z + vq.w;
        spk[tid] = vk.x + vk.y + vk.z + vk.w;
        __syncthreads();
        if (tid < 64) {
            int wy = tid >> 3, wx = tid & 7;
            int base = wy * 32 + wx;
            float sq = spq[base] + spq[base + 8] + spq[base + 16] + spq[base + 24];
            float sk = spk[base] + spk[base + 8] + spk[base + 16] + spk[base + 24];
            g_qm[((size_t)bh * 64 + tid) * DH + d] = sq * 0.0625f;
            g_km[((size_t)bh * 64 + tid) * DH + d] = sk * 0.0625f;
        }
        __syncthreads();
    }
}

// ---------------- affinity + exact top-4 ----------------
__global__ void topk_k() {
    int bh = blockIdx.x;
    __shared__ float kt[32][65];
    __shared__ float qs[64][32];
    int tid = threadIdx.x, warp = tid >> 5, lane = tid & 31;
    for (int e = tid; e < 2048; e += 256) {
        int j = e >> 5, d = e & 31;
        kt[d][j] = g_km[(size_t)bh * 2048 + e];
        qs[j][d] = g_qm[(size_t)bh * 2048 + e];
    }
    __syncthreads();
    for (int ii = 0; ii < 8; ii++) {
        int i = warp * 8 + ii;
        float s0 = 0.f, s1 = 0.f;
        #pragma unroll
        for (int d = 0; d < 32; d++) {
            float q = qs[i][d];
            s0 += q * kt[d][lane];
            s1 += q * kt[d][lane + 32];
        }
        float v0 = s0, v1 = s1;
        #pragma unroll
        for (int t = 0; t < KTOP; t++) {
            float bvv; int bj;
            if (v0 >= v1) { bvv = v0; bj = lane; } else { bvv = v1; bj = lane + 32; }
            #pragma unroll
            for (int off = 16; off; off >>= 1) {
                float ov = __shfl_xor_sync(0xffffffffu, bvv, off);
                int   oj = __shfl_xor_sync(0xffffffffu, bj,  off);
                if (ov > bvv || (ov == bvv && oj < bj)) { bvv = ov; bj = oj; }
            }
            if (lane == 0) g_idx[((size_t)bh * 64 + i) * KTOP + t] = bj;
            if (bj == lane)      v0 = -INFINITY;
            if (bj == lane + 32) v1 = -INFINITY;
        }
    }
}

// ---------------- gathered window attention (HMMA, 3-pass) ----------------
// block = one (b,h,window), 128 threads = 4 warps.
#define QK_STR 40
#define V_STR  72
#define SS_STR 68
#define P_STR  72
__global__ void __launch_bounds__(128) attn_k() {
    int bid = blockIdx.x;
    int n = bid & 63;
    int h = (bid >> 6) & 7;
    int b = bid >> 9;
    __shared__ __half qh[16 * QK_STR], ql[16 * QK_STR];
    __shared__ __half kh[64 * QK_STR], kl[64 * QK_STR];
    __shared__ __half vh[32 * V_STR],  vl[32 * V_STR];
    __shared__ float  ss[16 * SS_STR];
    __shared__ __half ph[16 * P_STR], pl[16 * P_STR];
    __shared__ int    widx[KTOP];
    int tid = threadIdx.x;
    if (tid < KTOP) widx[tid] = g_idx[(size_t)bid * KTOP + tid];
    __syncthreads();

    int wy = n >> 3, wx = n & 7;
    const float* qbase = g_qkv + ((size_t)b * 3 * CC + h * DH) * HWSZ;
    const float* kbase = qbase + (size_t)CC * HWSZ;
    const float* vbase = qbase + (size_t)2 * CC * HWSZ;

    // q: 512 elems -> qh/ql[t][d]
    for (int e = tid; e < 512; e += 128) {
        int d = e >> 4, t = e & 15;
        int hw = ((wy * 4 + (t >> 2)) << 5) + wx * 4 + (t & 3);
        __half hv, lv; cvt_split(qbase[(size_t)d * HWSZ + hw], hv, lv);
        qh[t * QK_STR + d] = hv; ql[t * QK_STR + d] = lv;
    }
    // k gathered: 2048 elems -> kh/kl[key][d]
    for (int e = tid; e < 2048; e += 128) {
        int d = e >> 6, kt = e & 63;
        int j = widx[kt >> 4];
        int t = kt & 15;
        int hw = (((j >> 3) * 4 + (t >> 2)) << 5) + (j & 7) * 4 + (t & 3);
        __half hv, lv; cvt_split(kbase[(size_t)d * HWSZ + hw], hv, lv);
        kh[kt * QK_STR + d] = hv; kl[kt * QK_STR + d] = lv;
    }
    // v gathered: 2048 elems -> vh/vl[d][key]
    for (int e = tid; e < 2048; e += 128) {
        int d = e >> 6, kt = e & 63;
        int j = widx[kt >> 4];
        int t = kt & 15;
        int hw = (((j >> 3) * 4 + (t >> 2)) << 5) + (j & 7) * 4 + (t & 3);
        __half hv, lv; cvt_split(vbase[(size_t)d * HWSZ + hw], hv, lv);
        vh[d * V_STR + kt] = hv; vl[d * V_STR + kt] = lv;
    }
    __syncthreads();

    int warp = tid >> 5, lane = tid & 31;
    int gq = lane >> 2, tq = lane & 3;
    const float scale = 0.17677669529663687f;

    // ---- scores: S[16][64], warp w covers cols [w*16, w*16+16) ----
    {
        float sc0[4] = {0.f, 0.f, 0.f, 0.f};
        float sc1[4] = {0.f, 0.f, 0.f, 0.f};
        #pragma unroll
        for (int ks = 0; ks < 2; ks++) {
            int cb = ks * 16 + 2 * tq;
            uint32_t ah[4], al[4];
            ah[0] = *(const uint32_t*)&qh[gq * QK_STR + cb];
            ah[1] = *(const uint32_t*)&qh[(gq + 8) * QK_STR + cb];
            ah[2] = *(const uint32_t*)&qh[gq * QK_STR + cb + 8];
            ah[3] = *(const uint32_t*)&qh[(gq + 8) * QK_STR + cb + 8];
            al[0] = *(const uint32_t*)&ql[gq * QK_STR + cb];
            al[1] = *(const uint32_t*)&ql[(gq + 8) * QK_STR + cb];
            al[2] = *(const uint32_t*)&ql[gq * QK_STR + cb + 8];
            al[3] = *(const uint32_t*)&ql[(gq + 8) * QK_STR + cb + 8];
            #pragma unroll
            for (int nt = 0; nt < 2; nt++) {
                int key = warp * 16 + nt * 8 + gq;
                uint32_t bh0 = *(const uint32_t*)&kh[key * QK_STR + cb];
                uint32_t bh1 = *(const uint32_t*)&kh[key * QK_STR + cb + 8];
                uint32_t bl0 = *(const uint32_t*)&kl[key * QK_STR + cb];
                uint32_t bl1 = *(const uint32_t*)&kl[key * QK_STR + cb + 8];
                float* sc = nt ? sc1 : sc0;
                mma_f16(sc, ah, bh0, bh1);
                mma_f16(sc, ah, bl0, bl1);
                mma_f16(sc, al, bh0, bh1);
            }
        }
        #pragma unroll
        for (int nt = 0; nt < 2; nt++) {
            const float* sc = nt ? sc1 : sc0;
            int c0 = warp * 16 + nt * 8 + 2 * tq;
            ss[gq * SS_STR + c0]           = sc[0] * scale;
            ss[gq * SS_STR + c0 + 1]       = sc[1] * scale;
            ss[(gq + 8) * SS_STR + c0]     = sc[2] * scale;
            ss[(gq + 8) * SS_STR + c0 + 1] = sc[3] * scale;
        }
    }
    __syncthreads();

    // ---- softmax: warp per 4 rows, write probs hi/lo ----
    #pragma unroll
    for (int rr = 0; rr < 4; rr++) {
        int row = warp * 4 + rr;
        float s0 = ss[row * SS_STR + lane];
        float s1 = ss[row * SS_STR + lane + 32];
        float mx = fmaxf(s0, s1);
        #pragma unroll
        for (int off = 16; off; off >>= 1) mx = fmaxf(mx, __shfl_xor_sync(0xffffffffu, mx, off));
        float e0 = expf(s0 - mx), e1 = expf(s1 - mx);
        float sum = e0 + e1;
        #pragma unroll
        for (int off = 16; off; off >>= 1) sum += __shfl_xor_sync(0xffffffffu, sum, off);
        float inv = 1.0f / sum;
        __half hv, lv;
        cvt_split(e0 * inv, hv, lv);
        ph[row * P_STR + lane] = hv; pl[row * P_STR + lane] = lv;
        cvt_split(e1 * inv, hv, lv);
        ph[row * P_STR + lane + 32] = hv; pl[row * P_STR + lane + 32] = lv;
    }
    __syncthreads();

    // ---- out = P @ V : M=16, N=32 (warp w covers d-cols [w*8, w*8+8)), K=64 ----
    {
        float f[4] = {0.f, 0.f, 0.f, 0.f};
        #pragma unroll
        for (int ks = 0; ks < 4; ks++) {
            int cb = ks * 16 + 2 * tq;
            uint32_t ah[4], al[4];
            ah[0] = *(const uint32_t*)&ph[gq * P_STR + cb];
            ah[1] = *(const uint32_t*)&ph[(gq + 8) * P_STR + cb];
            ah[2] = *(const uint32_t*)&ph[gq * P_STR + cb + 8];
            ah[3] = *(const uint32_t*)&ph[(gq + 8) * P_STR + cb + 8];
            al[0] = *(const uint32_t*)&pl[gq * P_STR + cb];
            al[1] = *(const uint32_t*)&pl[(gq + 8) * P_STR + cb];
            al[2] = *(const uint32_t*)&pl[gq * P_STR + cb + 8];
            al[3] = *(const uint32_t*)&pl[(gq + 8) * P_STR + cb + 8];
            int d = warp * 8 + gq;
            uint32_t bh0 = *(const uint32_t*)&vh[d * V_STR + cb];
            uint32_t bh1 = *(const uint32_t*)&vh[d * V_STR + cb + 8];
            uint32_t bl0 = *(const uint32_t*)&vl[d * V_STR + cb];
            uint32_t bl1 = *(const uint32_t*)&vl[d * V_STR + cb + 8];
            mma_f16(f, ah, bh0, bh1);
            mma_f16(f, ah, bl0, bl1);
            mma_f16(f, al, bh0, bh1);
        }
        float* mbase = g_msg + ((size_t)b * CC + h * DH) * HWSZ;
        int d0 = warp * 8 + 2 * tq;
        int hwA = ((wy * 4 + (gq >> 2)) << 5) + wx * 4 + (gq & 3);
        int hwB = ((wy * 4 + ((gq + 8) >> 2)) << 5) + wx * 4 + ((gq + 8) & 3);
        mbase[(size_t)d0 * HWSZ + hwA]       = f[0];
        mbase[(size_t)(d0 + 1) * HWSZ + hwA] = f[1];
        mbase[(size_t)d0 * HWSZ + hwB]       = f[2];
        mbase[(size_t)(d0 + 1) * HWSZ + hwB] = f[3];
    }
}

// ---------------- depthwise 3x3 + bn2 + gelu (float4) ----------------
__global__ void dw_k(const float* __restrict__ dw,
                     const float* __restrict__ g2, const float* __restrict__ b2,
                     const float* __restrict__ m2, const float* __restrict__ v2) {
    int bc = blockIdx.x;
    int c = bc & (MRC - 1);
    __shared__ float t[1024];
    __shared__ float wsh[9];
    int tid = threadIdx.x;
    const float* p = g_h1 + (size_t)bc * HWSZ;
    ((float4*)t)[tid] = ((const float4*)p)[tid];
    if (tid < 9) wsh[tid] = dw[c * 9 + tid];
    __syncthreads();
    float s = g2[c] * rsqrtf(v2[c] + EPSV);
    float bs = b2[c] - m2[c] * s;
    float* outp = g_h2 + (size_t)bc * HWSZ;
    int y = tid >> 3, x0 = (tid & 7) * 4;
    float4 res;
    float* rp = (float*)&res;
    #pragma unroll
    for (int j = 0; j < 4; j++) {
        int x = x0 + j;
        float acc = 0.f;
        #pragma unroll
        for (int dy = -1; dy <= 1; dy++) {
            int yy = y + dy;
            if (yy < 0 || yy > 31) continue;
            #pragma unroll
            for (int dx = -1; dx <= 1; dx++) {
                int xx = x + dx;
                if (xx < 0 || xx > 31) continue;
                acc += wsh[(dy + 1) * 3 + (dx + 1)] * t[yy * 32 + xx];
            }
        }
        rp[j] = gelu_f(acc * s + bs);
    }
    ((float4*)outp)[tid] = res;
}

// ---------------- launcher ----------------
extern "C" void kernel_launch(void* const* d_in, const int* in_sizes, int n_in,
                              void* d_out, int out_size) {
    const float* x      = (const float*)d_in[0];
    const float* bn0_g  = (const float*)d_in[1];
    const float* bn0_b  = (const float*)d_in[2];
    const float* bn0_m  = (const float*)d_in[3];
    const float* bn0_v  = (const float*)d_in[4];
    const float* w_qkv  = (const float*)d_in[5];
    const float* w_mrg  = (const float*)d_in[6];
    const float* b_mrg  = (const float*)d_in[7];
    const float* w1     = (const float*)d_in[8];
    const float* bn1_g  = (const float*)d_in[9];
    const float* bn1_b  = (const float*)d_in[10];
    const float* bn1_m  = (const float*)d_in[11];
    const float* bn1_v  = (const float*)d_in[12];
    const float* dw     = (const float*)d_in[13];
    const float* bn2_g  = (const float*)d_in[14];
    const float* bn2_b  = (const float*)d_in[15];
    const float* bn2_m  = (const float*)d_in[16];
    const float* bn2_v  = (const float*)d_in[17];
    const float* w2     = (const float*)d_in[18];
    const float* bn3_g  = (const float*)d_in[19];
    const float* bn3_b  = (const float*)d_in[20];
    const float* bn3_m  = (const float*)d_in[21];
    const float* bn3_v  = (const float*)d_in[22];

    float *h0, *qkv, *msg, *x1, *h1, *h2;
    cudaGetSymbolAddress((void**)&h0,  g_h0);
    cudaGetSymbolAddress((void**)&qkv, g_qkv);
    cudaGetSymbolAddress((void**)&msg, g_msg);
    cudaGetSymbolAddress((void**)&x1,  g_x1);
    cudaGetSymbolAddress((void**)&h1,  g_h1);
    cudaGetSymbolAddress((void**)&h2,  g_h2);

    cudaFuncSetAttribute((const void*)mgemm_k<0,3>, cudaFuncAttributeMaxDynamicSharedMemorySize, GEMM_SMEM);
    cudaFuncSetAttribute((const void*)mgemm_k<1,1>, cudaFuncAttributeMaxDynamicSharedMemorySize, GEMM_SMEM);
    cudaFuncSetAttribute((const void*)mgemm_k<2,1>, cudaFuncAttributeMaxDynamicSharedMemorySize, GEMM_SMEM);
    cudaFuncSetAttribute((const void*)mgemm_k<3,1>, cudaFuncAttributeMaxDynamicSharedMemorySize, GEMM_SMEM);

    // 1. h0 = gelu(bn0(x))
    bn0_gelu_k<<<(BB * CC * HWSZ + 255) / 256, 256>>>(x, bn0_g, bn0_b, bn0_m, bn0_v);

    // 2. qkv = w_qkv @ h0   (3-pass: top-k fidelity)
    mgemm_k<0,3><<<dim3(768 / 128, 8, BB), 256, GEMM_SMEM>>>(
        w_qkv, h0, qkv, 768, 256, nullptr, nullptr, nullptr, nullptr, nullptr, nullptr);

    // 3. window means
    wmean_k<<<BB * HEADS, 256>>>();

    // 4. affinity + top-4
    topk_k<<<BB * HEADS, 256>>>();

    // 5. gathered attention (HMMA)
    attn_k<<<BB * HEADS * NWIN, 128>>>();

    // 6. x1 = x + w_merge @ msg + b_merge   (1-pass)
    mgemm_k<1,1><<<dim3(CC / 128, 8, BB), 256, GEMM_SMEM>>>(
        w_mrg, msg, x1, CC, 256, x, b_mrg, nullptr, nullptr, nullptr, nullptr);

    // 7. h1 = gelu(bn1(w1 @ x1))   (1-pass)
    mgemm_k<2,1><<<dim3(MRC / 128, 8, BB), 256, GEMM_SMEM>>>(
        w1, x1, h1, MRC, 256, nullptr, nullptr, bn1_g, bn1_b, bn1_m, bn1_v);

    // 8. h2 = gelu(bn2(dwconv3x3(h1)))
    dw_k<<<BB * MRC, 256>>>(dw, bn2_g, bn2_b, bn2_m, bn2_v);

    // 9. out = x1 + bn3(w2 @ h2)   (1-pass)
    mgemm_k<3,1><<<dim3(CC / 128, 8, BB), 256, GEMM_SMEM>>>(
        w2, h2, (float*)d_out, CC, 1024, x1, nullptr, bn3_g, bn3_b, bn3_m, bn3_v);
}

// round 7
// speedup vs baseline: 1.2563x; 1.1375x over previous
#include <cuda_runtime.h>
#include <cuda_fp16.h>
#include <cstdint>
#include <math.h>

// ---------------- problem constants ----------------
#define BB   16
#define CC   256
#define HWSZ 1024
#define DH   32
#define HEADS 8
#define KTOP 4
#define MRC  1024
#define NWIN 64
#define EPSV 1e-5f

// pre-split weight offsets (halves)
#define WOFF_QKV 0
#define WOFF_MRG 196608
#define WOFF_W1  262144
#define WOFF_W2  524288
#define WTOT     786432

// ---------------- device scratch ----------------
__device__ float  g_h0 [BB * CC  * HWSZ];
__device__ float  g_qkv[BB * 3*CC * HWSZ];
__device__ float  g_qm [BB * HEADS * NWIN * DH];
__device__ float  g_km [BB * HEADS * NWIN * DH];
__device__ int    g_idx[BB * HEADS * NWIN * KTOP];
__device__ float  g_msg[BB * CC  * HWSZ];
__device__ float  g_x1 [BB * CC  * HWSZ];
__device__ float  g_h1 [BB * MRC * HWSZ];
__device__ float  g_h2 [BB * MRC * HWSZ];
__device__ __half g_wh [WTOT];
__device__ __half g_wl [196608];   // lo only for qkv

__device__ __forceinline__ float gelu_f(float x) {
    return 0.5f * x * (1.0f + erff(x * 0.7071067811865475f));
}

// ---------------- fp16 warp MMA + ldmatrix ----------------
__device__ __forceinline__ void mma_f16(float* d, const uint32_t* a, uint32_t b0, uint32_t b1) {
    asm volatile(
        "mma.sync.aligned.m16n8k16.row.col.f32.f16.f16.f32 "
        "{%0,%1,%2,%3}, {%4,%5,%6,%7}, {%8,%9}, {%0,%1,%2,%3};"
        : "+f"(d[0]), "+f"(d[1]), "+f"(d[2]), "+f"(d[3])
        : "r"(a[0]), "r"(a[1]), "r"(a[2]), "r"(a[3]), "r"(b0), "r"(b1));
}
__device__ __forceinline__ void ldsm_x2_t(uint32_t& r0, uint32_t& r1, uint32_t addr) {
    asm volatile("ldmatrix.sync.aligned.m8n8.x2.trans.shared.b16 {%0,%1}, [%2];"
                 : "=r"(r0), "=r"(r1) : "r"(addr));
}
__device__ __forceinline__ uint32_t smem_u32(const void* p) {
    uint32_t a;
    asm("{ .reg .u64 t; cvta.to.shared.u64 t, %1; cvt.u32.u64 %0, t; }" : "=r"(a) : "l"(p));
    return a;
}
__device__ __forceinline__ void cvt_split(float x, __half& h, __half& l) {
    h = __float2half_rn(x);
    l = __float2half_rn(x - __half2float(h));
}

// smem layout (per stage, bytes): WH@0 (128x40h=10240), WL@10240,
// AH@20480 (32x136h=8704), AL@29184. stage=37888.
#define WH_OFF 0
#define WL_OFF 10240
#define AH_OFF 20480
#define AL_OFF 29184
#define A_STR  136
#define STAGE_BYTES 37888
#define GEMM_SMEM (2 * STAGE_BYTES)

// ---------------- weight pre-split ----------------
__global__ void wsplit_k(const float* __restrict__ wqkv, const float* __restrict__ wmrg,
                         const float* __restrict__ w1,   const float* __restrict__ w2) {
    int i = blockIdx.x * 256 + threadIdx.x;
    if (i >= WTOT) return;
    if (i < WOFF_MRG) {
        __half h, l; cvt_split(wqkv[i], h, l);
        g_wh[i] = h; g_wl[i] = l;
    } else if (i < WOFF_W1) {
        g_wh[i] = __float2half_rn(wmrg[i - WOFF_MRG]);
    } else if (i < WOFF_W2) {
        g_wh[i] = __float2half_rn(w1[i - WOFF_W1]);
    } else {
        g_wh[i] = __float2half_rn(w2[i - WOFF_W2]);
    }
}

// ---------------- kernel: h0 = gelu(bn0(x)) ----------------
__global__ void bn0_gelu_k(const float* __restrict__ x,
                           const float* __restrict__ g, const float* __restrict__ b,
                           const float* __restrict__ m, const float* __restrict__ v) {
    int i = blockIdx.x * 256 + threadIdx.x;
    if (i >= BB * CC * HWSZ) return;
    int c = (i >> 10) & (CC - 1);
    float s = g[c] * rsqrtf(v[c] + EPSV);
    g_h0[i] = gelu_f((x[i] - m[c]) * s + b[c]);
}

// ---------------- tensor-core fused GEMM ----------------
// PASSES: 1 = hiW*hiA; 3 = + loW*hiA + hiW*loA (weights pre-split in g_wh/g_wl)
template<int MODE, int PASSES>
__global__ void __launch_bounds__(256, 1)
mgemm_k(const __half* __restrict__ Whg, const __half* __restrict__ Wlg,
        const float* __restrict__ A, float* __restrict__ Out, int O, int Kd,
        const float* __restrict__ Res, const float* __restrict__ bias,
        const float* __restrict__ g,  const float* __restrict__ bb,
        const float* __restrict__ mm, const float* __restrict__ vv) {
    extern __shared__ char smc[];
    const int tid = threadIdx.x, lane = tid & 31, warp = tid >> 5;
    const int b = blockIdx.z, om = blockIdx.x * 128, n0 = blockIdx.y * 128;
    const int wm = warp >> 1, wn = warp & 1;
    const int gq = lane >> 2, tq = lane & 3;
    const uint32_t smbase = smem_u32(smc);

    const float* Ab = A + (size_t)b * Kd * HWSZ + n0;

    float acc[2][8][4];
    #pragma unroll
    for (int mt = 0; mt < 2; mt++)
        #pragma unroll
        for (int nt = 0; nt < 8; nt++)
            #pragma unroll
            for (int r = 0; r < 4; r++) acc[mt][nt][r] = 0.f;

    const int acr = tid >> 5;          // 0..7 (A k-row within group of 8)
    const int acn = (tid & 31) * 4;    // A n-col
    const int wrow = tid >> 2;         // handled via e below
    (void)wrow;
    // ldmatrix per-lane offset (bytes) within A tile
    const uint32_t aoff = (uint32_t)(((lane & 15) * A_STR + wn * 64) * 2);

    uint4 wvh[2], wvl[2];
    float4 av[4];
    const int nch = Kd >> 5;

    // ---- helpers ----
    auto load_chunk = [&](int k0) {
        #pragma unroll
        for (int it = 0; it < 2; it++) {
            int e = tid + it * 256;
            int row = e >> 2, c4 = e & 3;
            wvh[it] = *(const uint4*)(Whg + (size_t)(om + row) * Kd + k0 + c4 * 8);
            if (PASSES >= 3)
                wvl[it] = *(const uint4*)(Wlg + (size_t)(om + row) * Kd + k0 + c4 * 8);
        }
        #pragma unroll
        for (int it = 0; it < 4; it++)
            av[it] = *(const float4*)(Ab + (size_t)(k0 + it * 8 + acr) * HWSZ + acn);
    };
    auto store_chunk = [&](char* st) {
        #pragma unroll
        for (int it = 0; it < 2; it++) {
            int e = tid + it * 256;
            int row = e >> 2, c4 = e & 3;
            *(uint4*)(st + WH_OFF + row * 80 + c4 * 16) = wvh[it];
            if (PASSES >= 3)
                *(uint4*)(st + WL_OFF + row * 80 + c4 * 16) = wvl[it];
        }
        #pragma unroll
        for (int it = 0; it < 4; it++) {
            int k = it * 8 + acr;
            __half2 h0 = __floats2half2_rn(av[it].x, av[it].y);
            __half2 h1 = __floats2half2_rn(av[it].z, av[it].w);
            uint2 u; u.x = *(uint32_t*)&h0; u.y = *(uint32_t*)&h1;
            *(uint2*)(st + AH_OFF + (k * A_STR + acn) * 2) = u;
            if (PASSES >= 3) {
                float lx = av[it].x - __low2float(h0);
                float ly = av[it].y - __high2float(h0);
                float lz = av[it].z - __low2float(h1);
                float lw = av[it].w - __high2float(h1);
                __half2 l0 = __floats2half2_rn(lx, ly);
                __half2 l1 = __floats2half2_rn(lz, lw);
                uint2 ul; ul.x = *(uint32_t*)&l0; ul.y = *(uint32_t*)&l1;
                *(uint2*)(st + AL_OFF + (k * A_STR + acn) * 2) = ul;
            }
        }
    };

    load_chunk(0);
    store_chunk(smc);
    __syncthreads();

    for (int ch = 0; ch < nch; ch++) {
        int s = ch & 1;
        char* st = smc + s * STAGE_BYTES;
        uint32_t stu = smbase + (uint32_t)s * STAGE_BYTES;

        if (ch + 1 < nch) load_chunk((ch + 1) << 5);

        const __half* ws_hi = (const __half*)(st + WH_OFF);
        const __half* ws_lo = (const __half*)(st + WL_OFF);

        #pragma unroll
        for (int ks = 0; ks < 2; ks++) {
            uint32_t afh[2][4], afl[2][4];
            #pragma unroll
            for (int mt = 0; mt < 2; mt++) {
                int rb = wm * 32 + mt * 16;
                int cb = ks * 16 + 2 * tq;
                afh[mt][0] = *(const uint32_t*)&ws_hi[(rb + gq)     * 40 + cb];
                afh[mt][1] = *(const uint32_t*)&ws_hi[(rb + gq + 8) * 40 + cb];
                afh[mt][2] = *(const uint32_t*)&ws_hi[(rb + gq)     * 40 + cb + 8];
                afh[mt][3] = *(const uint32_t*)&ws_hi[(rb + gq + 8) * 40 + cb + 8];
                if (PASSES >= 3) {
                    afl[mt][0] = *(const uint32_t*)&ws_lo[(rb + gq)     * 40 + cb];
                    afl[mt][1] = *(const uint32_t*)&ws_lo[(rb + gq + 8) * 40 + cb];
                    afl[mt][2] = *(const uint32_t*)&ws_lo[(rb + gq)     * 40 + cb + 8];
                    afl[mt][3] = *(const uint32_t*)&ws_lo[(rb + gq + 8) * 40 + cb + 8];
                }
            }
            uint32_t abase_h = stu + AH_OFF + aoff + (uint32_t)ks * (16 * A_STR * 2);
            uint32_t abase_l = stu + AL_OFF + aoff + (uint32_t)ks * (16 * A_STR * 2);
            #pragma unroll
            for (int nt = 0; nt < 8; nt++) {
                uint32_t bh0, bh1;
                ldsm_x2_t(bh0, bh1, abase_h + nt * 16);
                #pragma unroll
                for (int mt = 0; mt < 2; mt++) {
                    mma_f16(acc[mt][nt], afh[mt], bh0, bh1);
                    if (PASSES >= 3) mma_f16(acc[mt][nt], afl[mt], bh0, bh1);
                }
                if (PASSES >= 3) {
                    uint32_t bl0, bl1;
                    ldsm_x2_t(bl0, bl1, abase_l + nt * 16);
                    #pragma unroll
                    for (int mt = 0; mt < 2; mt++)
                        mma_f16(acc[mt][nt], afh[mt], bl0, bl1);
                }
            }
        }

        if (ch + 1 < nch) store_chunk(smc + (s ^ 1) * STAGE_BYTES);
        __syncthreads();
    }

    // ---- epilogue ----
    #pragma unroll
    for (int mt = 0; mt < 2; mt++) {
        int o0 = om + wm * 32 + mt * 16 + gq;
        int o1 = o0 + 8;
        float s0 = 0.f, bs0 = 0.f, s1 = 0.f, bs1 = 0.f, bi0 = 0.f, bi1 = 0.f;
        if (MODE == 2 || MODE == 3) {
            s0 = g[o0] * rsqrtf(vv[o0] + EPSV); bs0 = bb[o0] - mm[o0] * s0;
            s1 = g[o1] * rsqrtf(vv[o1] + EPSV); bs1 = bb[o1] - mm[o1] * s1;
        }
        if (MODE == 1) { bi0 = bias[o0]; bi1 = bias[o1]; }
        #pragma unroll
        for (int nt = 0; nt < 8; nt++) {
            int n = n0 + wn * 64 + nt * 8 + 2 * tq;
            size_t oi0 = ((size_t)b * O + o0) * HWSZ + n;
            size_t oi1 = ((size_t)b * O + o1) * HWSZ + n;
            float r0 = acc[mt][nt][0], r1 = acc[mt][nt][1];
            float r2 = acc[mt][nt][2], r3 = acc[mt][nt][3];
            if (MODE == 1) {
                float2 e0 = *(const float2*)&Res[oi0];
                float2 e1 = *(const float2*)&Res[oi1];
                r0 += e0.x + bi0; r1 += e0.y + bi0;
                r2 += e1.x + bi1; r3 += e1.y + bi1;
            }
            if (MODE == 2) {
                r0 = gelu_f(r0 * s0 + bs0); r1 = gelu_f(r1 * s0 + bs0);
                r2 = gelu_f(r2 * s1 + bs1); r3 = gelu_f(r3 * s1 + bs1);
            }
            if (MODE == 3) {
                float2 e0 = *(const float2*)&Res[oi0];
                float2 e1 = *(const float2*)&Res[oi1];
                r0 = e0.x + r0 * s0 + bs0; r1 = e0.y + r1 * s0 + bs0;
                r2 = e1.x + r2 * s1 + bs1; r3 = e1.y + r3 * s1 + bs1;
            }
            float2 v0 = {r0, r1}, v1 = {r2, r3};
            *(float2*)&Out[oi0] = v0;
            *(float2*)&Out[oi1] = v1;
        }
    }
}

// ---------------- window means (coalesced): block per (b,h) ----------------
__global__ void wmean_k() {
    int bh = blockIdx.x;
    int b = bh >> 3, h = bh & 7;
    int tid = threadIdx.x;
    __shared__ float spq[256], spk[256];
    const float* qpl = g_qkv + ((size_t)b * 3 * CC + h * DH) * HWSZ;
    const float* kpl = qpl + (size_t)CC * HWSZ;
    for (int d = 0; d < DH; d++) {
        float4 vq = ((const float4*)(qpl + (size_t)d * HWSZ))[tid];
        float4 vk = ((const float4*)(kpl + (size_t)d * HWSZ))[tid];
        spq[tid] = vq.x + vq.y + vq.z + vq.w;
        spk[tid] = vk.x + vk.y + vk.z + vk.w;
        __syncthreads();
        if (tid < 64) {
            int wy = tid >> 3, wx = tid & 7;
            int base = wy * 32 + wx;
            float sq = spq[base] + spq[base + 8] + spq[base + 16] + spq[base + 24];
            float sk = spk[base] + spk[base + 8] + spk[base + 16] + spk[base + 24];
            g_qm[((size_t)bh * 64 + tid) * DH + d] = sq * 0.0625f;
            g_km[((size_t)bh * 64 + tid) * DH + d] = sk * 0.0625f;
        }
        __syncthreads();
    }
}

// ---------------- affinity + exact top-4 ----------------
__global__ void topk_k() {
    int bh = blockIdx.x;
    __shared__ float kt[32][65];
    __shared__ float qs[64][32];
    int tid = threadIdx.x, warp = tid >> 5, lane = tid & 31;
    for (int e = tid; e < 2048; e += 256) {
        int j = e >> 5, d = e & 31;
        kt[d][j] = g_km[(size_t)bh * 2048 + e];
        qs[j][d] = g_qm[(size_t)bh * 2048 + e];
    }
    __syncthreads();
    for (int ii = 0; ii < 8; ii++) {
        int i = warp * 8 + ii;
        float s0 = 0.f, s1 = 0.f;
        #pragma unroll
        for (int d = 0; d < 32; d++) {
            float q = qs[i][d];
            s0 += q * kt[d][lane];
            s1 += q * kt[d][lane + 32];
        }
        float v0 = s0, v1 = s1;
        #pragma unroll
        for (int t = 0; t < KTOP; t++) {
            float bvv; int bj;
            if (v0 >= v1) { bvv = v0; bj = lane; } else { bvv = v1; bj = lane + 32; }
            #pragma unroll
            for (int off = 16; off; off >>= 1) {
                float ov = __shfl_xor_sync(0xffffffffu, bvv, off);
                int   oj = __shfl_xor_sync(0xffffffffu, bj,  off);
                if (ov > bvv || (ov == bvv && oj < bj)) { bvv = ov; bj = oj; }
            }
            if (lane == 0) g_idx[((size_t)bh * 64 + i) * KTOP + t] = bj;
            if (bj == lane)      v0 = -INFINITY;
            if (bj == lane + 32) v1 = -INFINITY;
        }
    }
}

// ---------------- gathered window attention (HMMA, 3-pass) ----------------
#define QK_STR 40
#define V_STR  72
#define SS_STR 68
#define P_STR  72
__global__ void __launch_bounds__(128) attn_k() {
    int bid = blockIdx.x;
    int n = bid & 63;
    int h = (bid >> 6) & 7;
    int b = bid >> 9;
    __shared__ __half qh[16 * QK_STR], ql[16 * QK_STR];
    __shared__ __half kh[64 * QK_STR], kl[64 * QK_STR];
    __shared__ __half vh[32 * V_STR],  vl[32 * V_STR];
    __shared__ float  ss[16 * SS_STR];
    __shared__ __half ph[16 * P_STR], pl[16 * P_STR];
    __shared__ int    widx[KTOP];
    int tid = threadIdx.x;
    if (tid < KTOP) widx[tid] = g_idx[(size_t)bid * KTOP + tid];
    __syncthreads();

    int wy = n >> 3, wx = n & 7;
    const float* qbase = g_qkv + ((size_t)b * 3 * CC + h * DH) * HWSZ;
    const float* kbase = qbase + (size_t)CC * HWSZ;
    const float* vbase = qbase + (size_t)2 * CC * HWSZ;

    for (int e = tid; e < 512; e += 128) {
        int d = e >> 4, t = e & 15;
        int hw = ((wy * 4 + (t >> 2)) << 5) + wx * 4 + (t & 3);
        __half hv, lv; cvt_split(qbase[(size_t)d * HWSZ + hw], hv, lv);
        qh[t * QK_STR + d] = hv; ql[t * QK_STR + d] = lv;
    }
    for (int e = tid; e < 2048; e += 128) {
        int d = e >> 6, kt = e & 63;
        int j = widx[kt >> 4];
        int t = kt & 15;
        int hw = (((j >> 3) * 4 + (t >> 2)) << 5) + (j & 7) * 4 + (t & 3);
        __half hv, lv; cvt_split(kbase[(size_t)d * HWSZ + hw], hv, lv);
        kh[kt * QK_STR + d] = hv; kl[kt * QK_STR + d] = lv;
    }
    for (int e = tid; e < 2048; e += 128) {
        int d = e >> 6, kt = e & 63;
        int j = widx[kt >> 4];
        int t = kt & 15;
        int hw = (((j >> 3) * 4 + (t >> 2)) << 5) + (j & 7) * 4 + (t & 3);
        __half hv, lv; cvt_split(vbase[(size_t)d * HWSZ + hw], hv, lv);
        vh[d * V_STR + kt] = hv; vl[d * V_STR + kt] = lv;
    }
    __syncthreads();

    int warp = tid >> 5, lane = tid & 31;
    int gq = lane >> 2, tq = lane & 3;
    const float scale = 0.17677669529663687f;

    {
        float sc0[4] = {0.f, 0.f, 0.f, 0.f};
        float sc1[4] = {0.f, 0.f, 0.f, 0.f};
        #pragma unroll
        for (int ks = 0; ks < 2; ks++) {
            int cb = ks * 16 + 2 * tq;
            uint32_t ah[4], al[4];
            ah[0] = *(const uint32_t*)&qh[gq * QK_STR + cb];
            ah[1] = *(const uint32_t*)&qh[(gq + 8) * QK_STR + cb];
            ah[2] = *(const uint32_t*)&qh[gq * QK_STR + cb + 8];
            ah[3] = *(const uint32_t*)&qh[(gq + 8) * QK_STR + cb + 8];
            al[0] = *(const uint32_t*)&ql[gq * QK_STR + cb];
            al[1] = *(const uint32_t*)&ql[(gq + 8) * QK_STR + cb];
            al[2] = *(const uint32_t*)&ql[gq * QK_STR + cb + 8];
            al[3] = *(const uint32_t*)&ql[(gq + 8) * QK_STR + cb + 8];
            #pragma unroll
            for (int nt = 0; nt < 2; nt++) {
                int key = warp * 16 + nt * 8 + gq;
                uint32_t bh0 = *(const uint32_t*)&kh[key * QK_STR + cb];
                uint32_t bh1 = *(const uint32_t*)&kh[key * QK_STR + cb + 8];
                uint32_t bl0 = *(const uint32_t*)&kl[key * QK_STR + cb];
                uint32_t bl1 = *(const uint32_t*)&kl[key * QK_STR + cb + 8];
                float* sc = nt ? sc1 : sc0;
                mma_f16(sc, ah, bh0, bh1);
                mma_f16(sc, ah, bl0, bl1);
                mma_f16(sc, al, bh0, bh1);
            }
        }
        #pragma unroll
        for (int nt = 0; nt < 2; nt++) {
            const float* sc = nt ? sc1 : sc0;
            int c0 = warp * 16 + nt * 8 + 2 * tq;
            ss[gq * SS_STR + c0]           = sc[0] * scale;
            ss[gq * SS_STR + c0 + 1]       = sc[1] * scale;
            ss[(gq + 8) * SS_STR + c0]     = sc[2] * scale;
            ss[(gq + 8) * SS_STR + c0 + 1] = sc[3] * scale;
        }
    }
    __syncthreads();

    #pragma unroll
    for (int rr = 0; rr < 4; rr++) {
        int row = warp * 4 + rr;
        float s0 = ss[row * SS_STR + lane];
        float s1 = ss[row * SS_STR + lane + 32];
        float mx = fmaxf(s0, s1);
        #pragma unroll
        for (int off = 16; off; off >>= 1) mx = fmaxf(mx, __shfl_xor_sync(0xffffffffu, mx, off));
        float e0 = expf(s0 - mx), e1 = expf(s1 - mx);
        float sum = e0 + e1;
        #pragma unroll
        for (int off = 16; off; off >>= 1) sum += __shfl_xor_sync(0xffffffffu, sum, off);
        float inv = 1.0f / sum;
        __half hv, lv;
        cvt_split(e0 * inv, hv, lv);
        ph[row * P_STR + lane] = hv; pl[row * P_STR + lane] = lv;
        cvt_split(e1 * inv, hv, lv);
        ph[row * P_STR + lane + 32] = hv; pl[row * P_STR + lane + 32] = lv;
    }
    __syncthreads();

    {
        float f[4] = {0.f, 0.f, 0.f, 0.f};
        #pragma unroll
        for (int ks = 0; ks < 4; ks++) {
            int cb = ks * 16 + 2 * tq;
            uint32_t ah[4], al[4];
            ah[0] = *(const uint32_t*)&ph[gq * P_STR + cb];
            ah[1] = *(const uint32_t*)&ph[(gq + 8) * P_STR + cb];
            ah[2] = *(const uint32_t*)&ph[gq * P_STR + cb + 8];
            ah[3] = *(const uint32_t*)&ph[(gq + 8) * P_STR + cb + 8];
            al[0] = *(const uint32_t*)&pl[gq * P_STR + cb];
            al[1] = *(const uint32_t*)&pl[(gq + 8) * P_STR + cb];
            al[2] = *(const uint32_t*)&pl[gq * P_STR + cb + 8];
            al[3] = *(const uint32_t*)&pl[(gq + 8) * P_STR + cb + 8];
            int d = warp * 8 + gq;
            uint32_t bh0 = *(const uint32_t*)&vh[d * V_STR + cb];
            uint32_t bh1 = *(const uint32_t*)&vh[d * V_STR + cb + 8];
            uint32_t bl0 = *(const uint32_t*)&vl[d * V_STR + cb];
            uint32_t bl1 = *(const uint32_t*)&vl[d * V_STR + cb + 8];
            mma_f16(f, ah, bh0, bh1);
            mma_f16(f, ah, bl0, bl1);
            mma_f16(f, al, bh0, bh1);
        }
        float* mbase = g_msg + ((size_t)b * CC + h * DH) * HWSZ;
        int d0 = warp * 8 + 2 * tq;
        int hwA = ((wy * 4 + (gq >> 2)) << 5) + wx * 4 + (gq & 3);
        int hwB = ((wy * 4 + ((gq + 8) >> 2)) << 5) + wx * 4 + ((gq + 8) & 3);
        mbase[(size_t)d0 * HWSZ + hwA]       = f[0];
        mbase[(size_t)(d0 + 1) * HWSZ + hwA] = f[1];
        mbase[(size_t)d0 * HWSZ + hwB]       = f[2];
        mbase[(size_t)(d0 + 1) * HWSZ + hwB] = f[3];
    }
}

// ---------------- depthwise 3x3 + bn2 + gelu (float4) ----------------
__global__ void dw_k(const float* __restrict__ dw,
                     const float* __restrict__ g2, const float* __restrict__ b2,
                     const float* __restrict__ m2, const float* __restrict__ v2) {
    int bc = blockIdx.x;
    int c = bc & (MRC - 1);
    __shared__ float t[1024];
    __shared__ float wsh[9];
    int tid = threadIdx.x;
    const float* p = g_h1 + (size_t)bc * HWSZ;
    ((float4*)t)[tid] = ((const float4*)p)[tid];
    if (tid < 9) wsh[tid] = dw[c * 9 + tid];
    __syncthreads();
    float s = g2[c] * rsqrtf(v2[c] + EPSV);
    float bs = b2[c] - m2[c] * s;
    float* outp = g_h2 + (size_t)bc * HWSZ;
    int y = tid >> 3, x0 = (tid & 7) * 4;
    float4 res;
    float* rp = (float*)&res;
    #pragma unroll
    for (int j = 0; j < 4; j++) {
        int x = x0 + j;
        float acc = 0.f;
        #pragma unroll
        for (int dy = -1; dy <= 1; dy++) {
            int yy = y + dy;
            if (yy < 0 || yy > 31) continue;
            #pragma unroll
            for (int dx = -1; dx <= 1; dx++) {
                int xx = x + dx;
                if (xx < 0 || xx > 31) continue;
                acc += wsh[(dy + 1) * 3 + (dx + 1)] * t[yy * 32 + xx];
            }
        }
        rp[j] = gelu_f(acc * s + bs);
    }
    ((float4*)outp)[tid] = res;
}

// ---------------- launcher ----------------
extern "C" void kernel_launch(void* const* d_in, const int* in_sizes, int n_in,
                              void* d_out, int out_size) {
    const float* x      = (const float*)d_in[0];
    const float* bn0_g  = (const float*)d_in[1];
    const float* bn0_b  = (const float*)d_in[2];
    const float* bn0_m  = (const float*)d_in[3];
    const float* bn0_v  = (const float*)d_in[4];
    const float* w_qkv  = (const float*)d_in[5];
    const float* w_mrg  = (const float*)d_in[6];
    const float* b_mrg  = (const float*)d_in[7];
    const float* w1     = (const float*)d_in[8];
    const float* bn1_g  = (const float*)d_in[9];
    const float* bn1_b  = (const float*)d_in[10];
    const float* bn1_m  = (const float*)d_in[11];
    const float* bn1_v  = (const float*)d_in[12];
    const float* dw     = (const float*)d_in[13];
    const float* bn2_g  = (const float*)d_in[14];
    const float* bn2_b  = (const float*)d_in[15];
    const float* bn2_m  = (const float*)d_in[16];
    const float* bn2_v  = (const float*)d_in[17];
    const float* w2     = (const float*)d_in[18];
    const float* bn3_g  = (const float*)d_in[19];
    const float* bn3_b  = (const float*)d_in[20];
    const float* bn3_m  = (const float*)d_in[21];
    const float* bn3_v  = (const float*)d_in[22];

    float *h0, *qkv, *msg, *x1, *h1, *h2;
    __half *wh, *wl;
    cudaGetSymbolAddress((void**)&h0,  g_h0);
    cudaGetSymbolAddress((void**)&qkv, g_qkv);
    cudaGetSymbolAddress((void**)&msg, g_msg);
    cudaGetSymbolAddress((void**)&x1,  g_x1);
    cudaGetSymbolAddress((void**)&h1,  g_h1);
    cudaGetSymbolAddress((void**)&h2,  g_h2);
    cudaGetSymbolAddress((void**)&wh,  g_wh);
    cudaGetSymbolAddress((void**)&wl,  g_wl);

    cudaFuncSetAttribute((const void*)mgemm_k<0,3>, cudaFuncAttributeMaxDynamicSharedMemorySize, GEMM_SMEM);
    cudaFuncSetAttribute((const void*)mgemm_k<1,1>, cudaFuncAttributeMaxDynamicSharedMemorySize, GEMM_SMEM);
    cudaFuncSetAttribute((const void*)mgemm_k<2,1>, cudaFuncAttributeMaxDynamicSharedMemorySize, GEMM_SMEM);
    cudaFuncSetAttribute((const void*)mgemm_k<3,1>, cudaFuncAttributeMaxDynamicSharedMemorySize, GEMM_SMEM);

    // 0. pre-split weights to fp16
    wsplit_k<<<(WTOT + 255) / 256, 256>>>(w_qkv, w_mrg, w1, w2);

    // 1. h0 = gelu(bn0(x))
    bn0_gelu_k<<<(BB * CC * HWSZ + 255) / 256, 256>>>(x, bn0_g, bn0_b, bn0_m, bn0_v);

    // 2. qkv = w_qkv @ h0   (3-pass)
    mgemm_k<0,3><<<dim3(768 / 128, 8, BB), 256, GEMM_SMEM>>>(
        wh + WOFF_QKV, wl, h0, qkv, 768, 256, nullptr, nullptr, nullptr, nullptr, nullptr, nullptr);

    // 3. window means
    wmean_k<<<BB * HEADS, 256>>>();

    // 4. affinity + top-4
    topk_k<<<BB * HEADS, 256>>>();

    // 5. gathered attention (HMMA)
    attn_k<<<BB * HEADS * NWIN, 128>>>();

    // 6. x1 = x + w_merge @ msg + b_merge   (1-pass)
    mgemm_k<1,1><<<dim3(CC / 128, 8, BB), 256, GEMM_SMEM>>>(
        wh + WOFF_MRG, nullptr, msg, x1, CC, 256, x, b_mrg, nullptr, nullptr, nullptr, nullptr);

    // 7. h1 = gelu(bn1(w1 @ x1))   (1-pass)
    mgemm_k<2,1><<<dim3(MRC / 128, 8, BB), 256, GEMM_SMEM>>>(
        wh + WOFF_W1, nullptr, x1, h1, MRC, 256, nullptr, nullptr, bn1_g, bn1_b, bn1_m, bn1_v);

    // 8. h2 = gelu(bn2(dwconv3x3(h1)))
    dw_k<<<BB * MRC, 256>>>(dw, bn2_g, bn2_b, bn2_m, bn2_v);

    // 9. out = x1 + bn3(w2 @ h2)   (1-pass)
    mgemm_k<3,1><<<dim3(CC / 128, 8, BB), 256, GEMM_SMEM>>>(
        wh + WOFF_W2, nullptr, h2, (float*)d_out, CC, 1024, x1, nullptr, bn3_g, bn3_b, bn3_m, bn3_v);
}

// round 8
// speedup vs baseline: 1.4428x; 1.1484x over previous
#include <cuda_runtime.h>
#include <cuda_fp16.h>
#include <cstdint>
#include <math.h>

// ---------------- problem constants ----------------
#define BB   16
#define CC   256
#define HWSZ 1024
#define DH   32
#define HEADS 8
#define KTOP 4
#define MRC  1024
#define NWIN 64
#define EPSV 1e-5f

// pre-split weight offsets (halves)
#define WOFF_QKV 0
#define WOFF_MRG 196608
#define WOFF_W1  262144
#define WOFF_W2  524288
#define WTOT     786432

// ---------------- device scratch ----------------
__device__ float  g_qkv [BB * 3*CC * HWSZ];
__device__ float  g_qm  [BB * HEADS * NWIN * DH];
__device__ float  g_km  [BB * HEADS * NWIN * DH];
__device__ int    g_idx [BB * HEADS * NWIN * KTOP];
__device__ float  g_x1  [BB * CC  * HWSZ];
__device__ __half g_h0h [BB * CC  * HWSZ];
__device__ __half g_h0l [BB * CC  * HWSZ];
__device__ __half g_msgh[BB * CC  * HWSZ];
__device__ __half g_x1h [BB * CC  * HWSZ];
__device__ __half g_h1h [BB * MRC * HWSZ];
__device__ __half g_h2h [BB * MRC * HWSZ];
__device__ __half g_wh  [WTOT];
__device__ __half g_wl  [196608];   // lo only for qkv

__device__ __forceinline__ float gelu_f(float x) {
    return 0.5f * x * (1.0f + erff(x * 0.7071067811865475f));
}

// ---------------- fp16 warp MMA + ldmatrix ----------------
__device__ __forceinline__ void mma_f16(float* d, const uint32_t* a, uint32_t b0, uint32_t b1) {
    asm volatile(
        "mma.sync.aligned.m16n8k16.row.col.f32.f16.f16.f32 "
        "{%0,%1,%2,%3}, {%4,%5,%6,%7}, {%8,%9}, {%0,%1,%2,%3};"
        : "+f"(d[0]), "+f"(d[1]), "+f"(d[2]), "+f"(d[3])
        : "r"(a[0]), "r"(a[1]), "r"(a[2]), "r"(a[3]), "r"(b0), "r"(b1));
}
__device__ __forceinline__ void ldsm_x2_t(uint32_t& r0, uint32_t& r1, uint32_t addr) {
    asm volatile("ldmatrix.sync.aligned.m8n8.x2.trans.shared.b16 {%0,%1}, [%2];"
                 : "=r"(r0), "=r"(r1) : "r"(addr));
}
__device__ __forceinline__ uint32_t smem_u32(const void* p) {
    uint32_t a;
    asm("{ .reg .u64 t; cvta.to.shared.u64 t, %1; cvt.u32.u64 %0, t; }" : "=r"(a) : "l"(p));
    return a;
}
__device__ __forceinline__ void cvt_split(float x, __half& h, __half& l) {
    h = __float2half_rn(x);
    l = __float2half_rn(x - __half2float(h));
}

#define A_STR 136

// ---------------- weight pre-split ----------------
__global__ void wsplit_k(const float* __restrict__ wqkv, const float* __restrict__ wmrg,
                         const float* __restrict__ w1,   const float* __restrict__ w2) {
    int i = blockIdx.x * 256 + threadIdx.x;
    if (i >= WTOT) return;
    if (i < WOFF_MRG) {
        __half h, l; cvt_split(wqkv[i], h, l);
        g_wh[i] = h; g_wl[i] = l;
    } else if (i < WOFF_W1) {
        g_wh[i] = __float2half_rn(wmrg[i - WOFF_MRG]);
    } else if (i < WOFF_W2) {
        g_wh[i] = __float2half_rn(w1[i - WOFF_W1]);
    } else {
        g_wh[i] = __float2half_rn(w2[i - WOFF_W2]);
    }
}

// ---------------- h0 = gelu(bn0(x)) -> fp16 hi/lo planes ----------------
__global__ void bn0_gelu_k(const float* __restrict__ x,
                           const float* __restrict__ g, const float* __restrict__ b,
                           const float* __restrict__ m, const float* __restrict__ v) {
    int i = blockIdx.x * 256 + threadIdx.x;      // over 4M float4 groups
    if (i >= BB * CC * HWSZ / 4) return;
    int c = (i >> 8) & (CC - 1);
    float s = g[c] * rsqrtf(v[c] + EPSV);
    float sh = b[c] - m[c] * s;
    float4 xv = ((const float4*)x)[i];
    float f0 = gelu_f(xv.x * s + sh), f1 = gelu_f(xv.y * s + sh);
    float f2 = gelu_f(xv.z * s + sh), f3 = gelu_f(xv.w * s + sh);
    __half h0, l0, h1, l1, h2, l2, h3, l3;
    cvt_split(f0, h0, l0); cvt_split(f1, h1, l1);
    cvt_split(f2, h2, l2); cvt_split(f3, h3, l3);
    __half hh[4] = {h0, h1, h2, h3};
    __half ll[4] = {l0, l1, l2, l3};
    ((uint2*)g_h0h)[i] = *(uint2*)hh;
    ((uint2*)g_h0l)[i] = *(uint2*)ll;
}

// ---------------- tensor-core fused GEMM (fp16-resident A) ----------------
// PASSES: 1 = hiW*hiA; 3 = + loW*hiA + hiW*loA
template<int MODE, int PASSES, int WF32, int WF16>
__global__ void __launch_bounds__(256, 2)
mgemm_k(const __half* __restrict__ Whg, const __half* __restrict__ Wlg,
        const __half* __restrict__ Ahg, const __half* __restrict__ Alg,
        float* __restrict__ Out, __half* __restrict__ Outh, int O, int Kd,
        const float* __restrict__ Res, const float* __restrict__ bias,
        const float* __restrict__ g,  const float* __restrict__ bb,
        const float* __restrict__ mm, const float* __restrict__ vv) {
    constexpr int WL_O = 10240;
    constexpr int AH_O = (PASSES >= 3) ? 20480 : 10240;
    constexpr int AL_O = 29184;
    constexpr int STG  = (PASSES >= 3) ? 37888 : 18944;

    extern __shared__ char smc[];
    const int tid = threadIdx.x, lane = tid & 31, warp = tid >> 5;
    const int b = blockIdx.z, om = blockIdx.x * 128, n0 = blockIdx.y * 128;
    const int wm = warp >> 1, wn = warp & 1;
    const int gq = lane >> 2, tq = lane & 3;
    const uint32_t smbase = smem_u32(smc);

    const __half* Abh = Ahg + (size_t)b * Kd * HWSZ + n0;
    const __half* Abl = (PASSES >= 3) ? (Alg + (size_t)b * Kd * HWSZ + n0) : nullptr;

    float acc[2][8][4];
    #pragma unroll
    for (int mt = 0; mt < 2; mt++)
        #pragma unroll
        for (int nt = 0; nt < 8; nt++)
            #pragma unroll
            for (int r = 0; r < 4; r++) acc[mt][nt][r] = 0.f;

    const uint32_t aoff = (uint32_t)(((lane & 15) * A_STR + wn * 64) * 2);

    uint4 wvh[2], wvl[2], avh[2], avl[2];
    const int nch = Kd >> 5;

    auto load_chunk = [&](int k0) {
        #pragma unroll
        for (int it = 0; it < 2; it++) {
            int e = tid + it * 256;
            int row = e >> 2, c4 = e & 3;
            wvh[it] = *(const uint4*)(Whg + (size_t)(om + row) * Kd + k0 + c4 * 8);
            if (PASSES >= 3)
                wvl[it] = *(const uint4*)(Wlg + (size_t)(om + row) * Kd + k0 + c4 * 8);
        }
        #pragma unroll
        for (int it = 0; it < 2; it++) {
            int e = tid + it * 256;
            int row = e >> 4, col8 = (e & 15) * 8;
            avh[it] = *(const uint4*)(Abh + (size_t)(k0 + row) * HWSZ + col8);
            if (PASSES >= 3)
                avl[it] = *(const uint4*)(Abl + (size_t)(k0 + row) * HWSZ + col8);
        }
    };
    auto store_chunk = [&](char* st) {
        #pragma unroll
        for (int it = 0; it < 2; it++) {
            int e = tid + it * 256;
            int row = e >> 2, c4 = e & 3;
            *(uint4*)(st + row * 80 + c4 * 16) = wvh[it];
            if (PASSES >= 3)
                *(uint4*)(st + WL_O + row * 80 + c4 * 16) = wvl[it];
        }
        #pragma unroll
        for (int it = 0; it < 2; it++) {
            int e = tid + it * 256;
            int row = e >> 4, col8 = (e & 15) * 8;
            *(uint4*)(st + AH_O + (row * A_STR + col8) * 2) = avh[it];
            if (PASSES >= 3)
                *(uint4*)(st + AL_O + (row * A_STR + col8) * 2) = avl[it];
        }
    };

    load_chunk(0);
    store_chunk(smc);
    __syncthreads();

    for (int ch = 0; ch < nch; ch++) {
        int s = ch & 1;
        char* st = smc + s * STG;
        uint32_t stu = smbase + (uint32_t)s * STG;

        if (ch + 1 < nch) load_chunk((ch + 1) << 5);

        const __half* ws_hi = (const __half*)st;
        const __half* ws_lo = (const __half*)(st + WL_O);

        #pragma unroll
        for (int ks = 0; ks < 2; ks++) {
            uint32_t afh[2][4], afl[2][4];
            #pragma unroll
            for (int mt = 0; mt < 2; mt++) {
                int rb = wm * 32 + mt * 16;
                int cb = ks * 16 + 2 * tq;
                afh[mt][0] = *(const uint32_t*)&ws_hi[(rb + gq)     * 40 + cb];
                afh[mt][1] = *(const uint32_t*)&ws_hi[(rb + gq + 8) * 40 + cb];
                afh[mt][2] = *(const uint32_t*)&ws_hi[(rb + gq)     * 40 + cb + 8];
                afh[mt][3] = *(const uint32_t*)&ws_hi[(rb + gq + 8) * 40 + cb + 8];
                if (PASSES >= 3) {
                    afl[mt][0] = *(const uint32_t*)&ws_lo[(rb + gq)     * 40 + cb];
                    afl[mt][1] = *(const uint32_t*)&ws_lo[(rb + gq + 8) * 40 + cb];
                    afl[mt][2] = *(const uint32_t*)&ws_lo[(rb + gq)     * 40 + cb + 8];
                    afl[mt][3] = *(const uint32_t*)&ws_lo[(rb + gq + 8) * 40 + cb + 8];
                }
            }
            uint32_t abase_h = stu + AH_O + aoff + (uint32_t)ks * (16 * A_STR * 2);
            uint32_t abase_l = stu + AL_O + aoff + (uint32_t)ks * (16 * A_STR * 2);
            #pragma unroll
            for (int nt = 0; nt < 8; nt++) {
                uint32_t bh0, bh1;
                ldsm_x2_t(bh0, bh1, abase_h + nt * 16);
                #pragma unroll
                for (int mt = 0; mt < 2; mt++) {
                    mma_f16(acc[mt][nt], afh[mt], bh0, bh1);
                    if (PASSES >= 3) mma_f16(acc[mt][nt], afl[mt], bh0, bh1);
                }
                if (PASSES >= 3) {
                    uint32_t bl0, bl1;
                    ldsm_x2_t(bl0, bl1, abase_l + nt * 16);
                    #pragma unroll
                    for (int mt = 0; mt < 2; mt++)
                        mma_f16(acc[mt][nt], afh[mt], bl0, bl1);
                }
            }
        }

        if (ch + 1 < nch) store_chunk(smc + (s ^ 1) * STG);
        __syncthreads();
    }

    // ---- epilogue ----
    #pragma unroll
    for (int mt = 0; mt < 2; mt++) {
        int o0 = om + wm * 32 + mt * 16 + gq;
        int o1 = o0 + 8;
        float s0 = 0.f, bs0 = 0.f, s1 = 0.f, bs1 = 0.f, bi0 = 0.f, bi1 = 0.f;
        if (MODE == 2 || MODE == 3) {
            s0 = g[o0] * rsqrtf(vv[o0] + EPSV); bs0 = bb[o0] - mm[o0] * s0;
            s1 = g[o1] * rsqrtf(vv[o1] + EPSV); bs1 = bb[o1] - mm[o1] * s1;
        }
        if (MODE == 1) { bi0 = bias[o0]; bi1 = bias[o1]; }
        #pragma unroll
        for (int nt = 0; nt < 8; nt++) {
            int n = n0 + wn * 64 + nt * 8 + 2 * tq;
            size_t oi0 = ((size_t)b * O + o0) * HWSZ + n;
            size_t oi1 = ((size_t)b * O + o1) * HWSZ + n;
            float r0 = acc[mt][nt][0], r1 = acc[mt][nt][1];
            float r2 = acc[mt][nt][2], r3 = acc[mt][nt][3];
            if (MODE == 1) {
                float2 e0 = *(const float2*)&Res[oi0];
                float2 e1 = *(const float2*)&Res[oi1];
                r0 += e0.x + bi0; r1 += e0.y + bi0;
                r2 += e1.x + bi1; r3 += e1.y + bi1;
            }
            if (MODE == 2) {
                r0 = gelu_f(r0 * s0 + bs0); r1 = gelu_f(r1 * s0 + bs0);
                r2 = gelu_f(r2 * s1 + bs1); r3 = gelu_f(r3 * s1 + bs1);
            }
            if (MODE == 3) {
                float2 e0 = *(const float2*)&Res[oi0];
                float2 e1 = *(const float2*)&Res[oi1];
                r0 = e0.x + r0 * s0 + bs0; r1 = e0.y + r1 * s0 + bs0;
                r2 = e1.x + r2 * s1 + bs1; r3 = e1.y + r3 * s1 + bs1;
            }
            if (WF32) {
                float2 v0 = {r0, r1}, v1 = {r2, r3};
                *(float2*)&Out[oi0] = v0;
                *(float2*)&Out[oi1] = v1;
            }
            if (WF16) {
                __half2 hv0 = __floats2half2_rn(r0, r1);
                __half2 hv1 = __floats2half2_rn(r2, r3);
                *(__half2*)&Outh[oi0] = hv0;
                *(__half2*)&Outh[oi1] = hv1;
            }
        }
    }
}

// ---------------- window means: block per (b,h,d) ----------------
__global__ void wmean_k() {
    int bid = blockIdx.x;             // b*256 + h*32 + d
    int d = bid & 31, h = (bid >> 5) & 7, b = bid >> 8;
    int tid = threadIdx.x;
    __shared__ float spq[256], spk[256];
    const float* qpl = g_qkv + ((size_t)b * 3 * CC + h * DH + d) * HWSZ;
    const float* kpl = qpl + (size_t)CC * HWSZ;
    float4 vq = ((const float4*)qpl)[tid];
    float4 vk = ((const float4*)kpl)[tid];
    spq[tid] = vq.x + vq.y + vq.z + vq.w;
    spk[tid] = vk.x + vk.y + vk.z + vk.w;
    __syncthreads();
    if (tid < 64) {
        int wy = tid >> 3, wx = tid & 7;
        int base = wy * 32 + wx;
        float sq = spq[base] + spq[base + 8] + spq[base + 16] + spq[base + 24];
        float sk = spk[base] + spk[base + 8] + spk[base + 16] + spk[base + 24];
        size_t o = ((size_t)(b * 8 + h) * 64 + tid) * DH + d;
        g_qm[o] = sq * 0.0625f;
        g_km[o] = sk * 0.0625f;
    }
}

// ---------------- affinity + exact top-4 ----------------
__global__ void topk_k() {
    int bh = blockIdx.x;
    __shared__ float kt[32][65];
    __shared__ float qs[64][32];
    int tid = threadIdx.x, warp = tid >> 5, lane = tid & 31;
    for (int e = tid; e < 2048; e += 256) {
        int j = e >> 5, d = e & 31;
        kt[d][j] = g_km[(size_t)bh * 2048 + e];
        qs[j][d] = g_qm[(size_t)bh * 2048 + e];
    }
    __syncthreads();
    for (int ii = 0; ii < 8; ii++) {
        int i = warp * 8 + ii;
        float s0 = 0.f, s1 = 0.f;
        #pragma unroll
        for (int d = 0; d < 32; d++) {
            float q = qs[i][d];
            s0 += q * kt[d][lane];
            s1 += q * kt[d][lane + 32];
        }
        float v0 = s0, v1 = s1;
        #pragma unroll
        for (int t = 0; t < KTOP; t++) {
            float bvv; int bj;
            if (v0 >= v1) { bvv = v0; bj = lane; } else { bvv = v1; bj = lane + 32; }
            #pragma unroll
            for (int off = 16; off; off >>= 1) {
                float ov = __shfl_xor_sync(0xffffffffu, bvv, off);
                int   oj = __shfl_xor_sync(0xffffffffu, bj,  off);
                if (ov > bvv || (ov == bvv && oj < bj)) { bvv = ov; bj = oj; }
            }
            if (lane == 0) g_idx[((size_t)bh * 64 + i) * KTOP + t] = bj;
            if (bj == lane)      v0 = -INFINITY;
            if (bj == lane + 32) v1 = -INFINITY;
        }
    }
}

// ---------------- gathered window attention (HMMA, 3-pass) ----------------
#define QK_STR 40
#define V_STR  72
#define SS_STR 68
#define P_STR  72
__global__ void __launch_bounds__(128) attn_k() {
    int bid = blockIdx.x;
    int n = bid & 63;
    int h = (bid >> 6) & 7;
    int b = bid >> 9;
    __shared__ __half qh[16 * QK_STR], ql[16 * QK_STR];
    __shared__ __half kh[64 * QK_STR], kl[64 * QK_STR];
    __shared__ __half vh[32 * V_STR],  vl[32 * V_STR];
    __shared__ float  ss[16 * SS_STR];
    __shared__ __half ph[16 * P_STR], pl[16 * P_STR];
    __shared__ int    widx[KTOP];
    int tid = threadIdx.x;
    if (tid < KTOP) widx[tid] = g_idx[(size_t)bid * KTOP + tid];
    __syncthreads();

    int wy = n >> 3, wx = n & 7;
    const float* qbase = g_qkv + ((size_t)b * 3 * CC + h * DH) * HWSZ;
    const float* kbase = qbase + (size_t)CC * HWSZ;
    const float* vbase = qbase + (size_t)2 * CC * HWSZ;

    for (int e = tid; e < 512; e += 128) {
        int d = e >> 4, t = e & 15;
        int hw = ((wy * 4 + (t >> 2)) << 5) + wx * 4 + (t & 3);
        __half hv, lv; cvt_split(qbase[(size_t)d * HWSZ + hw], hv, lv);
        qh[t * QK_STR + d] = hv; ql[t * QK_STR + d] = lv;
    }
    for (int e = tid; e < 2048; e += 128) {
        int d = e >> 6, kt = e & 63;
        int j = widx[kt >> 4];
        int t = kt & 15;
        int hw = (((j >> 3) * 4 + (t >> 2)) << 5) + (j & 7) * 4 + (t & 3);
        __half hv, lv; cvt_split(kbase[(size_t)d * HWSZ + hw], hv, lv);
        kh[kt * QK_STR + d] = hv; kl[kt * QK_STR + d] = lv;
    }
    for (int e = tid; e < 2048; e += 128) {
        int d = e >> 6, kt = e & 63;
        int j = widx[kt >> 4];
        int t = kt & 15;
        int hw = (((j >> 3) * 4 + (t >> 2)) << 5) + (j & 7) * 4 + (t & 3);
        __half hv, lv; cvt_split(vbase[(size_t)d * HWSZ + hw], hv, lv);
        vh[d * V_STR + kt] = hv; vl[d * V_STR + kt] = lv;
    }
    __syncthreads();

    int warp = tid >> 5, lane = tid & 31;
    int gq = lane >> 2, tq = lane & 3;
    const float scale = 0.17677669529663687f;

    {
        float sc0[4] = {0.f, 0.f, 0.f, 0.f};
        float sc1[4] = {0.f, 0.f, 0.f, 0.f};
        #pragma unroll
        for (int ks = 0; ks < 2; ks++) {
            int cb = ks * 16 + 2 * tq;
            uint32_t ah[4], al[4];
            ah[0] = *(const uint32_t*)&qh[gq * QK_STR + cb];
            ah[1] = *(const uint32_t*)&qh[(gq + 8) * QK_STR + cb];
            ah[2] = *(const uint32_t*)&qh[gq * QK_STR + cb + 8];
            ah[3] = *(const uint32_t*)&qh[(gq + 8) * QK_STR + cb + 8];
            al[0] = *(const uint32_t*)&ql[gq * QK_STR + cb];
            al[1] = *(const uint32_t*)&ql[(gq + 8) * QK_STR + cb];
            al[2] = *(const uint32_t*)&ql[gq * QK_STR + cb + 8];
            al[3] = *(const uint32_t*)&ql[(gq + 8) * QK_STR + cb + 8];
            #pragma unroll
            for (int nt = 0; nt < 2; nt++) {
                int key = warp * 16 + nt * 8 + gq;
                uint32_t bh0 = *(const uint32_t*)&kh[key * QK_STR + cb];
                uint32_t bh1 = *(const uint32_t*)&kh[key * QK_STR + cb + 8];
                uint32_t bl0 = *(const uint32_t*)&kl[key * QK_STR + cb];
                uint32_t bl1 = *(const uint32_t*)&kl[key * QK_STR + cb + 8];
                float* sc = nt ? sc1 : sc0;
                mma_f16(sc, ah, bh0, bh1);
                mma_f16(sc, ah, bl0, bl1);
                mma_f16(sc, al, bh0, bh1);
            }
        }
        #pragma unroll
        for (int nt = 0; nt < 2; nt++) {
            const float* sc = nt ? sc1 : sc0;
            int c0 = warp * 16 + nt * 8 + 2 * tq;
            ss[gq * SS_STR + c0]           = sc[0] * scale;
            ss[gq * SS_STR + c0 + 1]       = sc[1] * scale;
            ss[(gq + 8) * SS_STR + c0]     = sc[2] * scale;
            ss[(gq + 8) * SS_STR + c0 + 1] = sc[3] * scale;
        }
    }
    __syncthreads();

    #pragma unroll
    for (int rr = 0; rr < 4; rr++) {
        int row = warp * 4 + rr;
        float s0 = ss[row * SS_STR + lane];
        float s1 = ss[row * SS_STR + lane + 32];
        float mx = fmaxf(s0, s1);
        #pragma unroll
        for (int off = 16; off; off >>= 1) mx = fmaxf(mx, __shfl_xor_sync(0xffffffffu, mx, off));
        float e0 = expf(s0 - mx), e1 = expf(s1 - mx);
        float sum = e0 + e1;
        #pragma unroll
        for (int off = 16; off; off >>= 1) sum += __shfl_xor_sync(0xffffffffu, sum, off);
        float inv = 1.0f / sum;
        __half hv, lv;
        cvt_split(e0 * inv, hv, lv);
        ph[row * P_STR + lane] = hv; pl[row * P_STR + lane] = lv;
        cvt_split(e1 * inv, hv, lv);
        ph[row * P_STR + lane + 32] = hv; pl[row * P_STR + lane + 32] = lv;
    }
    __syncthreads();

    {
        float f[4] = {0.f, 0.f, 0.f, 0.f};
        #pragma unroll
        for (int ks = 0; ks < 4; ks++) {
            int cb = ks * 16 + 2 * tq;
            uint32_t ah[4], al[4];
            ah[0] = *(const uint32_t*)&ph[gq * P_STR + cb];
            ah[1] = *(const uint32_t*)&ph[(gq + 8) * P_STR + cb];
            ah[2] = *(const uint32_t*)&ph[gq * P_STR + cb + 8];
            ah[3] = *(const uint32_t*)&ph[(gq + 8) * P_STR + cb + 8];
            al[0] = *(const uint32_t*)&pl[gq * P_STR + cb];
            al[1] = *(const uint32_t*)&pl[(gq + 8) * P_STR + cb];
            al[2] = *(const uint32_t*)&pl[gq * P_STR + cb + 8];
            al[3] = *(const uint32_t*)&pl[(gq + 8) * P_STR + cb + 8];
            int d = warp * 8 + gq;
            uint32_t bh0 = *(const uint32_t*)&vh[d * V_STR + cb];
            uint32_t bh1 = *(const uint32_t*)&vh[d * V_STR + cb + 8];
            uint32_t bl0 = *(const uint32_t*)&vl[d * V_STR + cb];
            uint32_t bl1 = *(const uint32_t*)&vl[d * V_STR + cb + 8];
            mma_f16(f, ah, bh0, bh1);
            mma_f16(f, ah, bl0, bl1);
            mma_f16(f, al, bh0, bh1);
        }
        __half* mbase = g_msgh + ((size_t)b * CC + h * DH) * HWSZ;
        int d0 = warp * 8 + 2 * tq;
        int hwA = ((wy * 4 + (gq >> 2)) << 5) + wx * 4 + (gq & 3);
        int hwB = ((wy * 4 + ((gq + 8) >> 2)) << 5) + wx * 4 + ((gq + 8) & 3);
        mbase[(size_t)d0 * HWSZ + hwA]       = __float2half_rn(f[0]);
        mbase[(size_t)(d0 + 1) * HWSZ + hwA] = __float2half_rn(f[1]);
        mbase[(size_t)d0 * HWSZ + hwB]       = __float2half_rn(f[2]);
        mbase[(size_t)(d0 + 1) * HWSZ + hwB] = __float2half_rn(f[3]);
    }
}

// ---------------- depthwise 3x3 + bn2 + gelu (fp16 in/out) ----------------
__global__ void dw_k(const float* __restrict__ dw,
                     const float* __restrict__ g2, const float* __restrict__ b2,
                     const float* __restrict__ m2, const float* __restrict__ v2) {
    int bc = blockIdx.x;
    int c = bc & (MRC - 1);
    __shared__ float t[1024];
    __shared__ float wsh[9];
    int tid = threadIdx.x;
    const __half* p = g_h1h + (size_t)bc * HWSZ;
    {
        uint2 u = ((const uint2*)p)[tid];
        __half2 a = *(__half2*)&u.x, b2h = *(__half2*)&u.y;
        float4 f;
        f.x = __low2float(a);  f.y = __high2float(a);
        f.z = __low2float(b2h); f.w = __high2float(b2h);
        ((float4*)t)[tid] = f;
    }
    if (tid < 9) wsh[tid] = dw[c * 9 + tid];
    __syncthreads();
    float s = g2[c] * rsqrtf(v2[c] + EPSV);
    float bs = b2[c] - m2[c] * s;
    __half* outp = g_h2h + (size_t)bc * HWSZ;
    int y = tid >> 3, x0 = (tid & 7) * 4;
    float rp[4];
    #pragma unroll
    for (int j = 0; j < 4; j++) {
        int x = x0 + j;
        float acc = 0.f;
        #pragma unroll
        for (int dy = -1; dy <= 1; dy++) {
            int yy = y + dy;
            if (yy < 0 || yy > 31) continue;
            #pragma unroll
            for (int dx = -1; dx <= 1; dx++) {
                int xx = x + dx;
                if (xx < 0 || xx > 31) continue;
                acc += wsh[(dy + 1) * 3 + (dx + 1)] * t[yy * 32 + xx];
            }
        }
        rp[j] = gelu_f(acc * s + bs);
    }
    __half2 o0 = __floats2half2_rn(rp[0], rp[1]);
    __half2 o1 = __floats2half2_rn(rp[2], rp[3]);
    uint2 u; u.x = *(uint32_t*)&o0; u.y = *(uint32_t*)&o1;
    ((uint2*)outp)[tid] = u;
}

// ---------------- launcher ----------------
extern "C" void kernel_launch(void* const* d_in, const int* in_sizes, int n_in,
                              void* d_out, int out_size) {
    const float* x      = (const float*)d_in[0];
    const float* bn0_g  = (const float*)d_in[1];
    const float* bn0_b  = (const float*)d_in[2];
    const float* bn0_m  = (const float*)d_in[3];
    const float* bn0_v  = (const float*)d_in[4];
    const float* w_qkv  = (const float*)d_in[5];
    const float* w_mrg  = (const float*)d_in[6];
    const float* b_mrg  = (const float*)d_in[7];
    const float* w1     = (const float*)d_in[8];
    const float* bn1_g  = (const float*)d_in[9];
    const float* bn1_b  = (const float*)d_in[10];
    const float* bn1_m  = (const float*)d_in[11];
    const float* bn1_v  = (const float*)d_in[12];
    const float* dw     = (const float*)d_in[13];
    const float* bn2_g  = (const float*)d_in[14];
    const float* bn2_b  = (const float*)d_in[15];
    const float* bn2_m  = (const float*)d_in[16];
    const float* bn2_v  = (const float*)d_in[17];
    const float* w2     = (const float*)d_in[18];
    const float* bn3_g  = (const float*)d_in[19];
    const float* bn3_b  = (const float*)d_in[20];
    const float* bn3_m  = (const float*)d_in[21];
    const float* bn3_v  = (const float*)d_in[22];

    float *qkv, *x1;
    __half *wh, *wl, *h0h, *h0l, *msgh, *x1h, *h1h, *h2h;
    cudaGetSymbolAddress((void**)&qkv,  g_qkv);
    cudaGetSymbolAddress((void**)&x1,   g_x1);
    cudaGetSymbolAddress((void**)&wh,   g_wh);
    cudaGetSymbolAddress((void**)&wl,   g_wl);
    cudaGetSymbolAddress((void**)&h0h,  g_h0h);
    cudaGetSymbolAddress((void**)&h0l,  g_h0l);
    cudaGetSymbolAddress((void**)&msgh, g_msgh);
    cudaGetSymbolAddress((void**)&x1h,  g_x1h);
    cudaGetSymbolAddress((void**)&h1h,  g_h1h);
    cudaGetSymbolAddress((void**)&h2h,  g_h2h);

    cudaFuncSetAttribute((const void*)mgemm_k<0,3,1,0>, cudaFuncAttributeMaxDynamicSharedMemorySize, 75776);
    cudaFuncSetAttribute((const void*)mgemm_k<1,1,1,1>, cudaFuncAttributeMaxDynamicSharedMemorySize, 37888);
    cudaFuncSetAttribute((const void*)mgemm_k<2,1,0,1>, cudaFuncAttributeMaxDynamicSharedMemorySize, 37888);
    cudaFuncSetAttribute((const void*)mgemm_k<3,1,1,0>, cudaFuncAttributeMaxDynamicSharedMemorySize, 37888);

    // 0. pre-split weights to fp16
    wsplit_k<<<(WTOT + 255) / 256, 256>>>(w_qkv, w_mrg, w1, w2);

    // 1. h0 = gelu(bn0(x)) -> fp16 hi/lo
    bn0_gelu_k<<<(BB * CC * HWSZ / 4 + 255) / 256, 256>>>(x, bn0_g, bn0_b, bn0_m, bn0_v);

    // 2. qkv = w_qkv @ h0   (3-pass, fp16-resident operands)
    mgemm_k<0,3,1,0><<<dim3(768 / 128, 8, BB), 256, 75776>>>(
        wh + WOFF_QKV, wl, h0h, h0l, qkv, nullptr, 768, 256,
        nullptr, nullptr, nullptr, nullptr, nullptr, nullptr);

    // 3. window means (block per (b,h,d))
    wmean_k<<<BB * HEADS * DH, 256>>>();

    // 4. affinity + top-4
    topk_k<<<BB * HEADS, 256>>>();

    // 5. gathered attention (HMMA) -> msg fp16
    attn_k<<<BB * HEADS * NWIN, 128>>>();

    // 6. x1 = x + w_merge @ msg + b_merge   (fp32 + fp16 outputs)
    mgemm_k<1,1,1,1><<<dim3(CC / 128, 8, BB), 256, 37888>>>(
        wh + WOFF_MRG, nullptr, msgh, nullptr, x1, x1h, CC, 256,
        x, b_mrg, nullptr, nullptr, nullptr, nullptr);

    // 7. h1 = gelu(bn1(w1 @ x1))  -> fp16 only
    mgemm_k<2,1,0,1><<<dim3(MRC / 128, 8, BB), 256, 37888>>>(
        wh + WOFF_W1, nullptr, x1h, nullptr, nullptr, h1h, MRC, 256,
        nullptr, nullptr, bn1_g, bn1_b, bn1_m, bn1_v);

    // 8. h2 = gelu(bn2(dwconv3x3(h1))) -> fp16
    dw_k<<<BB * MRC, 256>>>(dw, bn2_g, bn2_b, bn2_m, bn2_v);

    // 9. out = x1 + bn3(w2 @ h2)
    mgemm_k<3,1,1,0><<<dim3(CC / 128, 8, BB), 256, 37888>>>(
        wh + WOFF_W2, nullptr, h2h, nullptr, (float*)d_out, nullptr, CC, 1024,
        x1, nullptr, bn3_g, bn3_b, bn3_m, bn3_v);
}

// round 9
// speedup vs baseline: 1.6523x; 1.1452x over previous
#include <cuda_runtime.h>
#include <cuda_fp16.h>
#include <cstdint>
#include <math.h>

// ---------------- problem constants ----------------
#define BB   16
#define CC   256
#define HWSZ 1024
#define DH   32
#define HEADS 8
#define KTOP 4
#define MRC  1024
#define NWIN 64
#define EPSV 1e-5f

// pre-split weight offsets (halves)
#define WOFF_QKV 0
#define WOFF_MRG 196608
#define WOFF_W1  262144
#define WOFF_W2  524288
#define WTOT     786432

// ---------------- device scratch ----------------
__device__ float  g_qkv [BB * 3*CC * HWSZ];
__device__ float  g_qm  [BB * HEADS * NWIN * DH];
__device__ float  g_km  [BB * HEADS * NWIN * DH];
__device__ int    g_idx [BB * HEADS * NWIN * KTOP];
__device__ float  g_x1  [BB * CC  * HWSZ];
__device__ __half g_h0h [BB * CC  * HWSZ];
__device__ __half g_msgh[BB * CC  * HWSZ];
__device__ __half g_x1h [BB * CC  * HWSZ];
__device__ __half g_h1h [BB * MRC * HWSZ];
__device__ __half g_h2h [BB * MRC * HWSZ];
__device__ __half g_wh  [WTOT];
__device__ __half g_wl  [196608];   // lo only for qkv

__device__ __forceinline__ float gelu_f(float x) {
    return 0.5f * x * (1.0f + erff(x * 0.7071067811865475f));
}

// ---------------- fp16 warp MMA + ldmatrix ----------------
__device__ __forceinline__ void mma_f16(float* d, const uint32_t* a, uint32_t b0, uint32_t b1) {
    asm volatile(
        "mma.sync.aligned.m16n8k16.row.col.f32.f16.f16.f32 "
        "{%0,%1,%2,%3}, {%4,%5,%6,%7}, {%8,%9}, {%0,%1,%2,%3};"
        : "+f"(d[0]), "+f"(d[1]), "+f"(d[2]), "+f"(d[3])
        : "r"(a[0]), "r"(a[1]), "r"(a[2]), "r"(a[3]), "r"(b0), "r"(b1));
}
__device__ __forceinline__ void ldsm_x2_t(uint32_t& r0, uint32_t& r1, uint32_t addr) {
    asm volatile("ldmatrix.sync.aligned.m8n8.x2.trans.shared.b16 {%0,%1}, [%2];"
                 : "=r"(r0), "=r"(r1) : "r"(addr));
}
__device__ __forceinline__ uint32_t smem_u32(const void* p) {
    uint32_t a;
    asm("{ .reg .u64 t; cvta.to.shared.u64 t, %1; cvt.u32.u64 %0, t; }" : "=r"(a) : "l"(p));
    return a;
}
__device__ __forceinline__ void cvt_split(float x, __half& h, __half& l) {
    h = __float2half_rn(x);
    l = __float2half_rn(x - __half2float(h));
}

#define A_STR 136

// ---------------- weight pre-split ----------------
__global__ void wsplit_k(const float* __restrict__ wqkv, const float* __restrict__ wmrg,
                         const float* __restrict__ w1,   const float* __restrict__ w2) {
    int i = blockIdx.x * 256 + threadIdx.x;
    if (i >= WTOT) return;
    if (i < WOFF_MRG) {
        __half h, l; cvt_split(wqkv[i], h, l);
        g_wh[i] = h; g_wl[i] = l;
    } else if (i < WOFF_W1) {
        g_wh[i] = __float2half_rn(wmrg[i - WOFF_MRG]);
    } else if (i < WOFF_W2) {
        g_wh[i] = __float2half_rn(w1[i - WOFF_W1]);
    } else {
        g_wh[i] = __float2half_rn(w2[i - WOFF_W2]);
    }
}

// ---------------- h0 = gelu(bn0(x)) -> fp16 hi plane ----------------
__global__ void bn0_gelu_k(const float* __restrict__ x,
                           const float* __restrict__ g, const float* __restrict__ b,
                           const float* __restrict__ m, const float* __restrict__ v) {
    int i = blockIdx.x * 256 + threadIdx.x;
    if (i >= BB * CC * HWSZ / 4) return;
    int c = (i >> 8) & (CC - 1);
    float s = g[c] * rsqrtf(v[c] + EPSV);
    float sh = b[c] - m[c] * s;
    float4 xv = ((const float4*)x)[i];
    __half2 h0 = __floats2half2_rn(gelu_f(xv.x * s + sh), gelu_f(xv.y * s + sh));
    __half2 h1 = __floats2half2_rn(gelu_f(xv.z * s + sh), gelu_f(xv.w * s + sh));
    uint2 u; u.x = *(uint32_t*)&h0; u.y = *(uint32_t*)&h1;
    ((uint2*)g_h0h)[i] = u;
}

// ---------------- tensor-core fused GEMM (fp16-resident A) ----------------
// PASSES: 1 = hiW*hiA; 2 = + loW*hiA (W exact, A rounded)
template<int MODE, int PASSES, int WF32, int WF16>
__global__ void __launch_bounds__(256, 2)
mgemm_k(const __half* __restrict__ Whg, const __half* __restrict__ Wlg,
        const __half* __restrict__ Ahg,
        float* __restrict__ Out, __half* __restrict__ Outh, int O, int Kd,
        const float* __restrict__ Res, const float* __restrict__ bias,
        const float* __restrict__ g,  const float* __restrict__ bb,
        const float* __restrict__ mm, const float* __restrict__ vv) {
    constexpr int WL_O = 10240;
    constexpr int AH_O = (PASSES >= 2) ? 20480 : 10240;
    constexpr int STG  = AH_O + 8704;

    extern __shared__ char smc[];
    const int tid = threadIdx.x, lane = tid & 31, warp = tid >> 5;
    const int b = blockIdx.z, om = blockIdx.x * 128, n0 = blockIdx.y * 128;
    const int wm = warp >> 1, wn = warp & 1;
    const int gq = lane >> 2, tq = lane & 3;
    const uint32_t smbase = smem_u32(smc);

    const __half* Abh = Ahg + (size_t)b * Kd * HWSZ + n0;

    float acc[2][8][4];
    #pragma unroll
    for (int mt = 0; mt < 2; mt++)
        #pragma unroll
        for (int nt = 0; nt < 8; nt++)
            #pragma unroll
            for (int r = 0; r < 4; r++) acc[mt][nt][r] = 0.f;

    const uint32_t aoff = (uint32_t)(((lane & 15) * A_STR + wn * 64) * 2);

    uint4 wvh[2], wvl[2], avh[2];
    const int nch = Kd >> 5;

    auto load_chunk = [&](int k0) {
        #pragma unroll
        for (int it = 0; it < 2; it++) {
            int e = tid + it * 256;
            int row = e >> 2, c4 = e & 3;
            wvh[it] = *(const uint4*)(Whg + (size_t)(om + row) * Kd + k0 + c4 * 8);
            if (PASSES >= 2)
                wvl[it] = *(const uint4*)(Wlg + (size_t)(om + row) * Kd + k0 + c4 * 8);
        }
        #pragma unroll
        for (int it = 0; it < 2; it++) {
            int e = tid + it * 256;
            int row = e >> 4, col8 = (e & 15) * 8;
            avh[it] = *(const uint4*)(Abh + (size_t)(k0 + row) * HWSZ + col8);
        }
    };
    auto store_chunk = [&](char* st) {
        #pragma unroll
        for (int it = 0; it < 2; it++) {
            int e = tid + it * 256;
            int row = e >> 2, c4 = e & 3;
            *(uint4*)(st + row * 80 + c4 * 16) = wvh[it];
            if (PASSES >= 2)
                *(uint4*)(st + WL_O + row * 80 + c4 * 16) = wvl[it];
        }
        #pragma unroll
        for (int it = 0; it < 2; it++) {
            int e = tid + it * 256;
            int row = e >> 4, col8 = (e & 15) * 8;
            *(uint4*)(st + AH_O + (row * A_STR + col8) * 2) = avh[it];
        }
    };

    load_chunk(0);
    store_chunk(smc);
    __syncthreads();

    for (int ch = 0; ch < nch; ch++) {
        int s = ch & 1;
        char* st = smc + s * STG;
        uint32_t stu = smbase + (uint32_t)s * STG;

        if (ch + 1 < nch) load_chunk((ch + 1) << 5);

        const __half* ws_hi = (const __half*)st;
        const __half* ws_lo = (const __half*)(st + WL_O);

        #pragma unroll
        for (int ks = 0; ks < 2; ks++) {
            uint32_t afh[2][4], afl[2][4];
            #pragma unroll
            for (int mt = 0; mt < 2; mt++) {
                int rb = wm * 32 + mt * 16;
                int cb = ks * 16 + 2 * tq;
                afh[mt][0] = *(const uint32_t*)&ws_hi[(rb + gq)     * 40 + cb];
                afh[mt][1] = *(const uint32_t*)&ws_hi[(rb + gq + 8) * 40 + cb];
                afh[mt][2] = *(const uint32_t*)&ws_hi[(rb + gq)     * 40 + cb + 8];
                afh[mt][3] = *(const uint32_t*)&ws_hi[(rb + gq + 8) * 40 + cb + 8];
                if (PASSES >= 2) {
                    afl[mt][0] = *(const uint32_t*)&ws_lo[(rb + gq)     * 40 + cb];
                    afl[mt][1] = *(const uint32_t*)&ws_lo[(rb + gq + 8) * 40 + cb];
                    afl[mt][2] = *(const uint32_t*)&ws_lo[(rb + gq)     * 40 + cb + 8];
                    afl[mt][3] = *(const uint32_t*)&ws_lo[(rb + gq + 8) * 40 + cb + 8];
                }
            }
            uint32_t abase_h = stu + AH_O + aoff + (uint32_t)ks * (16 * A_STR * 2);
            #pragma unroll
            for (int nt = 0; nt < 8; nt++) {
                uint32_t bh0, bh1;
                ldsm_x2_t(bh0, bh1, abase_h + nt * 16);
                #pragma unroll
                for (int mt = 0; mt < 2; mt++) {
                    mma_f16(acc[mt][nt], afh[mt], bh0, bh1);
                    if (PASSES >= 2) mma_f16(acc[mt][nt], afl[mt], bh0, bh1);
                }
            }
        }

        if (ch + 1 < nch) store_chunk(smc + (s ^ 1) * STG);
        __syncthreads();
    }

    // ---- epilogue ----
    #pragma unroll
    for (int mt = 0; mt < 2; mt++) {
        int o0 = om + wm * 32 + mt * 16 + gq;
        int o1 = o0 + 8;
        float s0 = 0.f, bs0 = 0.f, s1 = 0.f, bs1 = 0.f, bi0 = 0.f, bi1 = 0.f;
        if (MODE == 2 || MODE == 3) {
            s0 = g[o0] * rsqrtf(vv[o0] + EPSV); bs0 = bb[o0] - mm[o0] * s0;
            s1 = g[o1] * rsqrtf(vv[o1] + EPSV); bs1 = bb[o1] - mm[o1] * s1;
        }
        if (MODE == 1) { bi0 = bias[o0]; bi1 = bias[o1]; }
        #pragma unroll
        for (int nt = 0; nt < 8; nt++) {
            int n = n0 + wn * 64 + nt * 8 + 2 * tq;
            size_t oi0 = ((size_t)b * O + o0) * HWSZ + n;
            size_t oi1 = ((size_t)b * O + o1) * HWSZ + n;
            float r0 = acc[mt][nt][0], r1 = acc[mt][nt][1];
            float r2 = acc[mt][nt][2], r3 = acc[mt][nt][3];
            if (MODE == 1) {
                float2 e0 = *(const float2*)&Res[oi0];
                float2 e1 = *(const float2*)&Res[oi1];
                r0 += e0.x + bi0; r1 += e0.y + bi0;
                r2 += e1.x + bi1; r3 += e1.y + bi1;
            }
            if (MODE == 2) {
                r0 = gelu_f(r0 * s0 + bs0); r1 = gelu_f(r1 * s0 + bs0);
                r2 = gelu_f(r2 * s1 + bs1); r3 = gelu_f(r3 * s1 + bs1);
            }
            if (MODE == 3) {
                float2 e0 = *(const float2*)&Res[oi0];
                float2 e1 = *(const float2*)&Res[oi1];
                r0 = e0.x + r0 * s0 + bs0; r1 = e0.y + r1 * s0 + bs0;
                r2 = e1.x + r2 * s1 + bs1; r3 = e1.y + r3 * s1 + bs1;
            }
            if (WF32) {
                float2 v0 = {r0, r1}, v1 = {r2, r3};
                *(float2*)&Out[oi0] = v0;
                *(float2*)&Out[oi1] = v1;
            }
            if (WF16) {
                __half2 hv0 = __floats2half2_rn(r0, r1);
                __half2 hv1 = __floats2half2_rn(r2, r3);
                *(__half2*)&Outh[oi0] = hv0;
                *(__half2*)&Outh[oi1] = hv1;
            }
        }
    }
}

// ---------------- window means: block per (b,h,d) ----------------
__global__ void wmean_k() {
    int bid = blockIdx.x;             // b*256 + h*32 + d
    int d = bid & 31, h = (bid >> 5) & 7, b = bid >> 8;
    int tid = threadIdx.x;
    __shared__ float spq[256], spk[256];
    const float* qpl = g_qkv + ((size_t)b * 3 * CC + h * DH + d) * HWSZ;
    const float* kpl = qpl + (size_t)CC * HWSZ;
    float4 vq = ((const float4*)qpl)[tid];
    float4 vk = ((const float4*)kpl)[tid];
    spq[tid] = vq.x + vq.y + vq.z + vq.w;
    spk[tid] = vk.x + vk.y + vk.z + vk.w;
    __syncthreads();
    if (tid < 64) {
        int wy = tid >> 3, wx = tid & 7;
        int base = wy * 32 + wx;
        float sq = spq[base] + spq[base + 8] + spq[base + 16] + spq[base + 24];
        float sk = spk[base] + spk[base + 8] + spk[base + 16] + spk[base + 24];
        size_t o = ((size_t)(b * 8 + h) * 64 + tid) * DH + d;
        g_qm[o] = sq * 0.0625f;
        g_km[o] = sk * 0.0625f;
    }
}

// ---------------- affinity + exact top-4 ----------------
__global__ void topk_k() {
    int bh = blockIdx.x;
    __shared__ float kt[32][65];
    __shared__ float qs[64][32];
    int tid = threadIdx.x, warp = tid >> 5, lane = tid & 31;
    for (int e = tid; e < 2048; e += 256) {
        int j = e >> 5, d = e & 31;
        kt[d][j] = g_km[(size_t)bh * 2048 + e];
        qs[j][d] = g_qm[(size_t)bh * 2048 + e];
    }
    __syncthreads();
    for (int ii = 0; ii < 8; ii++) {
        int i = warp * 8 + ii;
        float s0 = 0.f, s1 = 0.f;
        #pragma unroll
        for (int d = 0; d < 32; d++) {
            float q = qs[i][d];
            s0 += q * kt[d][lane];
            s1 += q * kt[d][lane + 32];
        }
        float v0 = s0, v1 = s1;
        #pragma unroll
        for (int t = 0; t < KTOP; t++) {
            float bvv; int bj;
            if (v0 >= v1) { bvv = v0; bj = lane; } else { bvv = v1; bj = lane + 32; }
            #pragma unroll
            for (int off = 16; off; off >>= 1) {
                float ov = __shfl_xor_sync(0xffffffffu, bvv, off);
                int   oj = __shfl_xor_sync(0xffffffffu, bj,  off);
                if (ov > bvv || (ov == bvv && oj < bj)) { bvv = ov; bj = oj; }
            }
            if (lane == 0) g_idx[((size_t)bh * 64 + i) * KTOP + t] = bj;
            if (bj == lane)      v0 = -INFINITY;
            if (bj == lane + 32) v1 = -INFINITY;
        }
    }
}

// ---------------- gathered window attention (HMMA, 1-pass fp16) ----------------
#define QK_STR 40
#define V_STR  72
#define SS_STR 68
#define P_STR  72
__global__ void __launch_bounds__(128) attn_k() {
    int bid = blockIdx.x;
    int n = bid & 63;
    int h = (bid >> 6) & 7;
    int b = bid >> 9;
    __shared__ __half qh[16 * QK_STR];
    __shared__ __half kh[64 * QK_STR];
    __shared__ __half vh[32 * V_STR];
    __shared__ float  ss[16 * SS_STR];
    __shared__ __half ph[16 * P_STR];
    __shared__ int    widx[KTOP];
    int tid = threadIdx.x;
    if (tid < KTOP) widx[tid] = g_idx[(size_t)bid * KTOP + tid];
    __syncthreads();

    int wy = n >> 3, wx = n & 7;
    const float* qbase = g_qkv + ((size_t)b * 3 * CC + h * DH) * HWSZ;
    const float* kbase = qbase + (size_t)CC * HWSZ;
    const float* vbase = qbase + (size_t)2 * CC * HWSZ;

    for (int e = tid; e < 512; e += 128) {
        int d = e >> 4, t = e & 15;
        int hw = ((wy * 4 + (t >> 2)) << 5) + wx * 4 + (t & 3);
        qh[t * QK_STR + d] = __float2half_rn(qbase[(size_t)d * HWSZ + hw]);
    }
    for (int e = tid; e < 2048; e += 128) {
        int d = e >> 6, kt = e & 63;
        int j = widx[kt >> 4];
        int t = kt & 15;
        int hw = (((j >> 3) * 4 + (t >> 2)) << 5) + (j & 7) * 4 + (t & 3);
        kh[kt * QK_STR + d] = __float2half_rn(kbase[(size_t)d * HWSZ + hw]);
        vh[d * V_STR + kt]  = __float2half_rn(vbase[(size_t)d * HWSZ + hw]);
    }
    __syncthreads();

    int warp = tid >> 5, lane = tid & 31;
    int gq = lane >> 2, tq = lane & 3;
    const float scale = 0.17677669529663687f;

    {
        float sc0[4] = {0.f, 0.f, 0.f, 0.f};
        float sc1[4] = {0.f, 0.f, 0.f, 0.f};
        #pragma unroll
        for (int ks = 0; ks < 2; ks++) {
            int cb = ks * 16 + 2 * tq;
            uint32_t ah[4];
            ah[0] = *(const uint32_t*)&qh[gq * QK_STR + cb];
            ah[1] = *(const uint32_t*)&qh[(gq + 8) * QK_STR + cb];
            ah[2] = *(const uint32_t*)&qh[gq * QK_STR + cb + 8];
            ah[3] = *(const uint32_t*)&qh[(gq + 8) * QK_STR + cb + 8];
            #pragma unroll
            for (int nt = 0; nt < 2; nt++) {
                int key = warp * 16 + nt * 8 + gq;
                uint32_t bh0 = *(const uint32_t*)&kh[key * QK_STR + cb];
                uint32_t bh1 = *(const uint32_t*)&kh[key * QK_STR + cb + 8];
                mma_f16(nt ? sc1 : sc0, ah, bh0, bh1);
            }
        }
        #pragma unroll
        for (int nt = 0; nt < 2; nt++) {
            const float* sc = nt ? sc1 : sc0;
            int c0 = warp * 16 + nt * 8 + 2 * tq;
            ss[gq * SS_STR + c0]           = sc[0] * scale;
            ss[gq * SS_STR + c0 + 1]       = sc[1] * scale;
            ss[(gq + 8) * SS_STR + c0]     = sc[2] * scale;
            ss[(gq + 8) * SS_STR + c0 + 1] = sc[3] * scale;
        }
    }
    __syncthreads();

    #pragma unroll
    for (int rr = 0; rr < 4; rr++) {
        int row = warp * 4 + rr;
        float s0 = ss[row * SS_STR + lane];
        float s1 = ss[row * SS_STR + lane + 32];
        float mx = fmaxf(s0, s1);
        #pragma unroll
        for (int off = 16; off; off >>= 1) mx = fmaxf(mx, __shfl_xor_sync(0xffffffffu, mx, off));
        float e0 = expf(s0 - mx), e1 = expf(s1 - mx);
        float sum = e0 + e1;
        #pragma unroll
        for (int off = 16; off; off >>= 1) sum += __shfl_xor_sync(0xffffffffu, sum, off);
        float inv = 1.0f / sum;
        ph[row * P_STR + lane]      = __float2half_rn(e0 * inv);
        ph[row * P_STR + lane + 32] = __float2half_rn(e1 * inv);
    }
    __syncthreads();

    {
        float f[4] = {0.f, 0.f, 0.f, 0.f};
        #pragma unroll
        for (int ks = 0; ks < 4; ks++) {
            int cb = ks * 16 + 2 * tq;
            uint32_t ah[4];
            ah[0] = *(const uint32_t*)&ph[gq * P_STR + cb];
            ah[1] = *(const uint32_t*)&ph[(gq + 8) * P_STR + cb];
            ah[2] = *(const uint32_t*)&ph[gq * P_STR + cb + 8];
            ah[3] = *(const uint32_t*)&ph[(gq + 8) * P_STR + cb + 8];
            int d = warp * 8 + gq;
            uint32_t bh0 = *(const uint32_t*)&vh[d * V_STR + cb];
            uint32_t bh1 = *(const uint32_t*)&vh[d * V_STR + cb + 8];
            mma_f16(f, ah, bh0, bh1);
        }
        __half* mbase = g_msgh + ((size_t)b * CC + h * DH) * HWSZ;
        int d0 = warp * 8 + 2 * tq;
        int hwA = ((wy * 4 + (gq >> 2)) << 5) + wx * 4 + (gq & 3);
        int hwB = ((wy * 4 + ((gq + 8) >> 2)) << 5) + wx * 4 + ((gq + 8) & 3);
        mbase[(size_t)d0 * HWSZ + hwA]       = __float2half_rn(f[0]);
        mbase[(size_t)(d0 + 1) * HWSZ + hwA] = __float2half_rn(f[1]);
        mbase[(size_t)d0 * HWSZ + hwB]       = __float2half_rn(f[2]);
        mbase[(size_t)(d0 + 1) * HWSZ + hwB] = __float2half_rn(f[3]);
    }
}

// ---------------- depthwise 3x3 + bn2 + gelu (fp16 in/out) ----------------
__global__ void dw_k(const float* __restrict__ dw,
                     const float* __restrict__ g2, const float* __restrict__ b2,
                     const float* __restrict__ m2, const float* __restrict__ v2) {
    int bc = blockIdx.x;
    int c = bc & (MRC - 1);
    __shared__ float t[1024];
    __shared__ float wsh[9];
    int tid = threadIdx.x;
    const __half* p = g_h1h + (size_t)bc * HWSZ;
    {
        uint2 u = ((const uint2*)p)[tid];
        __half2 a = *(__half2*)&u.x, b2h = *(__half2*)&u.y;
        float4 f;
        f.x = __low2float(a);  f.y = __high2float(a);
        f.z = __low2float(b2h); f.w = __high2float(b2h);
        ((float4*)t)[tid] = f;
    }
    if (tid < 9) wsh[tid] = dw[c * 9 + tid];
    __syncthreads();
    float s = g2[c] * rsqrtf(v2[c] + EPSV);
    float bs = b2[c] - m2[c] * s;
    __half* outp = g_h2h + (size_t)bc * HWSZ;
    int y = tid >> 3, x0 = (tid & 7) * 4;
    float rp[4];
    #pragma unroll
    for (int j = 0; j < 4; j++) {
        int x = x0 + j;
        float acc = 0.f;
        #pragma unroll
        for (int dy = -1; dy <= 1; dy++) {
            int yy = y + dy;
            if (yy < 0 || yy > 31) continue;
            #pragma unroll
            for (int dx = -1; dx <= 1; dx++) {
                int xx = x + dx;
                if (xx < 0 || xx > 31) continue;
                acc += wsh[(dy + 1) * 3 + (dx + 1)] * t[yy * 32 + xx];
            }
        }
        rp[j] = gelu_f(acc * s + bs);
    }
    __half2 o0 = __floats2half2_rn(rp[0], rp[1]);
    __half2 o1 = __floats2half2_rn(rp[2], rp[3]);
    uint2 u; u.x = *(uint32_t*)&o0; u.y = *(uint32_t*)&o1;
    ((uint2*)outp)[tid] = u;
}

// ---------------- launcher ----------------
extern "C" void kernel_launch(void* const* d_in, const int* in_sizes, int n_in,
                              void* d_out, int out_size) {
    const float* x      = (const float*)d_in[0];
    const float* bn0_g  = (const float*)d_in[1];
    const float* bn0_b  = (const float*)d_in[2];
    const float* bn0_m  = (const float*)d_in[3];
    const float* bn0_v  = (const float*)d_in[4];
    const float* w_qkv  = (const float*)d_in[5];
    const float* w_mrg  = (const float*)d_in[6];
    const float* b_mrg  = (const float*)d_in[7];
    const float* w1     = (const float*)d_in[8];
    const float* bn1_g  = (const float*)d_in[9];
    const float* bn1_b  = (const float*)d_in[10];
    const float* bn1_m  = (const float*)d_in[11];
    const float* bn1_v  = (const float*)d_in[12];
    const float* dw     = (const float*)d_in[13];
    const float* bn2_g  = (const float*)d_in[14];
    const float* bn2_b  = (const float*)d_in[15];
    const float* bn2_m  = (const float*)d_in[16];
    const float* bn2_v  = (const float*)d_in[17];
    const float* w2     = (const float*)d_in[18];
    const float* bn3_g  = (const float*)d_in[19];
    const float* bn3_b  = (const float*)d_in[20];
    const float* bn3_m  = (const float*)d_in[21];
    const float* bn3_v  = (const float*)d_in[22];

    float *qkv, *x1;
    __half *wh, *wl, *h0h, *msgh, *x1h, *h1h, *h2h;
    cudaGetSymbolAddress((void**)&qkv,  g_qkv);
    cudaGetSymbolAddress((void**)&x1,   g_x1);
    cudaGetSymbolAddress((void**)&wh,   g_wh);
    cudaGetSymbolAddress((void**)&wl,   g_wl);
    cudaGetSymbolAddress((void**)&h0h,  g_h0h);
    cudaGetSymbolAddress((void**)&msgh, g_msgh);
    cudaGetSymbolAddress((void**)&x1h,  g_x1h);
    cudaGetSymbolAddress((void**)&h1h,  g_h1h);
    cudaGetSymbolAddress((void**)&h2h,  g_h2h);

    cudaFuncSetAttribute((const void*)mgemm_k<0,2,1,0>, cudaFuncAttributeMaxDynamicSharedMemorySize, 58368);
    cudaFuncSetAttribute((const void*)mgemm_k<1,1,1,1>, cudaFuncAttributeMaxDynamicSharedMemorySize, 37888);
    cudaFuncSetAttribute((const void*)mgemm_k<2,1,0,1>, cudaFuncAttributeMaxDynamicSharedMemorySize, 37888);
    cudaFuncSetAttribute((const void*)mgemm_k<3,1,1,0>, cudaFuncAttributeMaxDynamicSharedMemorySize, 37888);

    // 0. pre-split weights to fp16
    wsplit_k<<<(WTOT + 255) / 256, 256>>>(w_qkv, w_mrg, w1, w2);

    // 1. h0 = gelu(bn0(x)) -> fp16
    bn0_gelu_k<<<(BB * CC * HWSZ / 4 + 255) / 256, 256>>>(x, bn0_g, bn0_b, bn0_m, bn0_v);

    // 2. qkv = w_qkv @ h0   (2-pass: W exact, A fp16)
    mgemm_k<0,2,1,0><<<dim3(768 / 128, 8, BB), 256, 58368>>>(
        wh + WOFF_QKV, wl, h0h, qkv, nullptr, 768, 256,
        nullptr, nullptr, nullptr, nullptr, nullptr, nullptr);

    // 3. window means (block per (b,h,d))
    wmean_k<<<BB * HEADS * DH, 256>>>();

    // 4. affinity + top-4
    topk_k<<<BB * HEADS, 256>>>();

    // 5. gathered attention (HMMA, 1-pass fp16)
    attn_k<<<BB * HEADS * NWIN, 128>>>();

    // 6. x1 = x + w_merge @ msg + b_merge
    mgemm_k<1,1,1,1><<<dim3(CC / 128, 8, BB), 256, 37888>>>(
        wh + WOFF_MRG, nullptr, msgh, x1, x1h, CC, 256,
        x, b_mrg, nullptr, nullptr, nullptr, nullptr);

    // 7. h1 = gelu(bn1(w1 @ x1)) -> fp16
    mgemm_k<2,1,0,1><<<dim3(MRC / 128, 8, BB), 256, 37888>>>(
        wh + WOFF_W1, nullptr, x1h, nullptr, h1h, MRC, 256,
        nullptr, nullptr, bn1_g, bn1_b, bn1_m, bn1_v);

    // 8. h2 = gelu(bn2(dwconv3x3(h1))) -> fp16
    dw_k<<<BB * MRC, 256>>>(dw, bn2_g, bn2_b, bn2_m, bn2_v);

    // 9. out = x1 + bn3(w2 @ h2)
    mgemm_k<3,1,1,0><<<dim3(CC / 128, 8, BB), 256, 37888>>>(
        wh + WOFF_W2, nullptr, h2h, (float*)d_out, nullptr, CC, 1024,
        x1, nullptr, bn3_g, bn3_b, bn3_m, bn3_v);
}

// round 10
// speedup vs baseline: 1.8141x; 1.0979x over previous
#include <cuda_runtime.h>
#include <cuda_fp16.h>
#include <cstdint>
#include <math.h>

// ---------------- problem constants ----------------
#define BB   16
#define CC   256
#define HWSZ 1024
#define DH   32
#define HEADS 8
#define KTOP 4
#define MRC  1024
#define NWIN 64
#define EPSV 1e-5f

// pre-split weight offsets (halves)
#define WOFF_QKV 0
#define WOFF_MRG 196608
#define WOFF_W1  262144
#define WOFF_W2  524288
#define WTOT     786432

// ---------------- device scratch ----------------
__device__ float  g_qm  [BB * HEADS * NWIN * DH];
__device__ float  g_km  [BB * HEADS * NWIN * DH];
__device__ int    g_idx [BB * HEADS * NWIN * KTOP];
__device__ float  g_x1  [BB * CC  * HWSZ];
__device__ __half g_h0h [BB * CC  * HWSZ];
__device__ __half g_qkvh[BB * 3*CC * HWSZ];
__device__ __half g_msgh[BB * CC  * HWSZ];
__device__ __half g_x1h [BB * CC  * HWSZ];
__device__ __half g_h1h [BB * MRC * HWSZ];
__device__ __half g_h2h [BB * MRC * HWSZ];
__device__ __half g_wh  [WTOT];
__device__ __half g_wl  [196608];   // lo only for qkv

__device__ __forceinline__ float gelu_f(float x) {
    return 0.5f * x * (1.0f + erff(x * 0.7071067811865475f));
}

// ---------------- fp16 warp MMA + ldmatrix + cp.async ----------------
__device__ __forceinline__ void mma_f16(float* d, const uint32_t* a, uint32_t b0, uint32_t b1) {
    asm volatile(
        "mma.sync.aligned.m16n8k16.row.col.f32.f16.f16.f32 "
        "{%0,%1,%2,%3}, {%4,%5,%6,%7}, {%8,%9}, {%0,%1,%2,%3};"
        : "+f"(d[0]), "+f"(d[1]), "+f"(d[2]), "+f"(d[3])
        : "r"(a[0]), "r"(a[1]), "r"(a[2]), "r"(a[3]), "r"(b0), "r"(b1));
}
__device__ __forceinline__ void ldsm_x2_t(uint32_t& r0, uint32_t& r1, uint32_t addr) {
    asm volatile("ldmatrix.sync.aligned.m8n8.x2.trans.shared.b16 {%0,%1}, [%2];"
                 : "=r"(r0), "=r"(r1) : "r"(addr));
}
__device__ __forceinline__ uint32_t smem_u32(const void* p) {
    uint32_t a;
    asm("{ .reg .u64 t; cvta.to.shared.u64 t, %1; cvt.u32.u64 %0, t; }" : "=r"(a) : "l"(p));
    return a;
}
__device__ __forceinline__ void cp16(uint32_t dst, const void* src) {
    asm volatile("cp.async.cg.shared.global [%0], [%1], 16;" :: "r"(dst), "l"(src) : "memory");
}
#define CP_COMMIT() asm volatile("cp.async.commit_group;" ::: "memory")
#define CP_WAIT(N)  asm volatile("cp.async.wait_group %0;" :: "n"(N) : "memory")
__device__ __forceinline__ void cvt_split(float x, __half& h, __half& l) {
    h = __float2half_rn(x);
    l = __float2half_rn(x - __half2float(h));
}

#define A_STR 136

// ---------------- weight pre-split ----------------
__global__ void wsplit_k(const float* __restrict__ wqkv, const float* __restrict__ wmrg,
                         const float* __restrict__ w1,   const float* __restrict__ w2) {
    int i = blockIdx.x * 256 + threadIdx.x;
    if (i >= WTOT) return;
    if (i < WOFF_MRG) {
        __half h, l; cvt_split(wqkv[i], h, l);
        g_wh[i] = h; g_wl[i] = l;
    } else if (i < WOFF_W1) {
        g_wh[i] = __float2half_rn(wmrg[i - WOFF_MRG]);
    } else if (i < WOFF_W2) {
        g_wh[i] = __float2half_rn(w1[i - WOFF_W1]);
    } else {
        g_wh[i] = __float2half_rn(w2[i - WOFF_W2]);
    }
}

// ---------------- h0 = gelu(bn0(x)) -> fp16 ----------------
__global__ void bn0_gelu_k(const float* __restrict__ x,
                           const float* __restrict__ g, const float* __restrict__ b,
                           const float* __restrict__ m, const float* __restrict__ v) {
    int i = blockIdx.x * 256 + threadIdx.x;
    if (i >= BB * CC * HWSZ / 4) return;
    int c = (i >> 8) & (CC - 1);
    float s = g[c] * rsqrtf(v[c] + EPSV);
    float sh = b[c] - m[c] * s;
    float4 xv = ((const float4*)x)[i];
    __half2 h0 = __floats2half2_rn(gelu_f(xv.x * s + sh), gelu_f(xv.y * s + sh));
    __half2 h1 = __floats2half2_rn(gelu_f(xv.z * s + sh), gelu_f(xv.w * s + sh));
    uint2 u; u.x = *(uint32_t*)&h0; u.y = *(uint32_t*)&h1;
    ((uint2*)g_h0h)[i] = u;
}

// ---------------- tensor-core fused GEMM (cp.async 3-stage) ----------------
// PASSES: 1 = hiW*hiA; 2 = + loW*hiA (W exact, A rounded)
template<int MODE, int PASSES, int WF32, int WF16>
__global__ void __launch_bounds__(256, 2)
mgemm_k(const __half* __restrict__ Whg, const __half* __restrict__ Wlg,
        const __half* __restrict__ Ahg,
        float* __restrict__ Out, __half* __restrict__ Outh, int O, int Kd,
        const float* __restrict__ Res, const float* __restrict__ bias,
        const float* __restrict__ g,  const float* __restrict__ bb,
        const float* __restrict__ mm, const float* __restrict__ vv) {
    constexpr int WL_O = 10240;
    constexpr int AH_O = (PASSES >= 2) ? 20480 : 10240;
    constexpr int STG  = AH_O + 8704;

    extern __shared__ char smc[];
    const int tid = threadIdx.x, lane = tid & 31, warp = tid >> 5;
    const int b = blockIdx.z, om = blockIdx.x * 128, n0 = blockIdx.y * 128;
    const int wm = warp >> 1, wn = warp & 1;
    const int gq = lane >> 2, tq = lane & 3;
    const uint32_t smbase = smem_u32(smc);

    const __half* Abh = Ahg + (size_t)b * Kd * HWSZ + n0;

    float acc[2][8][4];
    #pragma unroll
    for (int mt = 0; mt < 2; mt++)
        #pragma unroll
        for (int nt = 0; nt < 8; nt++)
            #pragma unroll
            for (int r = 0; r < 4; r++) acc[mt][nt][r] = 0.f;

    const uint32_t aoff = (uint32_t)(((lane & 15) * A_STR + wn * 64) * 2);
    const int nch = Kd >> 5;

    auto issue = [&](int ch, int st) {
        int k0 = ch << 5;
        uint32_t stu = smbase + (uint32_t)st * STG;
        #pragma unroll
        for (int it = 0; it < 2; it++) {
            int e = tid + it * 256;
            int row = e >> 2, c4 = e & 3;
            cp16(stu + row * 80 + c4 * 16, Whg + (size_t)(om + row) * Kd + k0 + c4 * 8);
            if (PASSES >= 2)
                cp16(stu + WL_O + row * 80 + c4 * 16, Wlg + (size_t)(om + row) * Kd + k0 + c4 * 8);
        }
        #pragma unroll
        for (int it = 0; it < 2; it++) {
            int e = tid + it * 256;
            int row = e >> 4, col8 = (e & 15) * 8;
            cp16(stu + AH_O + (row * A_STR + col8) * 2, Abh + (size_t)(k0 + row) * HWSZ + col8);
        }
        CP_COMMIT();
    };

    issue(0, 0);
    issue(1, 1);

    int st = 0;
    for (int ch = 0; ch < nch; ch++) {
        if (ch + 1 < nch) { CP_WAIT(1); } else { CP_WAIT(0); }
        __syncthreads();
        if (ch + 2 < nch) {
            int st2 = st + 2; if (st2 >= 3) st2 -= 3;
            issue(ch + 2, st2);
        }

        uint32_t stu = smbase + (uint32_t)st * STG;
        const __half* ws_hi = (const __half*)(smc + (size_t)st * STG);
        const __half* ws_lo = ws_hi + WL_O / 2;

        #pragma unroll
        for (int ks = 0; ks < 2; ks++) {
            uint32_t afh[2][4], afl[2][4];
            #pragma unroll
            for (int mt = 0; mt < 2; mt++) {
                int rb = wm * 32 + mt * 16;
                int cb = ks * 16 + 2 * tq;
                afh[mt][0] = *(const uint32_t*)&ws_hi[(rb + gq)     * 40 + cb];
                afh[mt][1] = *(const uint32_t*)&ws_hi[(rb + gq + 8) * 40 + cb];
                afh[mt][2] = *(const uint32_t*)&ws_hi[(rb + gq)     * 40 + cb + 8];
                afh[mt][3] = *(const uint32_t*)&ws_hi[(rb + gq + 8) * 40 + cb + 8];
                if (PASSES >= 2) {
                    afl[mt][0] = *(const uint32_t*)&ws_lo[(rb + gq)     * 40 + cb];
                    afl[mt][1] = *(const uint32_t*)&ws_lo[(rb + gq + 8) * 40 + cb];
                    afl[mt][2] = *(const uint32_t*)&ws_lo[(rb + gq)     * 40 + cb + 8];
                    afl[mt][3] = *(const uint32_t*)&ws_lo[(rb + gq + 8) * 40 + cb + 8];
                }
            }
            uint32_t abase_h = stu + AH_O + aoff + (uint32_t)ks * (16 * A_STR * 2);
            #pragma unroll
            for (int nt = 0; nt < 8; nt++) {
                uint32_t bh0, bh1;
                ldsm_x2_t(bh0, bh1, abase_h + nt * 16);
                #pragma unroll
                for (int mt = 0; mt < 2; mt++) {
                    mma_f16(acc[mt][nt], afh[mt], bh0, bh1);
                    if (PASSES >= 2) mma_f16(acc[mt][nt], afl[mt], bh0, bh1);
                }
            }
        }
        __syncthreads();
        st = (st + 1 == 3) ? 0 : st + 1;
    }

    // ---- epilogue ----
    #pragma unroll
    for (int mt = 0; mt < 2; mt++) {
        int o0 = om + wm * 32 + mt * 16 + gq;
        int o1 = o0 + 8;
        float s0 = 0.f, bs0 = 0.f, s1 = 0.f, bs1 = 0.f, bi0 = 0.f, bi1 = 0.f;
        if (MODE == 2 || MODE == 3) {
            s0 = g[o0] * rsqrtf(vv[o0] + EPSV); bs0 = bb[o0] - mm[o0] * s0;
            s1 = g[o1] * rsqrtf(vv[o1] + EPSV); bs1 = bb[o1] - mm[o1] * s1;
        }
        if (MODE == 1) { bi0 = bias[o0]; bi1 = bias[o1]; }
        #pragma unroll
        for (int nt = 0; nt < 8; nt++) {
            int n = n0 + wn * 64 + nt * 8 + 2 * tq;
            size_t oi0 = ((size_t)b * O + o0) * HWSZ + n;
            size_t oi1 = ((size_t)b * O + o1) * HWSZ + n;
            float r0 = acc[mt][nt][0], r1 = acc[mt][nt][1];
            float r2 = acc[mt][nt][2], r3 = acc[mt][nt][3];
            if (MODE == 1) {
                float2 e0 = *(const float2*)&Res[oi0];
                float2 e1 = *(const float2*)&Res[oi1];
                r0 += e0.x + bi0; r1 += e0.y + bi0;
                r2 += e1.x + bi1; r3 += e1.y + bi1;
            }
            if (MODE == 2) {
                r0 = gelu_f(r0 * s0 + bs0); r1 = gelu_f(r1 * s0 + bs0);
                r2 = gelu_f(r2 * s1 + bs1); r3 = gelu_f(r3 * s1 + bs1);
            }
            if (MODE == 3) {
                float2 e0 = *(const float2*)&Res[oi0];
                float2 e1 = *(const float2*)&Res[oi1];
                r0 = e0.x + r0 * s0 + bs0; r1 = e0.y + r1 * s0 + bs0;
                r2 = e1.x + r2 * s1 + bs1; r3 = e1.y + r3 * s1 + bs1;
            }
            if (WF32) {
                float2 v0 = {r0, r1}, v1 = {r2, r3};
                *(float2*)&Out[oi0] = v0;
                *(float2*)&Out[oi1] = v1;
            }
            if (WF16) {
                __half2 hv0 = __floats2half2_rn(r0, r1);
                __half2 hv1 = __floats2half2_rn(r2, r3);
                *(__half2*)&Outh[oi0] = hv0;
                *(__half2*)&Outh[oi1] = hv1;
            }
        }
    }
}

// ---------------- window means (fp16 source): block per (b,h,d) ----------------
__global__ void wmean_k() {
    int bid = blockIdx.x;             // b*256 + h*32 + d
    int d = bid & 31, h = (bid >> 5) & 7, b = bid >> 8;
    int tid = threadIdx.x;
    __shared__ float spq[256], spk[256];
    const __half* qpl = g_qkvh + ((size_t)b * 3 * CC + h * DH + d) * HWSZ;
    const __half* kpl = qpl + (size_t)CC * HWSZ;
    uint2 uq = ((const uint2*)qpl)[tid];
    uint2 uk = ((const uint2*)kpl)[tid];
    __half2 qa = *(__half2*)&uq.x, qb = *(__half2*)&uq.y;
    __half2 ka = *(__half2*)&uk.x, kb = *(__half2*)&uk.y;
    spq[tid] = __low2float(qa) + __high2float(qa) + __low2float(qb) + __high2float(qb);
    spk[tid] = __low2float(ka) + __high2float(ka) + __low2float(kb) + __high2float(kb);
    __syncthreads();
    if (tid < 64) {
        int wy = tid >> 3, wx = tid & 7;
        int base = wy * 32 + wx;
        float sq = spq[base] + spq[base + 8] + spq[base + 16] + spq[base + 24];
        float sk = spk[base] + spk[base + 8] + spk[base + 16] + spk[base + 24];
        size_t o = ((size_t)(b * 8 + h) * 64 + tid) * DH + d;
        g_qm[o] = sq * 0.0625f;
        g_km[o] = sk * 0.0625f;
    }
}

// ---------------- affinity + exact top-4 ----------------
__global__ void topk_k() {
    int bh = blockIdx.x;
    __shared__ float kt[32][65];
    __shared__ float qs[64][32];
    int tid = threadIdx.x, warp = tid >> 5, lane = tid & 31;
    for (int e = tid; e < 2048; e += 256) {
        int j = e >> 5, d = e & 31;
        kt[d][j] = g_km[(size_t)bh * 2048 + e];
        qs[j][d] = g_qm[(size_t)bh * 2048 + e];
    }
    __syncthreads();
    for (int ii = 0; ii < 8; ii++) {
        int i = warp * 8 + ii;
        float s0 = 0.f, s1 = 0.f;
        #pragma unroll
        for (int d = 0; d < 32; d++) {
            float q = qs[i][d];
            s0 += q * kt[d][lane];
            s1 += q * kt[d][lane + 32];
        }
        float v0 = s0, v1 = s1;
        #pragma unroll
        for (int t = 0; t < KTOP; t++) {
            float bvv; int bj;
            if (v0 >= v1) { bvv = v0; bj = lane; } else { bvv = v1; bj = lane + 32; }
            #pragma unroll
            for (int off = 16; off; off >>= 1) {
                float ov = __shfl_xor_sync(0xffffffffu, bvv, off);
                int   oj = __shfl_xor_sync(0xffffffffu, bj,  off);
                if (ov > bvv || (ov == bvv && oj < bj)) { bvv = ov; bj = oj; }
            }
            if (lane == 0) g_idx[((size_t)bh * 64 + i) * KTOP + t] = bj;
            if (bj == lane)      v0 = -INFINITY;
            if (bj == lane + 32) v1 = -INFINITY;
        }
    }
}

// ---------------- gathered window attention (HMMA, fp16 source) ----------------
#define QK_STR 40
#define V_STR  72
#define SS_STR 68
#define P_STR  72
__global__ void __launch_bounds__(128) attn_k() {
    int bid = blockIdx.x;
    int n = bid & 63;
    int h = (bid >> 6) & 7;
    int b = bid >> 9;
    __shared__ __half qh[16 * QK_STR];
    __shared__ __half kh[64 * QK_STR];
    __shared__ __half vh[32 * V_STR];
    __shared__ float  ss[16 * SS_STR];
    __shared__ __half ph[16 * P_STR];
    __shared__ int    widx[KTOP];
    int tid = threadIdx.x;
    if (tid < KTOP) widx[tid] = g_idx[(size_t)bid * KTOP + tid];
    __syncthreads();

    int wy = n >> 3, wx = n & 7;
    const __half* qbase = g_qkvh + ((size_t)b * 3 * CC + h * DH) * HWSZ;
    const __half* kbase = qbase + (size_t)CC * HWSZ;
    const __half* vbase = qbase + (size_t)2 * CC * HWSZ;

    for (int e = tid; e < 512; e += 128) {
        int d = e >> 4, t = e & 15;
        int hw = ((wy * 4 + (t >> 2)) << 5) + wx * 4 + (t & 3);
        qh[t * QK_STR + d] = qbase[(size_t)d * HWSZ + hw];
    }
    for (int e = tid; e < 2048; e += 128) {
        int d = e >> 6, kt = e & 63;
        int j = widx[kt >> 4];
        int t = kt & 15;
        int hw = (((j >> 3) * 4 + (t >> 2)) << 5) + (j & 7) * 4 + (t & 3);
        kh[kt * QK_STR + d] = kbase[(size_t)d * HWSZ + hw];
        vh[d * V_STR + kt]  = vbase[(size_t)d * HWSZ + hw];
    }
    __syncthreads();

    int warp = tid >> 5, lane = tid & 31;
    int gq = lane >> 2, tq = lane & 3;
    const float scale = 0.17677669529663687f;

    {
        float sc0[4] = {0.f, 0.f, 0.f, 0.f};
        float sc1[4] = {0.f, 0.f, 0.f, 0.f};
        #pragma unroll
        for (int ks = 0; ks < 2; ks++) {
            int cb = ks * 16 + 2 * tq;
            uint32_t ah[4];
            ah[0] = *(const uint32_t*)&qh[gq * QK_STR + cb];
            ah[1] = *(const uint32_t*)&qh[(gq + 8) * QK_STR + cb];
            ah[2] = *(const uint32_t*)&qh[gq * QK_STR + cb + 8];
            ah[3] = *(const uint32_t*)&qh[(gq + 8) * QK_STR + cb + 8];
            #pragma unroll
            for (int nt = 0; nt < 2; nt++) {
                int key = warp * 16 + nt * 8 + gq;
                uint32_t bh0 = *(const uint32_t*)&kh[key * QK_STR + cb];
                uint32_t bh1 = *(const uint32_t*)&kh[key * QK_STR + cb + 8];
                mma_f16(nt ? sc1 : sc0, ah, bh0, bh1);
            }
        }
        #pragma unroll
        for (int nt = 0; nt < 2; nt++) {
            const float* sc = nt ? sc1 : sc0;
            int c0 = warp * 16 + nt * 8 + 2 * tq;
            ss[gq * SS_STR + c0]           = sc[0] * scale;
            ss[gq * SS_STR + c0 + 1]       = sc[1] * scale;
            ss[(gq + 8) * SS_STR + c0]     = sc[2] * scale;
            ss[(gq + 8) * SS_STR + c0 + 1] = sc[3] * scale;
        }
    }
    __syncthreads();

    #pragma unroll
    for (int rr = 0; rr < 4; rr++) {
        int row = warp * 4 + rr;
        float s0 = ss[row * SS_STR + lane];
        float s1 = ss[row * SS_STR + lane + 32];
        float mx = fmaxf(s0, s1);
        #pragma unroll
        for (int off = 16; off; off >>= 1) mx = fmaxf(mx, __shfl_xor_sync(0xffffffffu, mx, off));
        float e0 = expf(s0 - mx), e1 = expf(s1 - mx);
        float sum = e0 + e1;
        #pragma unroll
        for (int off = 16; off; off >>= 1) sum += __shfl_xor_sync(0xffffffffu, sum, off);
        float inv = 1.0f / sum;
        ph[row * P_STR + lane]      = __float2half_rn(e0 * inv);
        ph[row * P_STR + lane + 32] = __float2half_rn(e1 * inv);
    }
    __syncthreads();

    {
        float f[4] = {0.f, 0.f, 0.f, 0.f};
        #pragma unroll
        for (int ks = 0; ks < 4; ks++) {
            int cb = ks * 16 + 2 * tq;
            uint32_t ah[4];
            ah[0] = *(const uint32_t*)&ph[gq * P_STR + cb];
            ah[1] = *(const uint32_t*)&ph[(gq + 8) * P_STR + cb];
            ah[2] = *(const uint32_t*)&ph[gq * P_STR + cb + 8];
            ah[3] = *(const uint32_t*)&ph[(gq + 8) * P_STR + cb + 8];
            int d = warp * 8 + gq;
            uint32_t bh0 = *(const uint32_t*)&vh[d * V_STR + cb];
            uint32_t bh1 = *(const uint32_t*)&vh[d * V_STR + cb + 8];
            mma_f16(f, ah, bh0, bh1);
        }
        __half* mbase = g_msgh + ((size_t)b * CC + h * DH) * HWSZ;
        int d0 = warp * 8 + 2 * tq;
        int hwA = ((wy * 4 + (gq >> 2)) << 5) + wx * 4 + (gq & 3);
        int hwB = ((wy * 4 + ((gq + 8) >> 2)) << 5) + wx * 4 + ((gq + 8) & 3);
        mbase[(size_t)d0 * HWSZ + hwA]       = __float2half_rn(f[0]);
        mbase[(size_t)(d0 + 1) * HWSZ + hwA] = __float2half_rn(f[1]);
        mbase[(size_t)d0 * HWSZ + hwB]       = __float2half_rn(f[2]);
        mbase[(size_t)(d0 + 1) * HWSZ + hwB] = __float2half_rn(f[3]);
    }
}

// ---------------- depthwise 3x3 + bn2 + gelu (fp16 in/out) ----------------
__global__ void dw_k(const float* __restrict__ dw,
                     const float* __restrict__ g2, const float* __restrict__ b2,
                     const float* __restrict__ m2, const float* __restrict__ v2) {
    int bc = blockIdx.x;
    int c = bc & (MRC - 1);
    __shared__ float t[1024];
    __shared__ float wsh[9];
    int tid = threadIdx.x;
    const __half* p = g_h1h + (size_t)bc * HWSZ;
    {
        uint2 u = ((const uint2*)p)[tid];
        __half2 a = *(__half2*)&u.x, b2h = *(__half2*)&u.y;
        float4 f;
        f.x = __low2float(a);  f.y = __high2float(a);
        f.z = __low2float(b2h); f.w = __high2float(b2h);
        ((float4*)t)[tid] = f;
    }
    if (tid < 9) wsh[tid] = dw[c * 9 + tid];
    __syncthreads();
    float s = g2[c] * rsqrtf(v2[c] + EPSV);
    float bs = b2[c] - m2[c] * s;
    __half* outp = g_h2h + (size_t)bc * HWSZ;
    int y = tid >> 3, x0 = (tid & 7) * 4;
    float rp[4];
    #pragma unroll
    for (int j = 0; j < 4; j++) {
        int x = x0 + j;
        float acc = 0.f;
        #pragma unroll
        for (int dy = -1; dy <= 1; dy++) {
            int yy = y + dy;
            if (yy < 0 || yy > 31) continue;
            #pragma unroll
            for (int dx = -1; dx <= 1; dx++) {
                int xx = x + dx;
                if (xx < 0 || xx > 31) continue;
                acc += wsh[(dy + 1) * 3 + (dx + 1)] * t[yy * 32 + xx];
            }
        }
        rp[j] = gelu_f(acc * s + bs);
    }
    __half2 o0 = __floats2half2_rn(rp[0], rp[1]);
    __half2 o1 = __floats2half2_rn(rp[2], rp[3]);
    uint2 u; u.x = *(uint32_t*)&o0; u.y = *(uint32_t*)&o1;
    ((uint2*)outp)[tid] = u;
}

// ---------------- launcher ----------------
extern "C" void kernel_launch(void* const* d_in, const int* in_sizes, int n_in,
                              void* d_out, int out_size) {
    const float* x      = (const float*)d_in[0];
    const float* bn0_g  = (const float*)d_in[1];
    const float* bn0_b  = (const float*)d_in[2];
    const float* bn0_m  = (const float*)d_in[3];
    const float* bn0_v  = (const float*)d_in[4];
    const float* w_qkv  = (const float*)d_in[5];
    const float* w_mrg  = (const float*)d_in[6];
    const float* b_mrg  = (const float*)d_in[7];
    const float* w1     = (const float*)d_in[8];
    const float* bn1_g  = (const float*)d_in[9];
    const float* bn1_b  = (const float*)d_in[10];
    const float* bn1_m  = (const float*)d_in[11];
    const float* bn1_v  = (const float*)d_in[12];
    const float* dw     = (const float*)d_in[13];
    const float* bn2_g  = (const float*)d_in[14];
    const float* bn2_b  = (const float*)d_in[15];
    const float* bn2_m  = (const float*)d_in[16];
    const float* bn2_v  = (const float*)d_in[17];
    const float* w2     = (const float*)d_in[18];
    const float* bn3_g  = (const float*)d_in[19];
    const float* bn3_b  = (const float*)d_in[20];
    const float* bn3_m  = (const float*)d_in[21];
    const float* bn3_v  = (const float*)d_in[22];

    float *x1;
    __half *wh, *wl, *h0h, *qkvh, *msgh, *x1h, *h1h, *h2h;
    cudaGetSymbolAddress((void**)&x1,   g_x1);
    cudaGetSymbolAddress((void**)&wh,   g_wh);
    cudaGetSymbolAddress((void**)&wl,   g_wl);
    cudaGetSymbolAddress((void**)&h0h,  g_h0h);
    cudaGetSymbolAddress((void**)&qkvh, g_qkvh);
    cudaGetSymbolAddress((void**)&msgh, g_msgh);
    cudaGetSymbolAddress((void**)&x1h,  g_x1h);
    cudaGetSymbolAddress((void**)&h1h,  g_h1h);
    cudaGetSymbolAddress((void**)&h2h,  g_h2h);

    cudaFuncSetAttribute((const void*)mgemm_k<0,2,0,1>, cudaFuncAttributeMaxDynamicSharedMemorySize, 87552);
    cudaFuncSetAttribute((const void*)mgemm_k<1,1,1,1>, cudaFuncAttributeMaxDynamicSharedMemorySize, 56832);
    cudaFuncSetAttribute((const void*)mgemm_k<2,1,0,1>, cudaFuncAttributeMaxDynamicSharedMemorySize, 56832);
    cudaFuncSetAttribute((const void*)mgemm_k<3,1,1,0>, cudaFuncAttributeMaxDynamicSharedMemorySize, 56832);

    // 0. pre-split weights to fp16
    wsplit_k<<<(WTOT + 255) / 256, 256>>>(w_qkv, w_mrg, w1, w2);

    // 1. h0 = gelu(bn0(x)) -> fp16
    bn0_gelu_k<<<(BB * CC * HWSZ / 4 + 255) / 256, 256>>>(x, bn0_g, bn0_b, bn0_m, bn0_v);

    // 2. qkv = w_qkv @ h0   (2-pass, fp16 output only)
    mgemm_k<0,2,0,1><<<dim3(768 / 128, 8, BB), 256, 87552>>>(
        wh + WOFF_QKV, wl, h0h, nullptr, qkvh, 768, 256,
        nullptr, nullptr, nullptr, nullptr, nullptr, nullptr);

    // 3. window means (fp16 source)
    wmean_k<<<BB * HEADS * DH, 256>>>();

    // 4. affinity + top-4
    topk_k<<<BB * HEADS, 256>>>();

    // 5. gathered attention (HMMA, fp16 source)
    attn_k<<<BB * HEADS * NWIN, 128>>>();

    // 6. x1 = x + w_merge @ msg + b_merge
    mgemm_k<1,1,1,1><<<dim3(CC / 128, 8, BB), 256, 56832>>>(
        wh + WOFF_MRG, nullptr, msgh, x1, x1h, CC, 256,
        x, b_mrg, nullptr, nullptr, nullptr, nullptr);

    // 7. h1 = gelu(bn1(w1 @ x1)) -> fp16
    mgemm_k<2,1,0,1><<<dim3(MRC / 128, 8, BB), 256, 56832>>>(
        wh + WOFF_W1, nullptr, x1h, nullptr, h1h, MRC, 256,
        nullptr, nullptr, bn1_g, bn1_b, bn1_m, bn1_v);

    // 8. h2 = gelu(bn2(dwconv3x3(h1))) -> fp16
    dw_k<<<BB * MRC, 256>>>(dw, bn2_g, bn2_b, bn2_m, bn2_v);

    // 9. out = x1 + bn3(w2 @ h2)
    mgemm_k<3,1,1,0><<<dim3(CC / 128, 8, BB), 256, 56832>>>(
        wh + WOFF_W2, nullptr, h2h, (float*)d_out, nullptr, CC, 1024,
        x1, nullptr, bn3_g, bn3_b, bn3_m, bn3_v);
}

// round 11
// speedup vs baseline: 1.9254x; 1.0614x over previous
#include <cuda_runtime.h>
#include <cuda_fp16.h>
#include <cstdint>
#include <math.h>

// ---------------- problem constants ----------------
#define BB   16
#define CC   256
#define HWSZ 1024
#define DH   32
#define HEADS 8
#define KTOP 4
#define MRC  1024
#define NWIN 64
#define EPSV 1e-5f

// pre-split weight offsets (halves)
#define WOFF_QKV 0
#define WOFF_MRG 196608
#define WOFF_W1  262144
#define WOFF_W2  524288
#define WTOT     786432

// ---------------- device scratch ----------------
__device__ float  g_qm  [BB * HEADS * NWIN * DH];
__device__ float  g_km  [BB * HEADS * NWIN * DH];
__device__ int    g_idx [BB * HEADS * NWIN * KTOP];
__device__ float  g_x1  [BB * CC  * HWSZ];
__device__ __half g_h0h [BB * CC  * HWSZ];
__device__ __half g_qkvh[BB * 3*CC * HWSZ];
__device__ __half g_msgh[BB * CC  * HWSZ];
__device__ __half g_x1h [BB * CC  * HWSZ];
__device__ __half g_h1h [BB * MRC * HWSZ];
__device__ __half g_h2h [BB * MRC * HWSZ];
__device__ __half g_wh  [WTOT];
__device__ __half g_wl  [196608];   // lo only for qkv

__device__ __forceinline__ float gelu_f(float x) {
    return 0.5f * x * (1.0f + erff(x * 0.7071067811865475f));
}

// ---------------- fp16 warp MMA + ldmatrix + cp.async ----------------
__device__ __forceinline__ void mma_f16(float* d, const uint32_t* a, uint32_t b0, uint32_t b1) {
    asm volatile(
        "mma.sync.aligned.m16n8k16.row.col.f32.f16.f16.f32 "
        "{%0,%1,%2,%3}, {%4,%5,%6,%7}, {%8,%9}, {%0,%1,%2,%3};"
        : "+f"(d[0]), "+f"(d[1]), "+f"(d[2]), "+f"(d[3])
        : "r"(a[0]), "r"(a[1]), "r"(a[2]), "r"(a[3]), "r"(b0), "r"(b1));
}
__device__ __forceinline__ void ldsm_x2_t(uint32_t& r0, uint32_t& r1, uint32_t addr) {
    asm volatile("ldmatrix.sync.aligned.m8n8.x2.trans.shared.b16 {%0,%1}, [%2];"
                 : "=r"(r0), "=r"(r1) : "r"(addr));
}
__device__ __forceinline__ void ldsm_x4(uint32_t* r, uint32_t addr) {
    asm volatile("ldmatrix.sync.aligned.m8n8.x4.shared.b16 {%0,%1,%2,%3}, [%4];"
                 : "=r"(r[0]), "=r"(r[1]), "=r"(r[2]), "=r"(r[3]) : "r"(addr));
}
__device__ __forceinline__ void ldsm_x4_t(uint32_t* r, uint32_t addr) {
    asm volatile("ldmatrix.sync.aligned.m8n8.x4.trans.shared.b16 {%0,%1,%2,%3}, [%4];"
                 : "=r"(r[0]), "=r"(r[1]), "=r"(r[2]), "=r"(r[3]) : "r"(addr));
}
__device__ __forceinline__ uint32_t smem_u32(const void* p) {
    uint32_t a;
    asm("{ .reg .u64 t; cvta.to.shared.u64 t, %1; cvt.u32.u64 %0, t; }" : "=r"(a) : "l"(p));
    return a;
}
__device__ __forceinline__ void cp16(uint32_t dst, const void* src) {
    asm volatile("cp.async.cg.shared.global [%0], [%1], 16;" :: "r"(dst), "l"(src) : "memory");
}
#define CP_COMMIT() asm volatile("cp.async.commit_group;" ::: "memory")
#define CP_WAIT(N)  asm volatile("cp.async.wait_group %0;" :: "n"(N) : "memory")
__device__ __forceinline__ void cvt_split(float x, __half& h, __half& l) {
    h = __float2half_rn(x);
    l = __float2half_rn(x - __half2float(h));
}

#define A_STR 136

// ---------------- weight pre-split ----------------
__global__ void wsplit_k(const float* __restrict__ wqkv, const float* __restrict__ wmrg,
                         const float* __restrict__ w1,   const float* __restrict__ w2) {
    int i = blockIdx.x * 256 + threadIdx.x;
    if (i >= WTOT) return;
    if (i < WOFF_MRG) {
        __half h, l; cvt_split(wqkv[i], h, l);
        g_wh[i] = h; g_wl[i] = l;
    } else if (i < WOFF_W1) {
        g_wh[i] = __float2half_rn(wmrg[i - WOFF_MRG]);
    } else if (i < WOFF_W2) {
        g_wh[i] = __float2half_rn(w1[i - WOFF_W1]);
    } else {
        g_wh[i] = __float2half_rn(w2[i - WOFF_W2]);
    }
}

// ---------------- h0 = gelu(bn0(x)) -> fp16 ----------------
__global__ void bn0_gelu_k(const float* __restrict__ x,
                           const float* __restrict__ g, const float* __restrict__ b,
                           const float* __restrict__ m, const float* __restrict__ v) {
    int i = blockIdx.x * 256 + threadIdx.x;
    if (i >= BB * CC * HWSZ / 4) return;
    int c = (i >> 8) & (CC - 1);
    float s = g[c] * rsqrtf(v[c] + EPSV);
    float sh = b[c] - m[c] * s;
    float4 xv = ((const float4*)x)[i];
    __half2 h0 = __floats2half2_rn(gelu_f(xv.x * s + sh), gelu_f(xv.y * s + sh));
    __half2 h1 = __floats2half2_rn(gelu_f(xv.z * s + sh), gelu_f(xv.w * s + sh));
    uint2 u; u.x = *(uint32_t*)&h0; u.y = *(uint32_t*)&h1;
    ((uint2*)g_h0h)[i] = u;
}

// ---------------- tensor-core fused GEMM (cp.async 3-stage, ldmatrix W) ----------------
// PASSES: 1 = hiW*hiA; 2 = + loW*hiA (W exact, A rounded)
template<int MODE, int PASSES, int WF32, int WF16>
__global__ void __launch_bounds__(256, 2)
mgemm_k(const __half* __restrict__ Whg, const __half* __restrict__ Wlg,
        const __half* __restrict__ Ahg,
        float* __restrict__ Out, __half* __restrict__ Outh, int O, int Kd,
        const float* __restrict__ Res, const float* __restrict__ bias,
        const float* __restrict__ g,  const float* __restrict__ bb,
        const float* __restrict__ mm, const float* __restrict__ vv) {
    constexpr int WL_O = 10240;
    constexpr int AH_O = (PASSES >= 2) ? 20480 : 10240;
    constexpr int STG  = AH_O + 8704;

    extern __shared__ char smc[];
    const int tid = threadIdx.x, lane = tid & 31, warp = tid >> 5;
    const int b = blockIdx.z, om = blockIdx.x * 128, n0 = blockIdx.y * 128;
    const int wm = warp >> 1, wn = warp & 1;
    const int gq = lane >> 2, tq = lane & 3;
    const uint32_t smbase = smem_u32(smc);

    const __half* Abh = Ahg + (size_t)b * Kd * HWSZ + n0;

    float acc[2][8][4];
    #pragma unroll
    for (int mt = 0; mt < 2; mt++)
        #pragma unroll
        for (int nt = 0; nt < 8; nt++)
            #pragma unroll
            for (int r = 0; r < 4; r++) acc[mt][nt][r] = 0.f;

    const uint32_t aoff = (uint32_t)(((lane & 15) * A_STR + wn * 64) * 2);
    // W ldmatrix per-lane offset: row = wm*32 + (lane&7) + ((lane>>3)&1)*8, col = (lane>>4)*8
    const uint32_t woff = (uint32_t)(((wm * 32 + (lane & 7) + ((lane >> 3) & 1) * 8) * 40
                                     + (lane >> 4) * 8) * 2);
    const int nch = Kd >> 5;

    auto issue = [&](int ch, int st) {
        int k0 = ch << 5;
        uint32_t stu = smbase + (uint32_t)st * STG;
        #pragma unroll
        for (int it = 0; it < 2; it++) {
            int e = tid + it * 256;
            int row = e >> 2, c4 = e & 3;
            cp16(stu + row * 80 + c4 * 16, Whg + (size_t)(om + row) * Kd + k0 + c4 * 8);
            if (PASSES >= 2)
                cp16(stu + WL_O + row * 80 + c4 * 16, Wlg + (size_t)(om + row) * Kd + k0 + c4 * 8);
        }
        #pragma unroll
        for (int it = 0; it < 2; it++) {
            int e = tid + it * 256;
            int row = e >> 4, col8 = (e & 15) * 8;
            cp16(stu + AH_O + (row * A_STR + col8) * 2, Abh + (size_t)(k0 + row) * HWSZ + col8);
        }
        CP_COMMIT();
    };

    issue(0, 0);
    issue(1, 1);

    int st = 0;
    for (int ch = 0; ch < nch; ch++) {
        if (ch + 1 < nch) { CP_WAIT(1); } else { CP_WAIT(0); }
        __syncthreads();
        if (ch + 2 < nch) {
            int st2 = st + 2; if (st2 >= 3) st2 -= 3;
            issue(ch + 2, st2);
        }

        uint32_t stu = smbase + (uint32_t)st * STG;

        #pragma unroll
        for (int ks = 0; ks < 2; ks++) {
            uint32_t afh[2][4], afl[2][4];
            #pragma unroll
            for (int mt = 0; mt < 2; mt++) {
                uint32_t wa = stu + woff + (uint32_t)(mt * 16 * 40 * 2 + ks * 32);
                ldsm_x4(afh[mt], wa);
                if (PASSES >= 2) ldsm_x4(afl[mt], wa + WL_O);
            }
            uint32_t abase_h = stu + AH_O + aoff + (uint32_t)ks * (16 * A_STR * 2);
            #pragma unroll
            for (int nt = 0; nt < 8; nt++) {
                uint32_t bh0, bh1;
                ldsm_x2_t(bh0, bh1, abase_h + nt * 16);
                #pragma unroll
                for (int mt = 0; mt < 2; mt++) {
                    mma_f16(acc[mt][nt], afh[mt], bh0, bh1);
                    if (PASSES >= 2) mma_f16(acc[mt][nt], afl[mt], bh0, bh1);
                }
            }
        }
        st = (st + 1 == 3) ? 0 : st + 1;
    }
    __syncthreads();

    // ---- epilogue ----
    #pragma unroll
    for (int mt = 0; mt < 2; mt++) {
        int o0 = om + wm * 32 + mt * 16 + gq;
        int o1 = o0 + 8;
        float s0 = 0.f, bs0 = 0.f, s1 = 0.f, bs1 = 0.f, bi0 = 0.f, bi1 = 0.f;
        if (MODE == 2 || MODE == 3) {
            s0 = g[o0] * rsqrtf(vv[o0] + EPSV); bs0 = bb[o0] - mm[o0] * s0;
            s1 = g[o1] * rsqrtf(vv[o1] + EPSV); bs1 = bb[o1] - mm[o1] * s1;
        }
        if (MODE == 1) { bi0 = bias[o0]; bi1 = bias[o1]; }
        #pragma unroll
        for (int nt = 0; nt < 8; nt++) {
            int n = n0 + wn * 64 + nt * 8 + 2 * tq;
            size_t oi0 = ((size_t)b * O + o0) * HWSZ + n;
            size_t oi1 = ((size_t)b * O + o1) * HWSZ + n;
            float r0 = acc[mt][nt][0], r1 = acc[mt][nt][1];
            float r2 = acc[mt][nt][2], r3 = acc[mt][nt][3];
            if (MODE == 1) {
                float2 e0 = *(const float2*)&Res[oi0];
                float2 e1 = *(const float2*)&Res[oi1];
                r0 += e0.x + bi0; r1 += e0.y + bi0;
                r2 += e1.x + bi1; r3 += e1.y + bi1;
            }
            if (MODE == 2) {
                r0 = gelu_f(r0 * s0 + bs0); r1 = gelu_f(r1 * s0 + bs0);
                r2 = gelu_f(r2 * s1 + bs1); r3 = gelu_f(r3 * s1 + bs1);
            }
            if (MODE == 3) {
                float2 e0 = *(const float2*)&Res[oi0];
                float2 e1 = *(const float2*)&Res[oi1];
                r0 = e0.x + r0 * s0 + bs0; r1 = e0.y + r1 * s0 + bs0;
                r2 = e1.x + r2 * s1 + bs1; r3 = e1.y + r3 * s1 + bs1;
            }
            if (WF32) {
                float2 v0 = {r0, r1}, v1 = {r2, r3};
                *(float2*)&Out[oi0] = v0;
                *(float2*)&Out[oi1] = v1;
            }
            if (WF16) {
                __half2 hv0 = __floats2half2_rn(r0, r1);
                __half2 hv1 = __floats2half2_rn(r2, r3);
                *(__half2*)&Outh[oi0] = hv0;
                *(__half2*)&Outh[oi1] = hv1;
            }
        }
    }
}

// ---------------- window means (fp16 source): block per (b,h,d) ----------------
__global__ void wmean_k() {
    int bid = blockIdx.x;
    int d = bid & 31, h = (bid >> 5) & 7, b = bid >> 8;
    int tid = threadIdx.x;
    __shared__ float spq[256], spk[256];
    const __half* qpl = g_qkvh + ((size_t)b * 3 * CC + h * DH + d) * HWSZ;
    const __half* kpl = qpl + (size_t)CC * HWSZ;
    uint2 uq = ((const uint2*)qpl)[tid];
    uint2 uk = ((const uint2*)kpl)[tid];
    __half2 qa = *(__half2*)&uq.x, qb = *(__half2*)&uq.y;
    __half2 ka = *(__half2*)&uk.x, kb = *(__half2*)&uk.y;
    spq[tid] = __low2float(qa) + __high2float(qa) + __low2float(qb) + __high2float(qb);
    spk[tid] = __low2float(ka) + __high2float(ka) + __low2float(kb) + __high2float(kb);
    __syncthreads();
    if (tid < 64) {
        int wy = tid >> 3, wx = tid & 7;
        int base = wy * 32 + wx;
        float sq = spq[base] + spq[base + 8] + spq[base + 16] + spq[base + 24];
        float sk = spk[base] + spk[base + 8] + spk[base + 16] + spk[base + 24];
        size_t o = ((size_t)(b * 8 + h) * 64 + tid) * DH + d;
        g_qm[o] = sq * 0.0625f;
        g_km[o] = sk * 0.0625f;
    }
}

// ---------------- affinity + exact top-4 (2-way split) ----------------
__global__ void topk_k() {
    int bh = blockIdx.x >> 1;
    int half = blockIdx.x & 1;
    __shared__ float kt[32][65];
    __shared__ float qs[64][32];
    int tid = threadIdx.x, warp = tid >> 5, lane = tid & 31;
    for (int e = tid; e < 2048; e += 256) {
        int j = e >> 5, d = e & 31;
        kt[d][j] = g_km[(size_t)bh * 2048 + e];
        qs[j][d] = g_qm[(size_t)bh * 2048 + e];
    }
    __syncthreads();
    for (int ii = 0; ii < 4; ii++) {
        int i = half * 32 + warp * 4 + ii;
        float s0 = 0.f, s1 = 0.f;
        #pragma unroll
        for (int d = 0; d < 32; d++) {
            float q = qs[i][d];
            s0 += q * kt[d][lane];
            s1 += q * kt[d][lane + 32];
        }
        float v0 = s0, v1 = s1;
        #pragma unroll
        for (int t = 0; t < KTOP; t++) {
            float bvv; int bj;
            if (v0 >= v1) { bvv = v0; bj = lane; } else { bvv = v1; bj = lane + 32; }
            #pragma unroll
            for (int off = 16; off; off >>= 1) {
                float ov = __shfl_xor_sync(0xffffffffu, bvv, off);
                int   oj = __shfl_xor_sync(0xffffffffu, bj,  off);
                if (ov > bvv || (ov == bvv && oj < bj)) { bvv = ov; bj = oj; }
            }
            if (lane == 0) g_idx[((size_t)bh * 64 + i) * KTOP + t] = bj;
            if (bj == lane)      v0 = -INFINITY;
            if (bj == lane + 32) v1 = -INFINITY;
        }
    }
}

// ---------------- gathered window attention (HMMA, ldmatrix fragments) ----------------
// q stored [d][t] (stride 24), k/v stored [d][key] (stride 72)
#define QT_STR 24
#define KV_STR 72
#define SS_STR 68
#define P_STR  72
__global__ void __launch_bounds__(128) attn_k() {
    int bid = blockIdx.x;
    int n = bid & 63;
    int h = (bid >> 6) & 7;
    int b = bid >> 9;
    __shared__ __half qh[32 * QT_STR];
    __shared__ __half kh[32 * KV_STR];
    __shared__ __half vh[32 * KV_STR];
    __shared__ float  ss[16 * SS_STR];
    __shared__ __half ph[16 * P_STR];
    __shared__ int    widx[KTOP];
    int tid = threadIdx.x;
    if (tid < KTOP) widx[tid] = g_idx[(size_t)bid * KTOP + tid];
    __syncthreads();

    int wy = n >> 3, wx = n & 7;
    const __half* qbase = g_qkvh + ((size_t)b * 3 * CC + h * DH) * HWSZ;
    const __half* kbase = qbase + (size_t)CC * HWSZ;
    const __half* vbase = qbase + (size_t)2 * CC * HWSZ;

    // q: (d, tquad) -> 8B loads; 128 units
    {
        int d = tid >> 2, tj = tid & 3;
        int hw = ((wy * 4 + tj) << 5) + wx * 4;
        uint2 u = *(const uint2*)(qbase + (size_t)d * HWSZ + hw);
        *(uint2*)&qh[d * QT_STR + tj * 4] = u;
    }
    // k/v: (d, keyquad) -> 8B loads; 512 units each
    for (int e = tid; e < 512; e += 128) {
        int d = e >> 4, kq = e & 15;
        int j = widx[kq >> 2];
        int tj = kq & 3;
        int hw = (((j >> 3) * 4 + tj) << 5) + (j & 7) * 4;
        uint2 uk = *(const uint2*)(kbase + (size_t)d * HWSZ + hw);
        uint2 uv = *(const uint2*)(vbase + (size_t)d * HWSZ + hw);
        *(uint2*)&kh[d * KV_STR + kq * 4] = uk;
        *(uint2*)&vh[d * KV_STR + kq * 4] = uv;
    }
    __syncthreads();

    int warp = tid >> 5, lane = tid & 31;
    int gq = lane >> 2, tq = lane & 3;
    const float scale = 0.17677669529663687f;
    const uint32_t qsm = smem_u32(qh);
    const uint32_t ksm = smem_u32(kh);
    // Q ldmatrix.x4.trans lane offset: d = (lane&7) + ((lane>>4))*8, t-offset = ((lane>>3)&1)*8
    const uint32_t qloff = (uint32_t)((((lane & 7) + (lane >> 4) * 8) * QT_STR
                                      + ((lane >> 3) & 1) * 8) * 2);
    const uint32_t kloff = (uint32_t)(((lane & 15) * KV_STR + warp * 16) * 2);

    {
        float sc0[4] = {0.f, 0.f, 0.f, 0.f};
        float sc1[4] = {0.f, 0.f, 0.f, 0.f};
        #pragma unroll
        for (int ks = 0; ks < 2; ks++) {
            uint32_t ah[4];
            ldsm_x4_t(ah, qsm + qloff + (uint32_t)(ks * 16 * QT_STR * 2));
            uint32_t kb0, kb1;
            ldsm_x2_t(kb0, kb1, ksm + kloff + (uint32_t)(ks * 16 * KV_STR * 2));
            mma_f16(sc0, ah, kb0, kb1);
            uint32_t kb2, kb3;
            ldsm_x2_t(kb2, kb3, ksm + kloff + (uint32_t)(ks * 16 * KV_STR * 2) + 16);
            mma_f16(sc1, ah, kb2, kb3);
        }
        #pragma unroll
        for (int nt = 0; nt < 2; nt++) {
            const float* sc = nt ? sc1 : sc0;
            int c0 = warp * 16 + nt * 8 + 2 * tq;
            ss[gq * SS_STR + c0]           = sc[0] * scale;
            ss[gq * SS_STR + c0 + 1]       = sc[1] * scale;
            ss[(gq + 8) * SS_STR + c0]     = sc[2] * scale;
            ss[(gq + 8) * SS_STR + c0 + 1] = sc[3] * scale;
        }
    }
    __syncthreads();

    #pragma unroll
    for (int rr = 0; rr < 4; rr++) {
        int row = warp * 4 + rr;
        float s0 = ss[row * SS_STR + lane];
        float s1 = ss[row * SS_STR + lane + 32];
        float mx = fmaxf(s0, s1);
        #pragma unroll
        for (int off = 16; off; off >>= 1) mx = fmaxf(mx, __shfl_xor_sync(0xffffffffu, mx, off));
        float e0 = expf(s0 - mx), e1 = expf(s1 - mx);
        float sum = e0 + e1;
        #pragma unroll
        for (int off = 16; off; off >>= 1) sum += __shfl_xor_sync(0xffffffffu, sum, off);
        float inv = 1.0f / sum;
        ph[row * P_STR + lane]      = __float2half_rn(e0 * inv);
        ph[row * P_STR + lane + 32] = __float2half_rn(e1 * inv);
    }
    __syncthreads();

    {
        float f[4] = {0.f, 0.f, 0.f, 0.f};
        #pragma unroll
        for (int ks = 0; ks < 4; ks++) {
            int cb = ks * 16 + 2 * tq;
            uint32_t ah[4];
            ah[0] = *(const uint32_t*)&ph[gq * P_STR + cb];
            ah[1] = *(const uint32_t*)&ph[(gq + 8) * P_STR + cb];
            ah[2] = *(const uint32_t*)&ph[gq * P_STR + cb + 8];
            ah[3] = *(const uint32_t*)&ph[(gq + 8) * P_STR + cb + 8];
            int d = warp * 8 + gq;
            uint32_t bh0 = *(const uint32_t*)&vh[d * KV_STR + cb];
            uint32_t bh1 = *(const uint32_t*)&vh[d * KV_STR + cb + 8];
            mma_f16(f, ah, bh0, bh1);
        }
        __half* mbase = g_msgh + ((size_t)b * CC + h * DH) * HWSZ;
        int d0 = warp * 8 + 2 * tq;
        int hwA = ((wy * 4 + (gq >> 2)) << 5) + wx * 4 + (gq & 3);
        int hwB = ((wy * 4 + ((gq + 8) >> 2)) << 5) + wx * 4 + ((gq + 8) & 3);
        mbase[(size_t)d0 * HWSZ + hwA]       = __float2half_rn(f[0]);
        mbase[(size_t)(d0 + 1) * HWSZ + hwA] = __float2half_rn(f[1]);
        mbase[(size_t)d0 * HWSZ + hwB]       = __float2half_rn(f[2]);
        mbase[(size_t)(d0 + 1) * HWSZ + hwB] = __float2half_rn(f[3]);
    }
}

// ---------------- depthwise 3x3 + bn2 + gelu (fp16 in/out) ----------------
__global__ void dw_k(const float* __restrict__ dw,
                     const float* __restrict__ g2, const float* __restrict__ b2,
                     const float* __restrict__ m2, const float* __restrict__ v2) {
    int bc = blockIdx.x;
    int c = bc & (MRC - 1);
    __shared__ float t[1024];
    __shared__ float wsh[9];
    int tid = threadIdx.x;
    const __half* p = g_h1h + (size_t)bc * HWSZ;
    {
        uint2 u = ((const uint2*)p)[tid];
        __half2 a = *(__half2*)&u.x, b2h = *(__half2*)&u.y;
        float4 f;
        f.x = __low2float(a);  f.y = __high2float(a);
        f.z = __low2float(b2h); f.w = __high2float(b2h);
        ((float4*)t)[tid] = f;
    }
    if (tid < 9) wsh[tid] = dw[c * 9 + tid];
    __syncthreads();
    float s = g2[c] * rsqrtf(v2[c] + EPSV);
    float bs = b2[c] - m2[c] * s;
    __half* outp = g_h2h + (size_t)bc * HWSZ;
    int y = tid >> 3, x0 = (tid & 7) * 4;
    float rp[4];
    #pragma unroll
    for (int j = 0; j < 4; j++) {
        int x = x0 + j;
        float acc = 0.f;
        #pragma unroll
        for (int dy = -1; dy <= 1; dy++) {
            int yy = y + dy;
            if (yy < 0 || yy > 31) continue;
            #pragma unroll
            for (int dx = -1; dx <= 1; dx++) {
                int xx = x + dx;
                if (xx < 0 || xx > 31) continue;
                acc += wsh[(dy + 1) * 3 + (dx + 1)] * t[yy * 32 + xx];
            }
        }
        rp[j] = gelu_f(acc * s + bs);
    }
    __half2 o0 = __floats2half2_rn(rp[0], rp[1]);
    __half2 o1 = __floats2half2_rn(rp[2], rp[3]);
    uint2 u; u.x = *(uint32_t*)&o0; u.y = *(uint32_t*)&o1;
    ((uint2*)outp)[tid] = u;
}

// ---------------- launcher ----------------
extern "C" void kernel_launch(void* const* d_in, const int* in_sizes, int n_in,
                              void* d_out, int out_size) {
    const float* x      = (const float*)d_in[0];
    const float* bn0_g  = (const float*)d_in[1];
    const float* bn0_b  = (const float*)d_in[2];
    const float* bn0_m  = (const float*)d_in[3];
    const float* bn0_v  = (const float*)d_in[4];
    const float* w_qkv  = (const float*)d_in[5];
    const float* w_mrg  = (const float*)d_in[6];
    const float* b_mrg  = (const float*)d_in[7];
    const float* w1     = (const float*)d_in[8];
    const float* bn1_g  = (const float*)d_in[9];
    const float* bn1_b  = (const float*)d_in[10];
    const float* bn1_m  = (const float*)d_in[11];
    const float* bn1_v  = (const float*)d_in[12];
    const float* dw     = (const float*)d_in[13];
    const float* bn2_g  = (const float*)d_in[14];
    const float* bn2_b  = (const float*)d_in[15];
    const float* bn2_m  = (const float*)d_in[16];
    const float* bn2_v  = (const float*)d_in[17];
    const float* w2     = (const float*)d_in[18];
    const float* bn3_g  = (const float*)d_in[19];
    const float* bn3_b  = (const float*)d_in[20];
    const float* bn3_m  = (const float*)d_in[21];
    const float* bn3_v  = (const float*)d_in[22];

    float *x1;
    __half *wh, *wl, *h0h, *qkvh, *msgh, *x1h, *h1h, *h2h;
    cudaGetSymbolAddress((void**)&x1,   g_x1);
    cudaGetSymbolAddress((void**)&wh,   g_wh);
    cudaGetSymbolAddress((void**)&wl,   g_wl);
    cudaGetSymbolAddress((void**)&h0h,  g_h0h);
    cudaGetSymbolAddress((void**)&qkvh, g_qkvh);
    cudaGetSymbolAddress((void**)&msgh, g_msgh);
    cudaGetSymbolAddress((void**)&x1h,  g_x1h);
    cudaGetSymbolAddress((void**)&h1h,  g_h1h);
    cudaGetSymbolAddress((void**)&h2h,  g_h2h);

    cudaFuncSetAttribute((const void*)mgemm_k<0,2,0,1>, cudaFuncAttributeMaxDynamicSharedMemorySize, 87552);
    cudaFuncSetAttribute((const void*)mgemm_k<1,1,1,1>, cudaFuncAttributeMaxDynamicSharedMemorySize, 56832);
    cudaFuncSetAttribute((const void*)mgemm_k<2,1,0,1>, cudaFuncAttributeMaxDynamicSharedMemorySize, 56832);
    cudaFuncSetAttribute((const void*)mgemm_k<3,1,1,0>, cudaFuncAttributeMaxDynamicSharedMemorySize, 56832);

    // 0. pre-split weights to fp16
    wsplit_k<<<(WTOT + 255) / 256, 256>>>(w_qkv, w_mrg, w1, w2);

    // 1. h0 = gelu(bn0(x)) -> fp16
    bn0_gelu_k<<<(BB * CC * HWSZ / 4 + 255) / 256, 256>>>(x, bn0_g, bn0_b, bn0_m, bn0_v);

    // 2. qkv = w_qkv @ h0   (2-pass, fp16 output only)
    mgemm_k<0,2,0,1><<<dim3(768 / 128, 8, BB), 256, 87552>>>(
        wh + WOFF_QKV, wl, h0h, nullptr, qkvh, 768, 256,
        nullptr, nullptr, nullptr, nullptr, nullptr, nullptr);

    // 3. window means (fp16 source)
    wmean_k<<<BB * HEADS * DH, 256>>>();

    // 4. affinity + top-4 (2-way split)
    topk_k<<<BB * HEADS * 2, 256>>>();

    // 5. gathered attention (HMMA, ldmatrix fragments)
    attn_k<<<BB * HEADS * NWIN, 128>>>();

    // 6. x1 = x + w_merge @ msg + b_merge
    mgemm_k<1,1,1,1><<<dim3(CC / 128, 8, BB), 256, 56832>>>(
        wh + WOFF_MRG, nullptr, msgh, x1, x1h, CC, 256,
        x, b_mrg, nullptr, nullptr, nullptr, nullptr);

    // 7. h1 = gelu(bn1(w1 @ x1)) -> fp16
    mgemm_k<2,1,0,1><<<dim3(MRC / 128, 8, BB), 256, 56832>>>(
        wh + WOFF_W1, nullptr, x1h, nullptr, h1h, MRC, 256,
        nullptr, nullptr, bn1_g, bn1_b, bn1_m, bn1_v);

    // 8. h2 = gelu(bn2(dwconv3x3(h1))) -> fp16
    dw_k<<<BB * MRC, 256>>>(dw, bn2_g, bn2_b, bn2_m, bn2_v);

    // 9. out = x1 + bn3(w2 @ h2)
    mgemm_k<3,1,1,0><<<dim3(CC / 128, 8, BB), 256, 56832>>>(
        wh + WOFF_W2, nullptr, h2h, (float*)d_out, nullptr, CC, 1024,
        x1, nullptr, bn3_g, bn3_b, bn3_m, bn3_v);
}

// round 12
// speedup vs baseline: 1.9605x; 1.0182x over previous
#include <cuda_runtime.h>
#include <cuda_fp16.h>
#include <cstdint>
#include <math.h>

// ---------------- problem constants ----------------
#define BB   16
#define CC   256
#define HWSZ 1024
#define DH   32
#define HEADS 8
#define KTOP 4
#define MRC  1024
#define NWIN 64
#define EPSV 1e-5f

// pre-split weight offsets (halves)
#define WOFF_QKV 0
#define WOFF_MRG 196608
#define WOFF_W1  262144
#define WOFF_W2  524288
#define WTOT     786432

// ---------------- device scratch ----------------
__device__ float  g_qm  [BB * HEADS * NWIN * DH];
__device__ float  g_km  [BB * HEADS * NWIN * DH];
__device__ int    g_idx [BB * HEADS * NWIN * KTOP];
__device__ __half g_h0h [BB * CC  * HWSZ];
__device__ __half g_qkvh[BB * 3*CC * HWSZ];
__device__ __half g_msgh[BB * CC  * HWSZ];
__device__ __half g_x1h [BB * CC  * HWSZ];
__device__ __half g_h1h [BB * MRC * HWSZ];
__device__ __half g_h2h [BB * MRC * HWSZ];
__device__ __half g_wh  [WTOT];
__device__ __half g_wl  [196608];   // lo only for qkv

__device__ __forceinline__ float gelu_f(float x) {
    return 0.5f * x * (1.0f + erff(x * 0.7071067811865475f));
}

// ---------------- fp16 warp MMA + ldmatrix + cp.async ----------------
__device__ __forceinline__ void mma_f16(float* d, const uint32_t* a, uint32_t b0, uint32_t b1) {
    asm volatile(
        "mma.sync.aligned.m16n8k16.row.col.f32.f16.f16.f32 "
        "{%0,%1,%2,%3}, {%4,%5,%6,%7}, {%8,%9}, {%0,%1,%2,%3};"
        : "+f"(d[0]), "+f"(d[1]), "+f"(d[2]), "+f"(d[3])
        : "r"(a[0]), "r"(a[1]), "r"(a[2]), "r"(a[3]), "r"(b0), "r"(b1));
}
__device__ __forceinline__ void ldsm_x2_t(uint32_t& r0, uint32_t& r1, uint32_t addr) {
    asm volatile("ldmatrix.sync.aligned.m8n8.x2.trans.shared.b16 {%0,%1}, [%2];"
                 : "=r"(r0), "=r"(r1) : "r"(addr));
}
__device__ __forceinline__ void ldsm_x4(uint32_t* r, uint32_t addr) {
    asm volatile("ldmatrix.sync.aligned.m8n8.x4.shared.b16 {%0,%1,%2,%3}, [%4];"
                 : "=r"(r[0]), "=r"(r[1]), "=r"(r[2]), "=r"(r[3]) : "r"(addr));
}
__device__ __forceinline__ void ldsm_x4_t(uint32_t* r, uint32_t addr) {
    asm volatile("ldmatrix.sync.aligned.m8n8.x4.trans.shared.b16 {%0,%1,%2,%3}, [%4];"
                 : "=r"(r[0]), "=r"(r[1]), "=r"(r[2]), "=r"(r[3]) : "r"(addr));
}
__device__ __forceinline__ uint32_t smem_u32(const void* p) {
    uint32_t a;
    asm("{ .reg .u64 t; cvta.to.shared.u64 t, %1; cvt.u32.u64 %0, t; }" : "=r"(a) : "l"(p));
    return a;
}
__device__ __forceinline__ void cp16(uint32_t dst, const void* src) {
    asm volatile("cp.async.cg.shared.global [%0], [%1], 16;" :: "r"(dst), "l"(src) : "memory");
}
#define CP_COMMIT() asm volatile("cp.async.commit_group;" ::: "memory")
#define CP_WAIT(N)  asm volatile("cp.async.wait_group %0;" :: "n"(N) : "memory")
__device__ __forceinline__ void cvt_split(float x, __half& h, __half& l) {
    h = __float2half_rn(x);
    l = __float2half_rn(x - __half2float(h));
}

#define A_STR 136

// ---------------- weight pre-split ----------------
__global__ void wsplit_k(const float* __restrict__ wqkv, const float* __restrict__ wmrg,
                         const float* __restrict__ w1,   const float* __restrict__ w2) {
    int i = blockIdx.x * 256 + threadIdx.x;
    if (i >= WTOT) return;
    if (i < WOFF_MRG) {
        __half h, l; cvt_split(wqkv[i], h, l);
        g_wh[i] = h; g_wl[i] = l;
    } else if (i < WOFF_W1) {
        g_wh[i] = __float2half_rn(wmrg[i - WOFF_MRG]);
    } else if (i < WOFF_W2) {
        g_wh[i] = __float2half_rn(w1[i - WOFF_W1]);
    } else {
        g_wh[i] = __float2half_rn(w2[i - WOFF_W2]);
    }
}

// ---------------- h0 = gelu(bn0(x)) -> fp16 ----------------
__global__ void bn0_gelu_k(const float* __restrict__ x,
                           const float* __restrict__ g, const float* __restrict__ b,
                           const float* __restrict__ m, const float* __restrict__ v) {
    int i = blockIdx.x * 256 + threadIdx.x;
    if (i >= BB * CC * HWSZ / 4) return;
    int c = (i >> 8) & (CC - 1);
    float s = g[c] * rsqrtf(v[c] + EPSV);
    float sh = b[c] - m[c] * s;
    float4 xv = ((const float4*)x)[i];
    __half2 h0 = __floats2half2_rn(gelu_f(xv.x * s + sh), gelu_f(xv.y * s + sh));
    __half2 h1 = __floats2half2_rn(gelu_f(xv.z * s + sh), gelu_f(xv.w * s + sh));
    uint2 u; u.x = *(uint32_t*)&h0; u.y = *(uint32_t*)&h1;
    ((uint2*)g_h0h)[i] = u;
}

// ---------------- tensor-core fused GEMM (cp.async 3-stage, ldmatrix) ----------------
// PASSES: 1 = hiW*hiA; 2 = + loW*hiA (W exact, A rounded)
// MODE 0: plain; 1: Res32 + acc + bias; 2: gelu(bn(acc)); 5: ResH + bn(acc)
template<int MODE, int PASSES, int WF32, int WF16>
__global__ void __launch_bounds__(256, 2)
mgemm_k(const __half* __restrict__ Whg, const __half* __restrict__ Wlg,
        const __half* __restrict__ Ahg,
        float* __restrict__ Out, __half* __restrict__ Outh, int O, int Kd,
        const float* __restrict__ Res, const __half* __restrict__ ResH,
        const float* __restrict__ bias,
        const float* __restrict__ g,  const float* __restrict__ bb,
        const float* __restrict__ mm, const float* __restrict__ vv) {
    constexpr int WL_O = 10240;
    constexpr int AH_O = (PASSES >= 2) ? 20480 : 10240;
    constexpr int STG  = AH_O + 8704;

    extern __shared__ char smc[];
    const int tid = threadIdx.x, lane = tid & 31, warp = tid >> 5;
    const int b = blockIdx.z, om = blockIdx.x * 128, n0 = blockIdx.y * 128;
    const int wm = warp >> 1, wn = warp & 1;
    const int gq = lane >> 2, tq = lane & 3;
    const uint32_t smbase = smem_u32(smc);

    const __half* Abh = Ahg + (size_t)b * Kd * HWSZ + n0;

    float acc[2][8][4];
    #pragma unroll
    for (int mt = 0; mt < 2; mt++)
        #pragma unroll
        for (int nt = 0; nt < 8; nt++)
            #pragma unroll
            for (int r = 0; r < 4; r++) acc[mt][nt][r] = 0.f;

    const uint32_t aoff = (uint32_t)(((lane & 15) * A_STR + wn * 64) * 2);
    const uint32_t woff = (uint32_t)(((wm * 32 + (lane & 7) + ((lane >> 3) & 1) * 8) * 40
                                     + (lane >> 4) * 8) * 2);
    const int nch = Kd >> 5;

    auto issue = [&](int ch, int st) {
        int k0 = ch << 5;
        uint32_t stu = smbase + (uint32_t)st * STG;
        #pragma unroll
        for (int it = 0; it < 2; it++) {
            int e = tid + it * 256;
            int row = e >> 2, c4 = e & 3;
            cp16(stu + row * 80 + c4 * 16, Whg + (size_t)(om + row) * Kd + k0 + c4 * 8);
            if (PASSES >= 2)
                cp16(stu + WL_O + row * 80 + c4 * 16, Wlg + (size_t)(om + row) * Kd + k0 + c4 * 8);
        }
        #pragma unroll
        for (int it = 0; it < 2; it++) {
            int e = tid + it * 256;
            int row = e >> 4, col8 = (e & 15) * 8;
            cp16(stu + AH_O + (row * A_STR + col8) * 2, Abh + (size_t)(k0 + row) * HWSZ + col8);
        }
        CP_COMMIT();
    };

    issue(0, 0);
    issue(1, 1);

    int st = 0;
    for (int ch = 0; ch < nch; ch++) {
        if (ch + 1 < nch) { CP_WAIT(1); } else { CP_WAIT(0); }
        __syncthreads();
        if (ch + 2 < nch) {
            int st2 = st + 2; if (st2 >= 3) st2 -= 3;
            issue(ch + 2, st2);
        }

        uint32_t stu = smbase + (uint32_t)st * STG;

        #pragma unroll
        for (int ks = 0; ks < 2; ks++) {
            uint32_t afh[2][4], afl[2][4];
            #pragma unroll
            for (int mt = 0; mt < 2; mt++) {
                uint32_t wa = stu + woff + (uint32_t)(mt * 16 * 40 * 2 + ks * 32);
                ldsm_x4(afh[mt], wa);
                if (PASSES >= 2) ldsm_x4(afl[mt], wa + WL_O);
            }
            uint32_t abase_h = stu + AH_O + aoff + (uint32_t)ks * (16 * A_STR * 2);
            #pragma unroll
            for (int nt = 0; nt < 8; nt++) {
                uint32_t bh0, bh1;
                ldsm_x2_t(bh0, bh1, abase_h + nt * 16);
                #pragma unroll
                for (int mt = 0; mt < 2; mt++) {
                    mma_f16(acc[mt][nt], afh[mt], bh0, bh1);
                    if (PASSES >= 2) mma_f16(acc[mt][nt], afl[mt], bh0, bh1);
                }
            }
        }
        st = (st + 1 == 3) ? 0 : st + 1;
    }
    __syncthreads();

    // ---- epilogue ----
    #pragma unroll
    for (int mt = 0; mt < 2; mt++) {
        int o0 = om + wm * 32 + mt * 16 + gq;
        int o1 = o0 + 8;
        float s0 = 0.f, bs0 = 0.f, s1 = 0.f, bs1 = 0.f, bi0 = 0.f, bi1 = 0.f;
        if (MODE == 2 || MODE == 5) {
            s0 = g[o0] * rsqrtf(vv[o0] + EPSV); bs0 = bb[o0] - mm[o0] * s0;
            s1 = g[o1] * rsqrtf(vv[o1] + EPSV); bs1 = bb[o1] - mm[o1] * s1;
        }
        if (MODE == 1) { bi0 = bias[o0]; bi1 = bias[o1]; }
        #pragma unroll
        for (int nt = 0; nt < 8; nt++) {
            int n = n0 + wn * 64 + nt * 8 + 2 * tq;
            size_t oi0 = ((size_t)b * O + o0) * HWSZ + n;
            size_t oi1 = ((size_t)b * O + o1) * HWSZ + n;
            float r0 = acc[mt][nt][0], r1 = acc[mt][nt][1];
            float r2 = acc[mt][nt][2], r3 = acc[mt][nt][3];
            if (MODE == 1) {
                float2 e0 = *(const float2*)&Res[oi0];
                float2 e1 = *(const float2*)&Res[oi1];
                r0 += e0.x + bi0; r1 += e0.y + bi0;
                r2 += e1.x + bi1; r3 += e1.y + bi1;
            }
            if (MODE == 2) {
                r0 = gelu_f(r0 * s0 + bs0); r1 = gelu_f(r1 * s0 + bs0);
                r2 = gelu_f(r2 * s1 + bs1); r3 = gelu_f(r3 * s1 + bs1);
            }
            if (MODE == 5) {
                __half2 e0 = *(const __half2*)&ResH[oi0];
                __half2 e1 = *(const __half2*)&ResH[oi1];
                r0 = __low2float(e0) + r0 * s0 + bs0;
                r1 = __high2float(e0) + r1 * s0 + bs0;
                r2 = __low2float(e1) + r2 * s1 + bs1;
                r3 = __high2float(e1) + r3 * s1 + bs1;
            }
            if (WF32) {
                float2 v0 = {r0, r1}, v1 = {r2, r3};
                *(float2*)&Out[oi0] = v0;
                *(float2*)&Out[oi1] = v1;
            }
            if (WF16) {
                __half2 hv0 = __floats2half2_rn(r0, r1);
                __half2 hv1 = __floats2half2_rn(r2, r3);
                *(__half2*)&Outh[oi0] = hv0;
                *(__half2*)&Outh[oi1] = hv1;
            }
        }
    }
}

// ---------------- window means: block per (b,h,dpair) ----------------
__global__ void wmean_k() {
    int bid = blockIdx.x;             // b*128 + h*16 + dp
    int dp = bid & 15, h = (bid >> 4) & 7, b = bid >> 7;
    int d0 = dp * 2;
    int tid = threadIdx.x;
    __shared__ float spq[2][256], spk[2][256];
    const __half* qpl = g_qkvh + ((size_t)b * 3 * CC + h * DH + d0) * HWSZ;
    const __half* kpl = qpl + (size_t)CC * HWSZ;
    #pragma unroll
    for (int i = 0; i < 2; i++) {
        uint2 uq = ((const uint2*)(qpl + (size_t)i * HWSZ))[tid];
        uint2 uk = ((const uint2*)(kpl + (size_t)i * HWSZ))[tid];
        __half2 qa = *(__half2*)&uq.x, qb = *(__half2*)&uq.y;
        __half2 ka = *(__half2*)&uk.x, kb = *(__half2*)&uk.y;
        spq[i][tid] = __low2float(qa) + __high2float(qa) + __low2float(qb) + __high2float(qb);
        spk[i][tid] = __low2float(ka) + __high2float(ka) + __low2float(kb) + __high2float(kb);
    }
    __syncthreads();
    if (tid < 128) {
        int i = tid >> 6, w = tid & 63;
        int wy = w >> 3, wx = w & 7;
        int base = wy * 32 + wx;
        float sq = spq[i][base] + spq[i][base + 8] + spq[i][base + 16] + spq[i][base + 24];
        float sk = spk[i][base] + spk[i][base + 8] + spk[i][base + 16] + spk[i][base + 24];
        size_t o = ((size_t)(b * 8 + h) * 64 + w) * DH + d0 + i;
        g_qm[o] = sq * 0.0625f;
        g_km[o] = sk * 0.0625f;
    }
}

// ---------------- affinity + exact top-4 (2-way split) ----------------
__global__ void topk_k() {
    int bh = blockIdx.x >> 1;
    int half = blockIdx.x & 1;
    __shared__ float kt[32][65];
    __shared__ float qs[64][32];
    int tid = threadIdx.x, warp = tid >> 5, lane = tid & 31;
    for (int e = tid; e < 2048; e += 256) {
        int j = e >> 5, d = e & 31;
        kt[d][j] = g_km[(size_t)bh * 2048 + e];
        qs[j][d] = g_qm[(size_t)bh * 2048 + e];
    }
    __syncthreads();
    for (int ii = 0; ii < 4; ii++) {
        int i = half * 32 + warp * 4 + ii;
        float s0 = 0.f, s1 = 0.f;
        #pragma unroll
        for (int d = 0; d < 32; d++) {
            float q = qs[i][d];
            s0 += q * kt[d][lane];
            s1 += q * kt[d][lane + 32];
        }
        float v0 = s0, v1 = s1;
        #pragma unroll
        for (int t = 0; t < KTOP; t++) {
            float bvv; int bj;
            if (v0 >= v1) { bvv = v0; bj = lane; } else { bvv = v1; bj = lane + 32; }
            #pragma unroll
            for (int off = 16; off; off >>= 1) {
                float ov = __shfl_xor_sync(0xffffffffu, bvv, off);
                int   oj = __shfl_xor_sync(0xffffffffu, bj,  off);
                if (ov > bvv || (ov == bvv && oj < bj)) { bvv = ov; bj = oj; }
            }
            if (lane == 0) g_idx[((size_t)bh * 64 + i) * KTOP + t] = bj;
            if (bj == lane)      v0 = -INFINITY;
            if (bj == lane + 32) v1 = -INFINITY;
        }
    }
}

// ---------------- gathered window attention (HMMA, ldmatrix fragments) ----------------
#define QT_STR 24
#define KV_STR 72
#define SS_STR 68
#define P_STR  72
__global__ void __launch_bounds__(128) attn_k() {
    int bid = blockIdx.x;
    int n = bid & 63;
    int h = (bid >> 6) & 7;
    int b = bid >> 9;
    __shared__ __half qh[32 * QT_STR];
    __shared__ __half kh[32 * KV_STR];
    __shared__ __half vh[32 * KV_STR];
    __shared__ float  ss[16 * SS_STR];
    __shared__ __half ph[16 * P_STR];
    __shared__ int    widx[KTOP];
    int tid = threadIdx.x;
    if (tid < KTOP) widx[tid] = g_idx[(size_t)bid * KTOP + tid];
    __syncthreads();

    int wy = n >> 3, wx = n & 7;
    const __half* qbase = g_qkvh + ((size_t)b * 3 * CC + h * DH) * HWSZ;
    const __half* kbase = qbase + (size_t)CC * HWSZ;
    const __half* vbase = qbase + (size_t)2 * CC * HWSZ;

    {
        int d = tid >> 2, tj = tid & 3;
        int hw = ((wy * 4 + tj) << 5) + wx * 4;
        uint2 u = *(const uint2*)(qbase + (size_t)d * HWSZ + hw);
        *(uint2*)&qh[d * QT_STR + tj * 4] = u;
    }
    for (int e = tid; e < 512; e += 128) {
        int d = e >> 4, kq = e & 15;
        int j = widx[kq >> 2];
        int tj = kq & 3;
        int hw = (((j >> 3) * 4 + tj) << 5) + (j & 7) * 4;
        uint2 uk = *(const uint2*)(kbase + (size_t)d * HWSZ + hw);
        uint2 uv = *(const uint2*)(vbase + (size_t)d * HWSZ + hw);
        *(uint2*)&kh[d * KV_STR + kq * 4] = uk;
        *(uint2*)&vh[d * KV_STR + kq * 4] = uv;
    }
    __syncthreads();

    int warp = tid >> 5, lane = tid & 31;
    int gq = lane >> 2, tq = lane & 3;
    const float scale = 0.17677669529663687f;
    const uint32_t qsm = smem_u32(qh);
    const uint32_t ksm = smem_u32(kh);
    const uint32_t qloff = (uint32_t)((((lane & 7) + (lane >> 4) * 8) * QT_STR
                                      + ((lane >> 3) & 1) * 8) * 2);
    const uint32_t kloff = (uint32_t)(((lane & 15) * KV_STR + warp * 16) * 2);

    {
        float sc0[4] = {0.f, 0.f, 0.f, 0.f};
        float sc1[4] = {0.f, 0.f, 0.f, 0.f};
        #pragma unroll
        for (int ks = 0; ks < 2; ks++) {
            uint32_t ah[4];
            ldsm_x4_t(ah, qsm + qloff + (uint32_t)(ks * 16 * QT_STR * 2));
            uint32_t kb0, kb1;
            ldsm_x2_t(kb0, kb1, ksm + kloff + (uint32_t)(ks * 16 * KV_STR * 2));
            mma_f16(sc0, ah, kb0, kb1);
            uint32_t kb2, kb3;
            ldsm_x2_t(kb2, kb3, ksm + kloff + (uint32_t)(ks * 16 * KV_STR * 2) + 16);
            mma_f16(sc1, ah, kb2, kb3);
        }
        #pragma unroll
        for (int nt = 0; nt < 2; nt++) {
            const float* sc = nt ? sc1 : sc0;
            int c0 = warp * 16 + nt * 8 + 2 * tq;
            ss[gq * SS_STR + c0]           = sc[0] * scale;
            ss[gq * SS_STR + c0 + 1]       = sc[1] * scale;
            ss[(gq + 8) * SS_STR + c0]     = sc[2] * scale;
            ss[(gq + 8) * SS_STR + c0 + 1] = sc[3] * scale;
        }
    }
    __syncthreads();

    #pragma unroll
    for (int rr = 0; rr < 4; rr++) {
        int row = warp * 4 + rr;
        float s0 = ss[row * SS_STR + lane];
        float s1 = ss[row * SS_STR + lane + 32];
        float mx = fmaxf(s0, s1);
        #pragma unroll
        for (int off = 16; off; off >>= 1) mx = fmaxf(mx, __shfl_xor_sync(0xffffffffu, mx, off));
        float e0 = expf(s0 - mx), e1 = expf(s1 - mx);
        float sum = e0 + e1;
        #pragma unroll
        for (int off = 16; off; off >>= 1) sum += __shfl_xor_sync(0xffffffffu, sum, off);
        float inv = 1.0f / sum;
        ph[row * P_STR + lane]      = __float2half_rn(e0 * inv);
        ph[row * P_STR + lane + 32] = __float2half_rn(e1 * inv);
    }
    __syncthreads();

    {
        float f[4] = {0.f, 0.f, 0.f, 0.f};
        #pragma unroll
        for (int ks = 0; ks < 4; ks++) {
            int cb = ks * 16 + 2 * tq;
            uint32_t ah[4];
            ah[0] = *(const uint32_t*)&ph[gq * P_STR + cb];
            ah[1] = *(const uint32_t*)&ph[(gq + 8) * P_STR + cb];
            ah[2] = *(const uint32_t*)&ph[gq * P_STR + cb + 8];
            ah[3] = *(const uint32_t*)&ph[(gq + 8) * P_STR + cb + 8];
            int d = warp * 8 + gq;
            uint32_t bh0 = *(const uint32_t*)&vh[d * KV_STR + cb];
            uint32_t bh1 = *(const uint32_t*)&vh[d * KV_STR + cb + 8];
            mma_f16(f, ah, bh0, bh1);
        }
        __half* mbase = g_msgh + ((size_t)b * CC + h * DH) * HWSZ;
        int d0 = warp * 8 + 2 * tq;
        int hwA = ((wy * 4 + (gq >> 2)) << 5) + wx * 4 + (gq & 3);
        int hwB = ((wy * 4 + ((gq + 8) >> 2)) << 5) + wx * 4 + ((gq + 8) & 3);
        mbase[(size_t)d0 * HWSZ + hwA]       = __float2half_rn(f[0]);
        mbase[(size_t)(d0 + 1) * HWSZ + hwA] = __float2half_rn(f[1]);
        mbase[(size_t)d0 * HWSZ + hwB]       = __float2half_rn(f[2]);
        mbase[(size_t)(d0 + 1) * HWSZ + hwB] = __float2half_rn(f[3]);
    }
}

// ---------------- depthwise 3x3 + bn2 + gelu (fp16 in/out) ----------------
__global__ void dw_k(const float* __restrict__ dw,
                     const float* __restrict__ g2, const float* __restrict__ b2,
                     const float* __restrict__ m2, const float* __restrict__ v2) {
    int bc = blockIdx.x;
    int c = bc & (MRC - 1);
    __shared__ float t[1024];
    __shared__ float wsh[9];
    int tid = threadIdx.x;
    const __half* p = g_h1h + (size_t)bc * HWSZ;
    {
        uint2 u = ((const uint2*)p)[tid];
        __half2 a = *(__half2*)&u.x, b2h = *(__half2*)&u.y;
        float4 f;
        f.x = __low2float(a);  f.y = __high2float(a);
        f.z = __low2float(b2h); f.w = __high2float(b2h);
        ((float4*)t)[tid] = f;
    }
    if (tid < 9) wsh[tid] = dw[c * 9 + tid];
    __syncthreads();
    float s = g2[c] * rsqrtf(v2[c] + EPSV);
    float bs = b2[c] - m2[c] * s;
    __half* outp = g_h2h + (size_t)bc * HWSZ;
    int y = tid >> 3, x0 = (tid & 7) * 4;
    float rp[4];
    #pragma unroll
    for (int j = 0; j < 4; j++) {
        int x = x0 + j;
        float acc = 0.f;
        #pragma unroll
        for (int dy = -1; dy <= 1; dy++) {
            int yy = y + dy;
            if (yy < 0 || yy > 31) continue;
            #pragma unroll
            for (int dx = -1; dx <= 1; dx++) {
                int xx = x + dx;
                if (xx < 0 || xx > 31) continue;
                acc += wsh[(dy + 1) * 3 + (dx + 1)] * t[yy * 32 + xx];
            }
        }
        rp[j] = gelu_f(acc * s + bs);
    }
    __half2 o0 = __floats2half2_rn(rp[0], rp[1]);
    __half2 o1 = __floats2half2_rn(rp[2], rp[3]);
    uint2 u; u.x = *(uint32_t*)&o0; u.y = *(uint32_t*)&o1;
    ((uint2*)outp)[tid] = u;
}

// ---------------- launcher ----------------
extern "C" void kernel_launch(void* const* d_in, const int* in_sizes, int n_in,
                              void* d_out, int out_size) {
    const float* x      = (const float*)d_in[0];
    const float* bn0_g  = (const float*)d_in[1];
    const float* bn0_b  = (const float*)d_in[2];
    const float* bn0_m  = (const float*)d_in[3];
    const float* bn0_v  = (const float*)d_in[4];
    const float* w_qkv  = (const float*)d_in[5];
    const float* w_mrg  = (const float*)d_in[6];
    const float* b_mrg  = (const float*)d_in[7];
    const float* w1     = (const float*)d_in[8];
    const float* bn1_g  = (const float*)d_in[9];
    const float* bn1_b  = (const float*)d_in[10];
    const float* bn1_m  = (const float*)d_in[11];
    const float* bn1_v  = (const float*)d_in[12];
    const float* dw     = (const float*)d_in[13];
    const float* bn2_g  = (const float*)d_in[14];
    const float* bn2_b  = (const float*)d_in[15];
    const float* bn2_m  = (const float*)d_in[16];
    const float* bn2_v  = (const float*)d_in[17];
    const float* w2     = (const float*)d_in[18];
    const float* bn3_g  = (const float*)d_in[19];
    const float* bn3_b  = (const float*)d_in[20];
    const float* bn3_m  = (const float*)d_in[21];
    const float* bn3_v  = (const float*)d_in[22];

    __half *wh, *wl, *h0h, *qkvh, *msgh, *x1h, *h1h, *h2h;
    cudaGetSymbolAddress((void**)&wh,   g_wh);
    cudaGetSymbolAddress((void**)&wl,   g_wl);
    cudaGetSymbolAddress((void**)&h0h,  g_h0h);
    cudaGetSymbolAddress((void**)&qkvh, g_qkvh);
    cudaGetSymbolAddress((void**)&msgh, g_msgh);
    cudaGetSymbolAddress((void**)&x1h,  g_x1h);
    cudaGetSymbolAddress((void**)&h1h,  g_h1h);
    cudaGetSymbolAddress((void**)&h2h,  g_h2h);

    cudaFuncSetAttribute((const void*)mgemm_k<0,2,0,1>, cudaFuncAttributeMaxDynamicSharedMemorySize, 87552);
    cudaFuncSetAttribute((const void*)mgemm_k<1,1,0,1>, cudaFuncAttributeMaxDynamicSharedMemorySize, 56832);
    cudaFuncSetAttribute((const void*)mgemm_k<2,1,0,1>, cudaFuncAttributeMaxDynamicSharedMemorySize, 56832);
    cudaFuncSetAttribute((const void*)mgemm_k<5,1,1,0>, cudaFuncAttributeMaxDynamicSharedMemorySize, 56832);

    // 0. pre-split weights to fp16
    wsplit_k<<<(WTOT + 255) / 256, 256>>>(w_qkv, w_mrg, w1, w2);

    // 1. h0 = gelu(bn0(x)) -> fp16
    bn0_gelu_k<<<(BB * CC * HWSZ / 4 + 255) / 256, 256>>>(x, bn0_g, bn0_b, bn0_m, bn0_v);

    // 2. qkv = w_qkv @ h0   (2-pass, fp16 output only)
    mgemm_k<0,2,0,1><<<dim3(768 / 128, 8, BB), 256, 87552>>>(
        wh + WOFF_QKV, wl, h0h, nullptr, qkvh, 768, 256,
        nullptr, nullptr, nullptr, nullptr, nullptr, nullptr, nullptr);

    // 3. window means (2 d per block)
    wmean_k<<<BB * HEADS * DH / 2, 256>>>();

    // 4. affinity + top-4 (2-way split)
    topk_k<<<BB * HEADS * 2, 256>>>();

    // 5. gathered attention (HMMA, ldmatrix fragments)
    attn_k<<<BB * HEADS * NWIN, 128>>>();

    // 6. x1h = fp16(x + w_merge @ msg + b_merge)   (fp16 output only)
    mgemm_k<1,1,0,1><<<dim3(CC / 128, 8, BB), 256, 56832>>>(
        wh + WOFF_MRG, nullptr, msgh, nullptr, x1h, CC, 256,
        x, nullptr, b_mrg, nullptr, nullptr, nullptr, nullptr);

    // 7. h1 = gelu(bn1(w1 @ x1h)) -> fp16
    mgemm_k<2,1,0,1><<<dim3(MRC / 128, 8, BB), 256, 56832>>>(
        wh + WOFF_W1, nullptr, x1h, nullptr, h1h, MRC, 256,
        nullptr, nullptr, nullptr, bn1_g, bn1_b, bn1_m, bn1_v);

    // 8. h2 = gelu(bn2(dwconv3x3(h1))) -> fp16
    dw_k<<<BB * MRC, 256>>>(dw, bn2_g, bn2_b, bn2_m, bn2_v);

    // 9. out = x1h + bn3(w2 @ h2)   (fp16 residual, fp32 output)
    mgemm_k<5,1,1,0><<<dim3(CC / 128, 8, BB), 256, 56832>>>(
        wh + WOFF_W2, nullptr, h2h, (float*)d_out, nullptr, CC, 1024,
        nullptr, x1h, nullptr, bn3_g, bn3_b, bn3_m, bn3_v);
}

// round 13
// speedup vs baseline: 2.0051x; 1.0228x over previous
#include <cuda_runtime.h>
#include <cuda_fp16.h>
#include <cstdint>
#include <math.h>

// ---------------- problem constants ----------------
#define BB   16
#define CC   256
#define HWSZ 1024
#define DH   32
#define HEADS 8
#define KTOP 4
#define MRC  1024
#define NWIN 64
#define EPSV 1e-5f

// pre-split weight offsets (halves)
#define WOFF_QKV 0
#define WOFF_MRG 196608
#define WOFF_W1  262144
#define WOFF_W2  524288
#define WTOT     786432

// ---------------- device scratch ----------------
__device__ float  g_qm  [BB * HEADS * NWIN * DH];
__device__ float  g_km  [BB * HEADS * NWIN * DH];
__device__ int    g_idx [BB * HEADS * NWIN * KTOP];
__device__ __half g_h0h [BB * CC  * HWSZ];
__device__ __half g_qkvh[BB * 3*CC * HWSZ];
__device__ __half g_msgh[BB * CC  * HWSZ];
__device__ __half g_x1h [BB * CC  * HWSZ];
__device__ __half g_h1h [BB * MRC * HWSZ];
__device__ __half g_h2h [BB * MRC * HWSZ];
__device__ __half g_wh  [WTOT];
__device__ __half g_wl  [196608];   // lo only for qkv

__device__ __forceinline__ float gelu_f(float x) {
    return 0.5f * x * (1.0f + erff(x * 0.7071067811865475f));
}

// ---------------- fp16 warp MMA + ldmatrix + cp.async ----------------
__device__ __forceinline__ void mma_f16(float* d, const uint32_t* a, uint32_t b0, uint32_t b1) {
    asm volatile(
        "mma.sync.aligned.m16n8k16.row.col.f32.f16.f16.f32 "
        "{%0,%1,%2,%3}, {%4,%5,%6,%7}, {%8,%9}, {%0,%1,%2,%3};"
        : "+f"(d[0]), "+f"(d[1]), "+f"(d[2]), "+f"(d[3])
        : "r"(a[0]), "r"(a[1]), "r"(a[2]), "r"(a[3]), "r"(b0), "r"(b1));
}
__device__ __forceinline__ void ldsm_x2_t(uint32_t& r0, uint32_t& r1, uint32_t addr) {
    asm volatile("ldmatrix.sync.aligned.m8n8.x2.trans.shared.b16 {%0,%1}, [%2];"
                 : "=r"(r0), "=r"(r1) : "r"(addr));
}
__device__ __forceinline__ void ldsm_x4(uint32_t* r, uint32_t addr) {
    asm volatile("ldmatrix.sync.aligned.m8n8.x4.shared.b16 {%0,%1,%2,%3}, [%4];"
                 : "=r"(r[0]), "=r"(r[1]), "=r"(r[2]), "=r"(r[3]) : "r"(addr));
}
__device__ __forceinline__ void ldsm_x4_t(uint32_t* r, uint32_t addr) {
    asm volatile("ldmatrix.sync.aligned.m8n8.x4.trans.shared.b16 {%0,%1,%2,%3}, [%4];"
                 : "=r"(r[0]), "=r"(r[1]), "=r"(r[2]), "=r"(r[3]) : "r"(addr));
}
__device__ __forceinline__ uint32_t smem_u32(const void* p) {
    uint32_t a;
    asm("{ .reg .u64 t; cvta.to.shared.u64 t, %1; cvt.u32.u64 %0, t; }" : "=r"(a) : "l"(p));
    return a;
}
__device__ __forceinline__ void cp16(uint32_t dst, const void* src) {
    asm volatile("cp.async.cg.shared.global [%0], [%1], 16;" :: "r"(dst), "l"(src) : "memory");
}
#define CP_COMMIT() asm volatile("cp.async.commit_group;" ::: "memory")
#define CP_WAIT(N)  asm volatile("cp.async.wait_group %0;" :: "n"(N) : "memory")
__device__ __forceinline__ void cvt_split(float x, __half& h, __half& l) {
    h = __float2half_rn(x);
    l = __float2half_rn(x - __half2float(h));
}

#define A_STR 136

// ---------------- weight pre-split ----------------
__global__ void wsplit_k(const float* __restrict__ wqkv, const float* __restrict__ wmrg,
                         const float* __restrict__ w1,   const float* __restrict__ w2) {
    int i = blockIdx.x * 256 + threadIdx.x;
    if (i >= WTOT) return;
    if (i < WOFF_MRG) {
        __half h, l; cvt_split(wqkv[i], h, l);
        g_wh[i] = h; g_wl[i] = l;
    } else if (i < WOFF_W1) {
        g_wh[i] = __float2half_rn(wmrg[i - WOFF_MRG]);
    } else if (i < WOFF_W2) {
        g_wh[i] = __float2half_rn(w1[i - WOFF_W1]);
    } else {
        g_wh[i] = __float2half_rn(w2[i - WOFF_W2]);
    }
}

// ---------------- h0 = gelu(bn0(x)) -> fp16 ----------------
__global__ void bn0_gelu_k(const float* __restrict__ x,
                           const float* __restrict__ g, const float* __restrict__ b,
                           const float* __restrict__ m, const float* __restrict__ v) {
    int i = blockIdx.x * 256 + threadIdx.x;
    if (i >= BB * CC * HWSZ / 4) return;
    int c = (i >> 8) & (CC - 1);
    float s = g[c] * rsqrtf(v[c] + EPSV);
    float sh = b[c] - m[c] * s;
    float4 xv = ((const float4*)x)[i];
    __half2 h0 = __floats2half2_rn(gelu_f(xv.x * s + sh), gelu_f(xv.y * s + sh));
    __half2 h1 = __floats2half2_rn(gelu_f(xv.z * s + sh), gelu_f(xv.w * s + sh));
    uint2 u; u.x = *(uint32_t*)&h0; u.y = *(uint32_t*)&h1;
    ((uint2*)g_h0h)[i] = u;
}

// ---------------- tensor-core fused GEMM (cp.async 3-stage, ldmatrix, KC-chunk) ----------------
// PASSES: 1 = hiW*hiA; 2 = + loW*hiA (W exact, A rounded)
// MODE 0: plain; 1: Res32 + acc + bias; 2: gelu(bn(acc)); 5: ResH + bn(acc)
template<int MODE, int PASSES, int WF32, int WF16, int KC>
__global__ void __launch_bounds__(256, 2)
mgemm_k(const __half* __restrict__ Whg, const __half* __restrict__ Wlg,
        const __half* __restrict__ Ahg,
        float* __restrict__ Out, __half* __restrict__ Outh, int O, int Kd,
        const float* __restrict__ Res, const __half* __restrict__ ResH,
        const float* __restrict__ bias,
        const float* __restrict__ g,  const float* __restrict__ bb,
        const float* __restrict__ mm, const float* __restrict__ vv) {
    constexpr int W_STR = (KC == 64) ? 72 : 40;
    constexpr int WH_B  = 128 * W_STR * 2;          // W hi bytes
    constexpr int WL_O  = WH_B;                     // lo plane offset (PASSES==2 only)
    constexpr int AH_O  = (PASSES >= 2) ? 2 * WH_B : WH_B;
    constexpr int STG   = AH_O + KC * A_STR * 2;
    constexpr int KSN   = KC / 16;                  // ks iterations
    constexpr int WCP   = KC / 16;                  // W cp16 per thread
    constexpr int ACP   = KC / 16;                  // A cp16 per thread
    constexpr int WROWDIV = KC / 8;                 // cp16 chunks per W row

    extern __shared__ char smc[];
    const int tid = threadIdx.x, lane = tid & 31, warp = tid >> 5;
    const int b = blockIdx.z, om = blockIdx.x * 128, n0 = blockIdx.y * 128;
    const int wm = warp >> 1, wn = warp & 1;
    const int gq = lane >> 2, tq = lane & 3;
    const uint32_t smbase = smem_u32(smc);

    const __half* Abh = Ahg + (size_t)b * Kd * HWSZ + n0;

    float acc[2][8][4];
    #pragma unroll
    for (int mt = 0; mt < 2; mt++)
        #pragma unroll
        for (int nt = 0; nt < 8; nt++)
            #pragma unroll
            for (int r = 0; r < 4; r++) acc[mt][nt][r] = 0.f;

    const uint32_t aoff = (uint32_t)(((lane & 15) * A_STR + wn * 64) * 2);
    const uint32_t woff = (uint32_t)(((wm * 32 + (lane & 7) + ((lane >> 3) & 1) * 8) * W_STR
                                     + (lane >> 4) * 8) * 2);
    const int nch = Kd / KC;

    auto issue = [&](int ch, int st) {
        int k0 = ch * KC;
        uint32_t stu = smbase + (uint32_t)st * STG;
        #pragma unroll
        for (int it = 0; it < WCP; it++) {
            int e = tid + it * 256;
            int row = e / WROWDIV, cc = e % WROWDIV;
            cp16(stu + row * (W_STR * 2) + cc * 16,
                 Whg + (size_t)(om + row) * Kd + k0 + cc * 8);
            if (PASSES >= 2)
                cp16(stu + WL_O + row * (W_STR * 2) + cc * 16,
                     Wlg + (size_t)(om + row) * Kd + k0 + cc * 8);
        }
        #pragma unroll
        for (int it = 0; it < ACP; it++) {
            int e = tid + it * 256;
            int row = e >> 4, col8 = (e & 15) * 8;
            cp16(stu + AH_O + (row * A_STR + col8) * 2, Abh + (size_t)(k0 + row) * HWSZ + col8);
        }
        CP_COMMIT();
    };

    issue(0, 0);
    issue(1, 1);

    int st = 0;
    for (int ch = 0; ch < nch; ch++) {
        if (ch + 1 < nch) { CP_WAIT(1); } else { CP_WAIT(0); }
        __syncthreads();
        if (ch + 2 < nch) {
            int st2 = st + 2; if (st2 >= 3) st2 -= 3;
            issue(ch + 2, st2);
        }

        uint32_t stu = smbase + (uint32_t)st * STG;

        #pragma unroll
        for (int ks = 0; ks < KSN; ks++) {
            uint32_t afh[2][4], afl[2][4];
            #pragma unroll
            for (int mt = 0; mt < 2; mt++) {
                uint32_t wa = stu + woff + (uint32_t)(mt * 16 * W_STR * 2 + ks * 32);
                ldsm_x4(afh[mt], wa);
                if (PASSES >= 2) ldsm_x4(afl[mt], wa + WL_O);
            }
            uint32_t abase_h = stu + AH_O + aoff + (uint32_t)ks * (16 * A_STR * 2);
            #pragma unroll
            for (int nt = 0; nt < 8; nt++) {
                uint32_t bh0, bh1;
                ldsm_x2_t(bh0, bh1, abase_h + nt * 16);
                #pragma unroll
                for (int mt = 0; mt < 2; mt++) {
                    mma_f16(acc[mt][nt], afh[mt], bh0, bh1);
                    if (PASSES >= 2) mma_f16(acc[mt][nt], afl[mt], bh0, bh1);
                }
            }
        }
        st = (st + 1 == 3) ? 0 : st + 1;
    }
    __syncthreads();

    // ---- epilogue ----
    #pragma unroll
    for (int mt = 0; mt < 2; mt++) {
        int o0 = om + wm * 32 + mt * 16 + gq;
        int o1 = o0 + 8;
        float s0 = 0.f, bs0 = 0.f, s1 = 0.f, bs1 = 0.f, bi0 = 0.f, bi1 = 0.f;
        if (MODE == 2 || MODE == 5) {
            s0 = g[o0] * rsqrtf(vv[o0] + EPSV); bs0 = bb[o0] - mm[o0] * s0;
            s1 = g[o1] * rsqrtf(vv[o1] + EPSV); bs1 = bb[o1] - mm[o1] * s1;
        }
        if (MODE == 1) { bi0 = bias[o0]; bi1 = bias[o1]; }
        #pragma unroll
        for (int nt = 0; nt < 8; nt++) {
            int n = n0 + wn * 64 + nt * 8 + 2 * tq;
            size_t oi0 = ((size_t)b * O + o0) * HWSZ + n;
            size_t oi1 = ((size_t)b * O + o1) * HWSZ + n;
            float r0 = acc[mt][nt][0], r1 = acc[mt][nt][1];
            float r2 = acc[mt][nt][2], r3 = acc[mt][nt][3];
            if (MODE == 1) {
                float2 e0 = *(const float2*)&Res[oi0];
                float2 e1 = *(const float2*)&Res[oi1];
                r0 += e0.x + bi0; r1 += e0.y + bi0;
                r2 += e1.x + bi1; r3 += e1.y + bi1;
            }
            if (MODE == 2) {
                r0 = gelu_f(r0 * s0 + bs0); r1 = gelu_f(r1 * s0 + bs0);
                r2 = gelu_f(r2 * s1 + bs1); r3 = gelu_f(r3 * s1 + bs1);
            }
            if (MODE == 5) {
                __half2 e0 = *(const __half2*)&ResH[oi0];
                __half2 e1 = *(const __half2*)&ResH[oi1];
                r0 = __low2float(e0) + r0 * s0 + bs0;
                r1 = __high2float(e0) + r1 * s0 + bs0;
                r2 = __low2float(e1) + r2 * s1 + bs1;
                r3 = __high2float(e1) + r3 * s1 + bs1;
            }
            if (WF32) {
                float2 v0 = {r0, r1}, v1 = {r2, r3};
                *(float2*)&Out[oi0] = v0;
                *(float2*)&Out[oi1] = v1;
            }
            if (WF16) {
                __half2 hv0 = __floats2half2_rn(r0, r1);
                __half2 hv1 = __floats2half2_rn(r2, r3);
                *(__half2*)&Outh[oi0] = hv0;
                *(__half2*)&Outh[oi1] = hv1;
            }
        }
    }
}

// ---------------- window means: block per (b,h,dpair) ----------------
__global__ void wmean_k() {
    int bid = blockIdx.x;
    int dp = bid & 15, h = (bid >> 4) & 7, b = bid >> 7;
    int d0 = dp * 2;
    int tid = threadIdx.x;
    __shared__ float spq[2][256], spk[2][256];
    const __half* qpl = g_qkvh + ((size_t)b * 3 * CC + h * DH + d0) * HWSZ;
    const __half* kpl = qpl + (size_t)CC * HWSZ;
    #pragma unroll
    for (int i = 0; i < 2; i++) {
        uint2 uq = ((const uint2*)(qpl + (size_t)i * HWSZ))[tid];
        uint2 uk = ((const uint2*)(kpl + (size_t)i * HWSZ))[tid];
        __half2 qa = *(__half2*)&uq.x, qb = *(__half2*)&uq.y;
        __half2 ka = *(__half2*)&uk.x, kb = *(__half2*)&uk.y;
        spq[i][tid] = __low2float(qa) + __high2float(qa) + __low2float(qb) + __high2float(qb);
        spk[i][tid] = __low2float(ka) + __high2float(ka) + __low2float(kb) + __high2float(kb);
    }
    __syncthreads();
    if (tid < 128) {
        int i = tid >> 6, w = tid & 63;
        int wy = w >> 3, wx = w & 7;
        int base = wy * 32 + wx;
        float sq = spq[i][base] + spq[i][base + 8] + spq[i][base + 16] + spq[i][base + 24];
        float sk = spk[i][base] + spk[i][base + 8] + spk[i][base + 16] + spk[i][base + 24];
        size_t o = ((size_t)(b * 8 + h) * 64 + w) * DH + d0 + i;
        g_qm[o] = sq * 0.0625f;
        g_km[o] = sk * 0.0625f;
    }
}

// ---------------- affinity + exact top-4 (2-way split) ----------------
__global__ void topk_k() {
    int bh = blockIdx.x >> 1;
    int half = blockIdx.x & 1;
    __shared__ float kt[32][65];
    __shared__ float qs[64][32];
    int tid = threadIdx.x, warp = tid >> 5, lane = tid & 31;
    for (int e = tid; e < 2048; e += 256) {
        int j = e >> 5, d = e & 31;
        kt[d][j] = g_km[(size_t)bh * 2048 + e];
        qs[j][d] = g_qm[(size_t)bh * 2048 + e];
    }
    __syncthreads();
    for (int ii = 0; ii < 4; ii++) {
        int i = half * 32 + warp * 4 + ii;
        float s0 = 0.f, s1 = 0.f;
        #pragma unroll
        for (int d = 0; d < 32; d++) {
            float q = qs[i][d];
            s0 += q * kt[d][lane];
            s1 += q * kt[d][lane + 32];
        }
        float v0 = s0, v1 = s1;
        #pragma unroll
        for (int t = 0; t < KTOP; t++) {
            float bvv; int bj;
            if (v0 >= v1) { bvv = v0; bj = lane; } else { bvv = v1; bj = lane + 32; }
            #pragma unroll
            for (int off = 16; off; off >>= 1) {
                float ov = __shfl_xor_sync(0xffffffffu, bvv, off);
                int   oj = __shfl_xor_sync(0xffffffffu, bj,  off);
                if (ov > bvv || (ov == bvv && oj < bj)) { bvv = ov; bj = oj; }
            }
            if (lane == 0) g_idx[((size_t)bh * 64 + i) * KTOP + t] = bj;
            if (bj == lane)      v0 = -INFINITY;
            if (bj == lane + 32) v1 = -INFINITY;
        }
    }
}

// ---------------- gathered window attention (HMMA, ldmatrix fragments) ----------------
#define QT_STR 24
#define KV_STR 72
#define SS_STR 68
#define P_STR  72
__global__ void __launch_bounds__(128) attn_k() {
    int bid = blockIdx.x;
    int n = bid & 63;
    int h = (bid >> 6) & 7;
    int b = bid >> 9;
    __shared__ __half qh[32 * QT_STR];
    __shared__ __half kh[32 * KV_STR];
    __shared__ __half vh[32 * KV_STR];
    __shared__ float  ss[16 * SS_STR];
    __shared__ __half ph[16 * P_STR];
    __shared__ int    widx[KTOP];
    int tid = threadIdx.x;
    if (tid < KTOP) widx[tid] = g_idx[(size_t)bid * KTOP + tid];
    __syncthreads();

    int wy = n >> 3, wx = n & 7;
    const __half* qbase = g_qkvh + ((size_t)b * 3 * CC + h * DH) * HWSZ;
    const __half* kbase = qbase + (size_t)CC * HWSZ;
    const __half* vbase = qbase + (size_t)2 * CC * HWSZ;

    {
        int d = tid >> 2, tj = tid & 3;
        int hw = ((wy * 4 + tj) << 5) + wx * 4;
        uint2 u = *(const uint2*)(qbase + (size_t)d * HWSZ + hw);
        *(uint2*)&qh[d * QT_STR + tj * 4] = u;
    }
    for (int e = tid; e < 512; e += 128) {
        int d = e >> 4, kq = e & 15;
        int j = widx[kq >> 2];
        int tj = kq & 3;
        int hw = (((j >> 3) * 4 + tj) << 5) + (j & 7) * 4;
        uint2 uk = *(const uint2*)(kbase + (size_t)d * HWSZ + hw);
        uint2 uv = *(const uint2*)(vbase + (size_t)d * HWSZ + hw);
        *(uint2*)&kh[d * KV_STR + kq * 4] = uk;
        *(uint2*)&vh[d * KV_STR + kq * 4] = uv;
    }
    __syncthreads();

    int warp = tid >> 5, lane = tid & 31;
    int gq = lane >> 2, tq = lane & 3;
    const float scale = 0.17677669529663687f;
    const uint32_t qsm = smem_u32(qh);
    const uint32_t ksm = smem_u32(kh);
    const uint32_t qloff = (uint32_t)((((lane & 7) + (lane >> 4) * 8) * QT_STR
                                      + ((lane >> 3) & 1) * 8) * 2);
    const uint32_t kloff = (uint32_t)(((lane & 15) * KV_STR + warp * 16) * 2);

    {
        float sc0[4] = {0.f, 0.f, 0.f, 0.f};
        float sc1[4] = {0.f, 0.f, 0.f, 0.f};
        #pragma unroll
        for (int ks = 0; ks < 2; ks++) {
            uint32_t ah[4];
            ldsm_x4_t(ah, qsm + qloff + (uint32_t)(ks * 16 * QT_STR * 2));
            uint32_t kb0, kb1;
            ldsm_x2_t(kb0, kb1, ksm + kloff + (uint32_t)(ks * 16 * KV_STR * 2));
            mma_f16(sc0, ah, kb0, kb1);
            uint32_t kb2, kb3;
            ldsm_x2_t(kb2, kb3, ksm + kloff + (uint32_t)(ks * 16 * KV_STR * 2) + 16);
            mma_f16(sc1, ah, kb2, kb3);
        }
        #pragma unroll
        for (int nt = 0; nt < 2; nt++) {
            const float* sc = nt ? sc1 : sc0;
            int c0 = warp * 16 + nt * 8 + 2 * tq;
            ss[gq * SS_STR + c0]           = sc[0] * scale;
            ss[gq * SS_STR + c0 + 1]       = sc[1] * scale;
            ss[(gq + 8) * SS_STR + c0]     = sc[2] * scale;
            ss[(gq + 8) * SS_STR + c0 + 1] = sc[3] * scale;
        }
    }
    __syncthreads();

    #pragma unroll
    for (int rr = 0; rr < 4; rr++) {
        int row = warp * 4 + rr;
        float s0 = ss[row * SS_STR + lane];
        float s1 = ss[row * SS_STR + lane + 32];
        float mx = fmaxf(s0, s1);
        #pragma unroll
        for (int off = 16; off; off >>= 1) mx = fmaxf(mx, __shfl_xor_sync(0xffffffffu, mx, off));
        float e0 = expf(s0 - mx), e1 = expf(s1 - mx);
        float sum = e0 + e1;
        #pragma unroll
        for (int off = 16; off; off >>= 1) sum += __shfl_xor_sync(0xffffffffu, sum, off);
        float inv = 1.0f / sum;
        ph[row * P_STR + lane]      = __float2half_rn(e0 * inv);
        ph[row * P_STR + lane + 32] = __float2half_rn(e1 * inv);
    }
    __syncthreads();

    {
        float f[4] = {0.f, 0.f, 0.f, 0.f};
        #pragma unroll
        for (int ks = 0; ks < 4; ks++) {
            int cb = ks * 16 + 2 * tq;
            uint32_t ah[4];
            ah[0] = *(const uint32_t*)&ph[gq * P_STR + cb];
            ah[1] = *(const uint32_t*)&ph[(gq + 8) * P_STR + cb];
            ah[2] = *(const uint32_t*)&ph[gq * P_STR + cb + 8];
            ah[3] = *(const uint32_t*)&ph[(gq + 8) * P_STR + cb + 8];
            int d = warp * 8 + gq;
            uint32_t bh0 = *(const uint32_t*)&vh[d * KV_STR + cb];
            uint32_t bh1 = *(const uint32_t*)&vh[d * KV_STR + cb + 8];
            mma_f16(f, ah, bh0, bh1);
        }
        __half* mbase = g_msgh + ((size_t)b * CC + h * DH) * HWSZ;
        int d0 = warp * 8 + 2 * tq;
        int hwA = ((wy * 4 + (gq >> 2)) << 5) + wx * 4 + (gq & 3);
        int hwB = ((wy * 4 + ((gq + 8) >> 2)) << 5) + wx * 4 + ((gq + 8) & 3);
        mbase[(size_t)d0 * HWSZ + hwA]       = __float2half_rn(f[0]);
        mbase[(size_t)(d0 + 1) * HWSZ + hwA] = __float2half_rn(f[1]);
        mbase[(size_t)d0 * HWSZ + hwB]       = __float2half_rn(f[2]);
        mbase[(size_t)(d0 + 1) * HWSZ + hwB] = __float2half_rn(f[3]);
    }
}

// ---------------- depthwise 3x3 + bn2 + gelu (fp16 in/out) ----------------
__global__ void dw_k(const float* __restrict__ dw,
                     const float* __restrict__ g2, const float* __restrict__ b2,
                     const float* __restrict__ m2, const float* __restrict__ v2) {
    int bc = blockIdx.x;
    int c = bc & (MRC - 1);
    __shared__ float t[1024];
    __shared__ float wsh[9];
    int tid = threadIdx.x;
    const __half* p = g_h1h + (size_t)bc * HWSZ;
    {
        uint2 u = ((const uint2*)p)[tid];
        __half2 a = *(__half2*)&u.x, b2h = *(__half2*)&u.y;
        float4 f;
        f.x = __low2float(a);  f.y = __high2float(a);
        f.z = __low2float(b2h); f.w = __high2float(b2h);
        ((float4*)t)[tid] = f;
    }
    if (tid < 9) wsh[tid] = dw[c * 9 + tid];
    __syncthreads();
    float s = g2[c] * rsqrtf(v2[c] + EPSV);
    float bs = b2[c] - m2[c] * s;
    __half* outp = g_h2h + (size_t)bc * HWSZ;
    int y = tid >> 3, x0 = (tid & 7) * 4;
    float rp[4];
    #pragma unroll
    for (int j = 0; j < 4; j++) {
        int x = x0 + j;
        float acc = 0.f;
        #pragma unroll
        for (int dy = -1; dy <= 1; dy++) {
            int yy = y + dy;
            if (yy < 0 || yy > 31) continue;
            #pragma unroll
            for (int dx = -1; dx <= 1; dx++) {
                int xx = x + dx;
                if (xx < 0 || xx > 31) continue;
                acc += wsh[(dy + 1) * 3 + (dx + 1)] * t[yy * 32 + xx];
            }
        }
        rp[j] = gelu_f(acc * s + bs);
    }
    __half2 o0 = __floats2half2_rn(rp[0], rp[1]);
    __half2 o1 = __floats2half2_rn(rp[2], rp[3]);
    uint2 u; u.x = *(uint32_t*)&o0; u.y = *(uint32_t*)&o1;
    ((uint2*)outp)[tid] = u;
}

// ---------------- launcher ----------------
extern "C" void kernel_launch(void* const* d_in, const int* in_sizes, int n_in,
                              void* d_out, int out_size) {
    const float* x      = (const float*)d_in[0];
    const float* bn0_g  = (const float*)d_in[1];
    const float* bn0_b  = (const float*)d_in[2];
    const float* bn0_m  = (const float*)d_in[3];
    const float* bn0_v  = (const float*)d_in[4];
    const float* w_qkv  = (const float*)d_in[5];
    const float* w_mrg  = (const float*)d_in[6];
    const float* b_mrg  = (const float*)d_in[7];
    const float* w1     = (const float*)d_in[8];
    const float* bn1_g  = (const float*)d_in[9];
    const float* bn1_b  = (const float*)d_in[10];
    const float* bn1_m  = (const float*)d_in[11];
    const float* bn1_v  = (const float*)d_in[12];
    const float* dw     = (const float*)d_in[13];
    const float* bn2_g  = (const float*)d_in[14];
    const float* bn2_b  = (const float*)d_in[15];
    const float* bn2_m  = (const float*)d_in[16];
    const float* bn2_v  = (const float*)d_in[17];
    const float* w2     = (const float*)d_in[18];
    const float* bn3_g  = (const float*)d_in[19];
    const float* bn3_b  = (const float*)d_in[20];
    const float* bn3_m  = (const float*)d_in[21];
    const float* bn3_v  = (const float*)d_in[22];

    __half *wh, *wl, *h0h, *qkvh, *msgh, *x1h, *h1h, *h2h;
    cudaGetSymbolAddress((void**)&wh,   g_wh);
    cudaGetSymbolAddress((void**)&wl,   g_wl);
    cudaGetSymbolAddress((void**)&h0h,  g_h0h);
    cudaGetSymbolAddress((void**)&qkvh, g_qkvh);
    cudaGetSymbolAddress((void**)&msgh, g_msgh);
    cudaGetSymbolAddress((void**)&x1h,  g_x1h);
    cudaGetSymbolAddress((void**)&h1h,  g_h1h);
    cudaGetSymbolAddress((void**)&h2h,  g_h2h);

    // smem: qkv (KC=32, 2-pass): 3*29184=87552; 1-pass KC=64: 3*(18432+17408)=107520
    cudaFuncSetAttribute((const void*)mgemm_k<0,2,0,1,32>, cudaFuncAttributeMaxDynamicSharedMemorySize, 87552);
    cudaFuncSetAttribute((const void*)mgemm_k<1,1,0,1,64>, cudaFuncAttributeMaxDynamicSharedMemorySize, 107520);
    cudaFuncSetAttribute((const void*)mgemm_k<2,1,0,1,64>, cudaFuncAttributeMaxDynamicSharedMemorySize, 107520);
    cudaFuncSetAttribute((const void*)mgemm_k<5,1,1,0,64>, cudaFuncAttributeMaxDynamicSharedMemorySize, 107520);

    // 0. pre-split weights to fp16
    wsplit_k<<<(WTOT + 255) / 256, 256>>>(w_qkv, w_mrg, w1, w2);

    // 1. h0 = gelu(bn0(x)) -> fp16
    bn0_gelu_k<<<(BB * CC * HWSZ / 4 + 255) / 256, 256>>>(x, bn0_g, bn0_b, bn0_m, bn0_v);

    // 2. qkv = w_qkv @ h0   (2-pass, KC=32)
    mgemm_k<0,2,0,1,32><<<dim3(768 / 128, 8, BB), 256, 87552>>>(
        wh + WOFF_QKV, wl, h0h, nullptr, qkvh, 768, 256,
        nullptr, nullptr, nullptr, nullptr, nullptr, nullptr, nullptr);

    // 3. window means (2 d per block)
    wmean_k<<<BB * HEADS * DH / 2, 256>>>();

    // 4. affinity + top-4 (2-way split)
    topk_k<<<BB * HEADS * 2, 256>>>();

    // 5. gathered attention
    attn_k<<<BB * HEADS * NWIN, 128>>>();

    // 6. x1h = fp16(x + w_merge @ msg + b_merge)   (KC=64)
    mgemm_k<1,1,0,1,64><<<dim3(CC / 128, 8, BB), 256, 107520>>>(
        wh + WOFF_MRG, nullptr, msgh, nullptr, x1h, CC, 256,
        x, nullptr, b_mrg, nullptr, nullptr, nullptr, nullptr);

    // 7. h1 = gelu(bn1(w1 @ x1h)) -> fp16   (KC=64)
    mgemm_k<2,1,0,1,64><<<dim3(MRC / 128, 8, BB), 256, 107520>>>(
        wh + WOFF_W1, nullptr, x1h, nullptr, h1h, MRC, 256,
        nullptr, nullptr, nullptr, bn1_g, bn1_b, bn1_m, bn1_v);

    // 8. h2 = gelu(bn2(dwconv3x3(h1))) -> fp16
    dw_k<<<BB * MRC, 256>>>(dw, bn2_g, bn2_b, bn2_m, bn2_v);

    // 9. out = x1h + bn3(w2 @ h2)   (KC=64)
    mgemm_k<5,1,1,0,64><<<dim3(CC / 128, 8, BB), 256, 107520>>>(
        wh + WOFF_W2, nullptr, h2h, (float*)d_out, nullptr, CC, 1024,
        nullptr, x1h, nullptr, bn3_g, bn3_b, bn3_m, bn3_v);
}

// round 14
// speedup vs baseline: 2.0134x; 1.0041x over previous
#include <cuda_runtime.h>
#include <cuda_fp16.h>
#include <cstdint>
#include <math.h>

// ---------------- problem constants ----------------
#define BB   16
#define CC   256
#define HWSZ 1024
#define DH   32
#define HEADS 8
#define KTOP 4
#define MRC  1024
#define NWIN 64
#define EPSV 1e-5f

// pre-split weight offsets (halves)
#define WOFF_QKV 0
#define WOFF_MRG 196608
#define WOFF_W1  262144
#define WOFF_W2  524288
#define WTOT     786432

// ---------------- device scratch ----------------
__device__ float  g_qm  [BB * HEADS * NWIN * DH];
__device__ float  g_km  [BB * HEADS * NWIN * DH];
__device__ int    g_idx [BB * HEADS * NWIN * KTOP];
__device__ __half g_h0h [BB * CC  * HWSZ];
__device__ __half g_qkvh[BB * 3*CC * HWSZ];
__device__ __half g_msgh[BB * CC  * HWSZ];
__device__ __half g_x1h [BB * CC  * HWSZ];
__device__ __half g_h1h [BB * MRC * HWSZ];
__device__ __half g_h2h [BB * MRC * HWSZ];
__device__ __half g_wh  [WTOT];
__device__ __half g_wl  [196608];   // lo only for qkv (q,k rows used)

__device__ __forceinline__ float gelu_f(float x) {
    return 0.5f * x * (1.0f + erff(x * 0.7071067811865475f));
}

// ---------------- fp16 warp MMA + ldmatrix + cp.async ----------------
__device__ __forceinline__ void mma_f16(float* d, const uint32_t* a, uint32_t b0, uint32_t b1) {
    asm volatile(
        "mma.sync.aligned.m16n8k16.row.col.f32.f16.f16.f32 "
        "{%0,%1,%2,%3}, {%4,%5,%6,%7}, {%8,%9}, {%0,%1,%2,%3};"
        : "+f"(d[0]), "+f"(d[1]), "+f"(d[2]), "+f"(d[3])
        : "r"(a[0]), "r"(a[1]), "r"(a[2]), "r"(a[3]), "r"(b0), "r"(b1));
}
__device__ __forceinline__ void ldsm_x2_t(uint32_t& r0, uint32_t& r1, uint32_t addr) {
    asm volatile("ldmatrix.sync.aligned.m8n8.x2.trans.shared.b16 {%0,%1}, [%2];"
                 : "=r"(r0), "=r"(r1) : "r"(addr));
}
__device__ __forceinline__ void ldsm_x4(uint32_t* r, uint32_t addr) {
    asm volatile("ldmatrix.sync.aligned.m8n8.x4.shared.b16 {%0,%1,%2,%3}, [%4];"
                 : "=r"(r[0]), "=r"(r[1]), "=r"(r[2]), "=r"(r[3]) : "r"(addr));
}
__device__ __forceinline__ void ldsm_x4_t(uint32_t* r, uint32_t addr) {
    asm volatile("ldmatrix.sync.aligned.m8n8.x4.trans.shared.b16 {%0,%1,%2,%3}, [%4];"
                 : "=r"(r[0]), "=r"(r[1]), "=r"(r[2]), "=r"(r[3]) : "r"(addr));
}
__device__ __forceinline__ uint32_t smem_u32(const void* p) {
    uint32_t a;
    asm("{ .reg .u64 t; cvta.to.shared.u64 t, %1; cvt.u32.u64 %0, t; }" : "=r"(a) : "l"(p));
    return a;
}
__device__ __forceinline__ void cp16(uint32_t dst, const void* src) {
    asm volatile("cp.async.cg.shared.global [%0], [%1], 16;" :: "r"(dst), "l"(src) : "memory");
}
#define CP_COMMIT() asm volatile("cp.async.commit_group;" ::: "memory")
#define CP_WAIT(N)  asm volatile("cp.async.wait_group %0;" :: "n"(N) : "memory")
__device__ __forceinline__ void cvt_split(float x, __half& h, __half& l) {
    h = __float2half_rn(x);
    l = __float2half_rn(x - __half2float(h));
}

#define A_STR 136

// ---------------- weight pre-split ----------------
__global__ void wsplit_k(const float* __restrict__ wqkv, const float* __restrict__ wmrg,
                         const float* __restrict__ w1,   const float* __restrict__ w2) {
    int i = blockIdx.x * 256 + threadIdx.x;
    if (i >= WTOT) return;
    if (i < WOFF_MRG) {
        __half h, l; cvt_split(wqkv[i], h, l);
        g_wh[i] = h; g_wl[i] = l;
    } else if (i < WOFF_W1) {
        g_wh[i] = __float2half_rn(wmrg[i - WOFF_MRG]);
    } else if (i < WOFF_W2) {
        g_wh[i] = __float2half_rn(w1[i - WOFF_W1]);
    } else {
        g_wh[i] = __float2half_rn(w2[i - WOFF_W2]);
    }
}

// ---------------- h0 = gelu(bn0(x)) -> fp16 ----------------
__global__ void bn0_gelu_k(const float* __restrict__ x,
                           const float* __restrict__ g, const float* __restrict__ b,
                           const float* __restrict__ m, const float* __restrict__ v) {
    int i = blockIdx.x * 256 + threadIdx.x;
    if (i >= BB * CC * HWSZ / 4) return;
    int c = (i >> 8) & (CC - 1);
    float s = g[c] * rsqrtf(v[c] + EPSV);
    float sh = b[c] - m[c] * s;
    float4 xv = ((const float4*)x)[i];
    __half2 h0 = __floats2half2_rn(gelu_f(xv.x * s + sh), gelu_f(xv.y * s + sh));
    __half2 h1 = __floats2half2_rn(gelu_f(xv.z * s + sh), gelu_f(xv.w * s + sh));
    uint2 u; u.x = *(uint32_t*)&h0; u.y = *(uint32_t*)&h1;
    ((uint2*)g_h0h)[i] = u;
}

// ---------------- tensor-core fused GEMM (cp.async 3-stage, ldmatrix, KC-chunk) ----------------
// PASSES: 1 = hiW*hiA; 2 = + loW*hiA (W exact, A rounded)
// MODE 0: plain; 1: Res32 + acc + bias; 2: gelu(bn(acc)); 5: ResH + bn(acc)
template<int MODE, int PASSES, int WF32, int WF16, int KC>
__global__ void __launch_bounds__(256, 2)
mgemm_k(const __half* __restrict__ Whg, const __half* __restrict__ Wlg,
        const __half* __restrict__ Ahg,
        float* __restrict__ Out, __half* __restrict__ Outh, int O, int Kd,
        const float* __restrict__ Res, const __half* __restrict__ ResH,
        const float* __restrict__ bias,
        const float* __restrict__ g,  const float* __restrict__ bb,
        const float* __restrict__ mm, const float* __restrict__ vv) {
    constexpr int W_STR = (KC == 64) ? 72 : 40;
    constexpr int WH_B  = 128 * W_STR * 2;
    constexpr int WL_O  = WH_B;
    constexpr int AH_O  = (PASSES >= 2) ? 2 * WH_B : WH_B;
    constexpr int STG   = AH_O + KC * A_STR * 2;
    constexpr int KSN   = KC / 16;
    constexpr int WCP   = KC / 16;
    constexpr int ACP   = KC / 16;
    constexpr int WROWDIV = KC / 8;

    extern __shared__ char smc[];
    const int tid = threadIdx.x, lane = tid & 31, warp = tid >> 5;
    const int b = blockIdx.z, om = blockIdx.x * 128, n0 = blockIdx.y * 128;
    const int wm = warp >> 1, wn = warp & 1;
    const int gq = lane >> 2, tq = lane & 3;
    const uint32_t smbase = smem_u32(smc);

    const __half* Abh = Ahg + (size_t)b * Kd * HWSZ + n0;

    float acc[2][8][4];
    #pragma unroll
    for (int mt = 0; mt < 2; mt++)
        #pragma unroll
        for (int nt = 0; nt < 8; nt++)
            #pragma unroll
            for (int r = 0; r < 4; r++) acc[mt][nt][r] = 0.f;

    const uint32_t aoff = (uint32_t)(((lane & 15) * A_STR + wn * 64) * 2);
    const uint32_t woff = (uint32_t)(((wm * 32 + (lane & 7) + ((lane >> 3) & 1) * 8) * W_STR
                                     + (lane >> 4) * 8) * 2);
    const int nch = Kd / KC;

    auto issue = [&](int ch, int st) {
        int k0 = ch * KC;
        uint32_t stu = smbase + (uint32_t)st * STG;
        #pragma unroll
        for (int it = 0; it < WCP; it++) {
            int e = tid + it * 256;
            int row = e / WROWDIV, cc = e % WROWDIV;
            cp16(stu + row * (W_STR * 2) + cc * 16,
                 Whg + (size_t)(om + row) * Kd + k0 + cc * 8);
            if (PASSES >= 2)
                cp16(stu + WL_O + row * (W_STR * 2) + cc * 16,
                     Wlg + (size_t)(om + row) * Kd + k0 + cc * 8);
        }
        #pragma unroll
        for (int it = 0; it < ACP; it++) {
            int e = tid + it * 256;
            int row = e >> 4, col8 = (e & 15) * 8;
            cp16(stu + AH_O + (row * A_STR + col8) * 2, Abh + (size_t)(k0 + row) * HWSZ + col8);
        }
        CP_COMMIT();
    };

    issue(0, 0);
    issue(1, 1);

    int st = 0;
    for (int ch = 0; ch < nch; ch++) {
        if (ch + 1 < nch) { CP_WAIT(1); } else { CP_WAIT(0); }
        __syncthreads();
        if (ch + 2 < nch) {
            int st2 = st + 2; if (st2 >= 3) st2 -= 3;
            issue(ch + 2, st2);
        }

        uint32_t stu = smbase + (uint32_t)st * STG;

        #pragma unroll
        for (int ks = 0; ks < KSN; ks++) {
            uint32_t afh[2][4], afl[2][4];
            #pragma unroll
            for (int mt = 0; mt < 2; mt++) {
                uint32_t wa = stu + woff + (uint32_t)(mt * 16 * W_STR * 2 + ks * 32);
                ldsm_x4(afh[mt], wa);
                if (PASSES >= 2) ldsm_x4(afl[mt], wa + WL_O);
            }
            uint32_t abase_h = stu + AH_O + aoff + (uint32_t)ks * (16 * A_STR * 2);
            #pragma unroll
            for (int nt = 0; nt < 8; nt++) {
                uint32_t bh0, bh1;
                ldsm_x2_t(bh0, bh1, abase_h + nt * 16);
                #pragma unroll
                for (int mt = 0; mt < 2; mt++) {
                    mma_f16(acc[mt][nt], afh[mt], bh0, bh1);
                    if (PASSES >= 2) mma_f16(acc[mt][nt], afl[mt], bh0, bh1);
                }
            }
        }
        st = (st + 1 == 3) ? 0 : st + 1;
    }
    __syncthreads();

    // ---- epilogue ----
    #pragma unroll
    for (int mt = 0; mt < 2; mt++) {
        int o0 = om + wm * 32 + mt * 16 + gq;
        int o1 = o0 + 8;
        float s0 = 0.f, bs0 = 0.f, s1 = 0.f, bs1 = 0.f, bi0 = 0.f, bi1 = 0.f;
        if (MODE == 2 || MODE == 5) {
            s0 = g[o0] * rsqrtf(vv[o0] + EPSV); bs0 = bb[o0] - mm[o0] * s0;
            s1 = g[o1] * rsqrtf(vv[o1] + EPSV); bs1 = bb[o1] - mm[o1] * s1;
        }
        if (MODE == 1) { bi0 = bias[o0]; bi1 = bias[o1]; }
        #pragma unroll
        for (int nt = 0; nt < 8; nt++) {
            int n = n0 + wn * 64 + nt * 8 + 2 * tq;
            size_t oi0 = ((size_t)b * O + o0) * HWSZ + n;
            size_t oi1 = ((size_t)b * O + o1) * HWSZ + n;
            float r0 = acc[mt][nt][0], r1 = acc[mt][nt][1];
            float r2 = acc[mt][nt][2], r3 = acc[mt][nt][3];
            if (MODE == 1) {
                float2 e0 = *(const float2*)&Res[oi0];
                float2 e1 = *(const float2*)&Res[oi1];
                r0 += e0.x + bi0; r1 += e0.y + bi0;
                r2 += e1.x + bi1; r3 += e1.y + bi1;
            }
            if (MODE == 2) {
                r0 = gelu_f(r0 * s0 + bs0); r1 = gelu_f(r1 * s0 + bs0);
                r2 = gelu_f(r2 * s1 + bs1); r3 = gelu_f(r3 * s1 + bs1);
            }
            if (MODE == 5) {
                __half2 e0 = *(const __half2*)&ResH[oi0];
                __half2 e1 = *(const __half2*)&ResH[oi1];
                r0 = __low2float(e0) + r0 * s0 + bs0;
                r1 = __high2float(e0) + r1 * s0 + bs0;
                r2 = __low2float(e1) + r2 * s1 + bs1;
                r3 = __high2float(e1) + r3 * s1 + bs1;
            }
            if (WF32) {
                float2 v0 = {r0, r1}, v1 = {r2, r3};
                *(float2*)&Out[oi0] = v0;
                *(float2*)&Out[oi1] = v1;
            }
            if (WF16) {
                __half2 hv0 = __floats2half2_rn(r0, r1);
                __half2 hv1 = __floats2half2_rn(r2, r3);
                *(__half2*)&Outh[oi0] = hv0;
                *(__half2*)&Outh[oi1] = hv1;
            }
        }
    }
}

// ---------------- window means: block per (b,h,dpair) ----------------
__global__ void wmean_k() {
    int bid = blockIdx.x;
    int dp = bid & 15, h = (bid >> 4) & 7, b = bid >> 7;
    int d0 = dp * 2;
    int tid = threadIdx.x;
    __shared__ float spq[2][256], spk[2][256];
    const __half* qpl = g_qkvh + ((size_t)b * 3 * CC + h * DH + d0) * HWSZ;
    const __half* kpl = qpl + (size_t)CC * HWSZ;
    #pragma unroll
    for (int i = 0; i < 2; i++) {
        uint2 uq = ((const uint2*)(qpl + (size_t)i * HWSZ))[tid];
        uint2 uk = ((const uint2*)(kpl + (size_t)i * HWSZ))[tid];
        __half2 qa = *(__half2*)&uq.x, qb = *(__half2*)&uq.y;
        __half2 ka = *(__half2*)&uk.x, kb = *(__half2*)&uk.y;
        spq[i][tid] = __low2float(qa) + __high2float(qa) + __low2float(qb) + __high2float(qb);
        spk[i][tid] = __low2float(ka) + __high2float(ka) + __low2float(kb) + __high2float(kb);
    }
    __syncthreads();
    if (tid < 128) {
        int i = tid >> 6, w = tid & 63;
        int wy = w >> 3, wx = w & 7;
        int base = wy * 32 + wx;
        float sq = spq[i][base] + spq[i][base + 8] + spq[i][base + 16] + spq[i][base + 24];
        float sk = spk[i][base] + spk[i][base + 8] + spk[i][base + 16] + spk[i][base + 24];
        size_t o = ((size_t)(b * 8 + h) * 64 + w) * DH + d0 + i;
        g_qm[o] = sq * 0.0625f;
        g_km[o] = sk * 0.0625f;
    }
}

// ---------------- affinity + exact top-4 (2-way split) ----------------
__global__ void topk_k() {
    int bh = blockIdx.x >> 1;
    int half = blockIdx.x & 1;
    __shared__ float kt[32][65];
    __shared__ float qs[64][32];
    int tid = threadIdx.x, warp = tid >> 5, lane = tid & 31;
    for (int e = tid; e < 2048; e += 256) {
        int j = e >> 5, d = e & 31;
        kt[d][j] = g_km[(size_t)bh * 2048 + e];
        qs[j][d] = g_qm[(size_t)bh * 2048 + e];
    }
    __syncthreads();
    for (int ii = 0; ii < 4; ii++) {
        int i = half * 32 + warp * 4 + ii;
        float s0 = 0.f, s1 = 0.f;
        #pragma unroll
        for (int d = 0; d < 32; d++) {
            float q = qs[i][d];
            s0 += q * kt[d][lane];
            s1 += q * kt[d][lane + 32];
        }
        float v0 = s0, v1 = s1;
        #pragma unroll
        for (int t = 0; t < KTOP; t++) {
            float bvv; int bj;
            if (v0 >= v1) { bvv = v0; bj = lane; } else { bvv = v1; bj = lane + 32; }
            #pragma unroll
            for (int off = 16; off; off >>= 1) {
                float ov = __shfl_xor_sync(0xffffffffu, bvv, off);
                int   oj = __shfl_xor_sync(0xffffffffu, bj,  off);
                if (ov > bvv || (ov == bvv && oj < bj)) { bvv = ov; bj = oj; }
            }
            if (lane == 0) g_idx[((size_t)bh * 64 + i) * KTOP + t] = bj;
            if (bj == lane)      v0 = -INFINITY;
            if (bj == lane + 32) v1 = -INFINITY;
        }
    }
}

// ---------------- gathered window attention (HMMA, ldmatrix fragments) ----------------
#define QT_STR 24
#define KV_STR 72
#define SS_STR 68
#define P_STR  72
__global__ void __launch_bounds__(128) attn_k() {
    int bid = blockIdx.x;
    int n = bid & 63;
    int h = (bid >> 6) & 7;
    int b = bid >> 9;
    __shared__ __half qh[32 * QT_STR];
    __shared__ __half kh[32 * KV_STR];
    __shared__ __half vh[32 * KV_STR];
    __shared__ float  ss[16 * SS_STR];
    __shared__ __half ph[16 * P_STR];
    __shared__ int    widx[KTOP];
    int tid = threadIdx.x;
    if (tid < KTOP) widx[tid] = g_idx[(size_t)bid * KTOP + tid];
    __syncthreads();

    int wy = n >> 3, wx = n & 7;
    const __half* qbase = g_qkvh + ((size_t)b * 3 * CC + h * DH) * HWSZ;
    const __half* kbase = qbase + (size_t)CC * HWSZ;
    const __half* vbase = qbase + (size_t)2 * CC * HWSZ;

    {
        int d = tid >> 2, tj = tid & 3;
        int hw = ((wy * 4 + tj) << 5) + wx * 4;
        uint2 u = *(const uint2*)(qbase + (size_t)d * HWSZ + hw);
        *(uint2*)&qh[d * QT_STR + tj * 4] = u;
    }
    for (int e = tid; e < 512; e += 128) {
        int d = e >> 4, kq = e & 15;
        int j = widx[kq >> 2];
        int tj = kq & 3;
        int hw = (((j >> 3) * 4 + tj) << 5) + (j & 7) * 4;
        uint2 uk = *(const uint2*)(kbase + (size_t)d * HWSZ + hw);
        uint2 uv = *(const uint2*)(vbase + (size_t)d * HWSZ + hw);
        *(uint2*)&kh[d * KV_STR + kq * 4] = uk;
        *(uint2*)&vh[d * KV_STR + kq * 4] = uv;
    }
    __syncthreads();

    int warp = tid >> 5, lane = tid & 31;
    int gq = lane >> 2, tq = lane & 3;
    const float scale = 0.17677669529663687f;
    const uint32_t qsm = smem_u32(qh);
    const uint32_t ksm = smem_u32(kh);
    const uint32_t qloff = (uint32_t)((((lane & 7) + (lane >> 4) * 8) * QT_STR
                                      + ((lane >> 3) & 1) * 8) * 2);
    const uint32_t kloff = (uint32_t)(((lane & 15) * KV_STR + warp * 16) * 2);

    {
        float sc0[4] = {0.f, 0.f, 0.f, 0.f};
        float sc1[4] = {0.f, 0.f, 0.f, 0.f};
        #pragma unroll
        for (int ks = 0; ks < 2; ks++) {
            uint32_t ah[4];
            ldsm_x4_t(ah, qsm + qloff + (uint32_t)(ks * 16 * QT_STR * 2));
            uint32_t kb0, kb1;
            ldsm_x2_t(kb0, kb1, ksm + kloff + (uint32_t)(ks * 16 * KV_STR * 2));
            mma_f16(sc0, ah, kb0, kb1);
            uint32_t kb2, kb3;
            ldsm_x2_t(kb2, kb3, ksm + kloff + (uint32_t)(ks * 16 * KV_STR * 2) + 16);
            mma_f16(sc1, ah, kb2, kb3);
        }
        #pragma unroll
        for (int nt = 0; nt < 2; nt++) {
            const float* sc = nt ? sc1 : sc0;
            int c0 = warp * 16 + nt * 8 + 2 * tq;
            ss[gq * SS_STR + c0]           = sc[0] * scale;
            ss[gq * SS_STR + c0 + 1]       = sc[1] * scale;
            ss[(gq + 8) * SS_STR + c0]     = sc[2] * scale;
            ss[(gq + 8) * SS_STR + c0 + 1] = sc[3] * scale;
        }
    }
    __syncthreads();

    #pragma unroll
    for (int rr = 0; rr < 4; rr++) {
        int row = warp * 4 + rr;
        float s0 = ss[row * SS_STR + lane];
        float s1 = ss[row * SS_STR + lane + 32];
        float mx = fmaxf(s0, s1);
        #pragma unroll
        for (int off = 16; off; off >>= 1) mx = fmaxf(mx, __shfl_xor_sync(0xffffffffu, mx, off));
        float e0 = expf(s0 - mx), e1 = expf(s1 - mx);
        float sum = e0 + e1;
        #pragma unroll
        for (int off = 16; off; off >>= 1) sum += __shfl_xor_sync(0xffffffffu, sum, off);
        float inv = 1.0f / sum;
        ph[row * P_STR + lane]      = __float2half_rn(e0 * inv);
        ph[row * P_STR + lane + 32] = __float2half_rn(e1 * inv);
    }
    __syncthreads();

    {
        float f[4] = {0.f, 0.f, 0.f, 0.f};
        #pragma unroll
        for (int ks = 0; ks < 4; ks++) {
            int cb = ks * 16 + 2 * tq;
            uint32_t ah[4];
            ah[0] = *(const uint32_t*)&ph[gq * P_STR + cb];
            ah[1] = *(const uint32_t*)&ph[(gq + 8) * P_STR + cb];
            ah[2] = *(const uint32_t*)&ph[gq * P_STR + cb + 8];
            ah[3] = *(const uint32_t*)&ph[(gq + 8) * P_STR + cb + 8];
            int d = warp * 8 + gq;
            uint32_t bh0 = *(const uint32_t*)&vh[d * KV_STR + cb];
            uint32_t bh1 = *(const uint32_t*)&vh[d * KV_STR + cb + 8];
            mma_f16(f, ah, bh0, bh1);
        }
        __half* mbase = g_msgh + ((size_t)b * CC + h * DH) * HWSZ;
        int d0 = warp * 8 + 2 * tq;
        int hwA = ((wy * 4 + (gq >> 2)) << 5) + wx * 4 + (gq & 3);
        int hwB = ((wy * 4 + ((gq + 8) >> 2)) << 5) + wx * 4 + ((gq + 8) & 3);
        mbase[(size_t)d0 * HWSZ + hwA]       = __float2half_rn(f[0]);
        mbase[(size_t)(d0 + 1) * HWSZ + hwA] = __float2half_rn(f[1]);
        mbase[(size_t)d0 * HWSZ + hwB]       = __float2half_rn(f[2]);
        mbase[(size_t)(d0 + 1) * HWSZ + hwB] = __float2half_rn(f[3]);
    }
}

// ---------------- depthwise 3x3 + bn2 + gelu (2 channels/block) ----------------
__global__ void dw_k(const float* __restrict__ dw,
                     const float* __restrict__ g2, const float* __restrict__ b2,
                     const float* __restrict__ m2, const float* __restrict__ v2) {
    int bc0 = blockIdx.x * 2;
    __shared__ float t[2][1024];
    __shared__ float wsh[2][9];
    int tid = threadIdx.x;
    #pragma unroll
    for (int i = 0; i < 2; i++) {
        const __half* p = g_h1h + (size_t)(bc0 + i) * HWSZ;
        uint2 u = ((const uint2*)p)[tid];
        __half2 a = *(__half2*)&u.x, bp = *(__half2*)&u.y;
        float4 f;
        f.x = __low2float(a);  f.y = __high2float(a);
        f.z = __low2float(bp); f.w = __high2float(bp);
        ((float4*)t[i])[tid] = f;
    }
    if (tid < 18) {
        int i = tid / 9, w = tid % 9;
        wsh[i][w] = dw[((bc0 + i) & (MRC - 1)) * 9 + w];
    }
    __syncthreads();
    int y = tid >> 3, x0 = (tid & 7) * 4;
    #pragma unroll
    for (int i = 0; i < 2; i++) {
        int c = (bc0 + i) & (MRC - 1);
        float s = g2[c] * rsqrtf(v2[c] + EPSV);
        float bs = b2[c] - m2[c] * s;
        __half* outp = g_h2h + (size_t)(bc0 + i) * HWSZ;
        float rp[4];
        #pragma unroll
        for (int j = 0; j < 4; j++) {
            int x = x0 + j;
            float acc = 0.f;
            #pragma unroll
            for (int dy = -1; dy <= 1; dy++) {
                int yy = y + dy;
                if (yy < 0 || yy > 31) continue;
                #pragma unroll
                for (int dx = -1; dx <= 1; dx++) {
                    int xx = x + dx;
                    if (xx < 0 || xx > 31) continue;
                    acc += wsh[i][(dy + 1) * 3 + (dx + 1)] * t[i][yy * 32 + xx];
                }
            }
            rp[j] = gelu_f(acc * s + bs);
        }
        __half2 o0 = __floats2half2_rn(rp[0], rp[1]);
        __half2 o1 = __floats2half2_rn(rp[2], rp[3]);
        uint2 u; u.x = *(uint32_t*)&o0; u.y = *(uint32_t*)&o1;
        ((uint2*)outp)[tid] = u;
    }
}

// ---------------- launcher ----------------
extern "C" void kernel_launch(void* const* d_in, const int* in_sizes, int n_in,
                              void* d_out, int out_size) {
    const float* x      = (const float*)d_in[0];
    const float* bn0_g  = (const float*)d_in[1];
    const float* bn0_b  = (const float*)d_in[2];
    const float* bn0_m  = (const float*)d_in[3];
    const float* bn0_v  = (const float*)d_in[4];
    const float* w_qkv  = (const float*)d_in[5];
    const float* w_mrg  = (const float*)d_in[6];
    const float* b_mrg  = (const float*)d_in[7];
    const float* w1     = (const float*)d_in[8];
    const float* bn1_g  = (const float*)d_in[9];
    const float* bn1_b  = (const float*)d_in[10];
    const float* bn1_m  = (const float*)d_in[11];
    const float* bn1_v  = (const float*)d_in[12];
    const float* dw     = (const float*)d_in[13];
    const float* bn2_g  = (const float*)d_in[14];
    const float* bn2_b  = (const float*)d_in[15];
    const float* bn2_m  = (const float*)d_in[16];
    const float* bn2_v  = (const float*)d_in[17];
    const float* w2     = (const float*)d_in[18];
    const float* bn3_g  = (const float*)d_in[19];
    const float* bn3_b  = (const float*)d_in[20];
    const float* bn3_m  = (const float*)d_in[21];
    const float* bn3_v  = (const float*)d_in[22];

    __half *wh, *wl, *h0h, *qkvh, *msgh, *x1h, *h1h, *h2h;
    cudaGetSymbolAddress((void**)&wh,   g_wh);
    cudaGetSymbolAddress((void**)&wl,   g_wl);
    cudaGetSymbolAddress((void**)&h0h,  g_h0h);
    cudaGetSymbolAddress((void**)&qkvh, g_qkvh);
    cudaGetSymbolAddress((void**)&msgh, g_msgh);
    cudaGetSymbolAddress((void**)&x1h,  g_x1h);
    cudaGetSymbolAddress((void**)&h1h,  g_h1h);
    cudaGetSymbolAddress((void**)&h2h,  g_h2h);

    cudaFuncSetAttribute((const void*)mgemm_k<0,2,0,1,32>, cudaFuncAttributeMaxDynamicSharedMemorySize, 87552);
    cudaFuncSetAttribute((const void*)mgemm_k<0,1,0,1,64>, cudaFuncAttributeMaxDynamicSharedMemorySize, 107520);
    cudaFuncSetAttribute((const void*)mgemm_k<1,1,0,1,64>, cudaFuncAttributeMaxDynamicSharedMemorySize, 107520);
    cudaFuncSetAttribute((const void*)mgemm_k<2,1,0,1,64>, cudaFuncAttributeMaxDynamicSharedMemorySize, 107520);
    cudaFuncSetAttribute((const void*)mgemm_k<5,1,1,0,64>, cudaFuncAttributeMaxDynamicSharedMemorySize, 107520);

    // 0. pre-split weights to fp16
    wsplit_k<<<(WTOT + 255) / 256, 256>>>(w_qkv, w_mrg, w1, w2);

    // 1. h0 = gelu(bn0(x)) -> fp16
    bn0_gelu_k<<<(BB * CC * HWSZ / 4 + 255) / 256, 256>>>(x, bn0_g, bn0_b, bn0_m, bn0_v);

    // 2a. q,k = w_qkv[0:512] @ h0   (2-pass, KC=32)
    mgemm_k<0,2,0,1,32><<<dim3(4, 8, BB), 256, 87552>>>(
        wh + WOFF_QKV, wl, h0h, nullptr, qkvh, 768, 256,
        nullptr, nullptr, nullptr, nullptr, nullptr, nullptr, nullptr);

    // 2b. v = w_qkv[512:768] @ h0   (1-pass, KC=64; output rows 512.. via base offset)
    mgemm_k<0,1,0,1,64><<<dim3(2, 8, BB), 256, 107520>>>(
        wh + WOFF_QKV + 512 * 256, nullptr, h0h, nullptr,
        qkvh + (size_t)512 * HWSZ, 768, 256,
        nullptr, nullptr, nullptr, nullptr, nullptr, nullptr, nullptr);

    // 3. window means (2 d per block)
    wmean_k<<<BB * HEADS * DH / 2, 256>>>();

    // 4. affinity + top-4 (2-way split)
    topk_k<<<BB * HEADS * 2, 256>>>();

    // 5. gathered attention
    attn_k<<<BB * HEADS * NWIN, 128>>>();

    // 6. x1h = fp16(x + w_merge @ msg + b_merge)   (KC=64)
    mgemm_k<1,1,0,1,64><<<dim3(CC / 128, 8, BB), 256, 107520>>>(
        wh + WOFF_MRG, nullptr, msgh, nullptr, x1h, CC, 256,
        x, nullptr, b_mrg, nullptr, nullptr, nullptr, nullptr);

    // 7. h1 = gelu(bn1(w1 @ x1h)) -> fp16   (KC=64)
    mgemm_k<2,1,0,1,64><<<dim3(MRC / 128, 8, BB), 256, 107520>>>(
        wh + WOFF_W1, nullptr, x1h, nullptr, h1h, MRC, 256,
        nullptr, nullptr, nullptr, bn1_g, bn1_b, bn1_m, bn1_v);

    // 8. h2 = gelu(bn2(dwconv3x3(h1))) -> fp16   (2 channels/block)
    dw_k<<<BB * MRC / 2, 256>>>(dw, bn2_g, bn2_b, bn2_m, bn2_v);

    // 9. out = x1h + bn3(w2 @ h2)   (KC=64)
    mgemm_k<5,1,1,0,64><<<dim3(CC / 128, 8, BB), 256, 107520>>>(
        wh + WOFF_W2, nullptr, h2h, (float*)d_out, nullptr, CC, 1024,
        nullptr, x1h, nullptr, bn3_g, bn3_b, bn3_m, bn3_v);
}